// round 11
// baseline (speedup 1.0000x reference)
#include <cuda_runtime.h>
#include <cuda_bf16.h>
#include <math.h>
#include <stdint.h>

#define MTOT 8192
#define KDIM 8192
#define DIM 128
#define FEAT 256
#define EPSV 1e-5f
#define NKSL 8
#define NTILE 64

// ---------------- scratch (device globals; no allocs allowed) ----------------
__device__ float g_bufX [MTOT * DIM];
__device__ float g_bufX2[MTOT * DIM];
__device__ float g_LxP [NKSL * MTOT * DIM];  // K-slice partials (slice 0 -> folded sum)
__device__ __nv_bfloat16 g_Bh[DIM * MTOT];   // B^T bf16 hi [feat][node]
__device__ __nv_bfloat16 g_Bl[DIM * MTOT];
__device__ float g_partials[4 * DIM * NTILE];  // [quad][feat][mtile]
__device__ int   g_tilecnt[NTILE];             // zero-init; folder resets
__device__ float g_scale[FEAT];
__device__ float g_shift[FEAT];
__device__ __nv_bfloat16 g_wBh[DIM * FEAT];  // folded weights bf16 [j][k]
__device__ __nv_bfloat16 g_wBl[DIM * FEAT];
__device__ float g_beff[DIM];

// ---------------- helpers ----------------
__device__ __forceinline__ uint32_t smem_u32(const void* p) {
    uint32_t a;
    asm("{ .reg .u64 t; cvta.to.shared.u64 t, %1; cvt.u32.u64 %0, t; }" : "=r"(a) : "l"(p));
    return a;
}
__device__ __forceinline__ void ldmx4(uint32_t* r, uint32_t addr) {
    asm volatile("ldmatrix.sync.aligned.m8n8.x4.shared.b16 {%0,%1,%2,%3}, [%4];"
                 : "=r"(r[0]), "=r"(r[1]), "=r"(r[2]), "=r"(r[3]) : "r"(addr));
}
__device__ __forceinline__ void mma_bf16(float* d, const uint32_t* a, uint32_t b0, uint32_t b1) {
    asm volatile(
        "mma.sync.aligned.m16n8k16.row.col.f32.bf16.bf16.f32 "
        "{%0,%1,%2,%3}, {%4,%5,%6,%7}, {%8,%9}, {%0,%1,%2,%3};"
        : "+f"(d[0]), "+f"(d[1]), "+f"(d[2]), "+f"(d[3])
        : "r"(a[0]), "r"(a[1]), "r"(a[2]), "r"(a[3]), "r"(b0), "r"(b1));
}
__device__ __forceinline__ void cpasync16(uint32_t dst, const void* src) {
    asm volatile("cp.async.cg.shared.global [%0], [%1], 16;" :: "r"(dst), "l"(src));
}
__device__ __forceinline__ void cp_commit() { asm volatile("cp.async.commit_group;"); }
__device__ __forceinline__ void cp_wait0()  { asm volatile("cp.async.wait_group 0;" ::: "memory"); }

__device__ __forceinline__ float eluf(float v) { return v > 0.f ? v : expm1f(v); }

__device__ __forceinline__ float warp_sum(float v) {
#pragma unroll
    for (int o = 16; o > 0; o >>= 1) v += __shfl_xor_sync(0xFFFFFFFFu, v, o);
    return v;
}
__device__ __forceinline__ void split_bf16(float v, __nv_bfloat16& h, __nv_bfloat16& l) {
    h = __float2bfloat16(v);
    l = __float2bfloat16(v - __bfloat162float(h));
}

// ---------------- pack: inputs -> ELU -> g_bufX + B^T bf16 hi/lo ------------
__global__ __launch_bounds__(256) void pack_kernel(const float* __restrict__ src) {
    __shared__ float tile[128][65];
    const int tid = threadIdx.x;
    const int node0 = blockIdx.x * 64;

    const float4* sv = (const float4*)src + (size_t)node0 * 32;
    float4* xv = (float4*)g_bufX + (size_t)node0 * 32;
#pragma unroll
    for (int i = 0; i < 8; i++) {
        int idx = tid + 256 * i;
        int node = idx >> 5;
        int fq = idx & 31;
        float4 v = sv[idx];
        v.x = eluf(v.x); v.y = eluf(v.y); v.z = eluf(v.z); v.w = eluf(v.w);
        xv[idx] = v;
        tile[fq * 4 + 0][node] = v.x;
        tile[fq * 4 + 1][node] = v.y;
        tile[fq * 4 + 2][node] = v.z;
        tile[fq * 4 + 3][node] = v.w;
    }
    __syncthreads();

    const int feat = tid >> 1;
    const int h = tid & 1;
    const float* r = &tile[feat][h * 32];
    uint32_t hi[16], lo[16];
#pragma unroll
    for (int j = 0; j < 16; j++) {
        float a = r[2 * j], b = r[2 * j + 1];
        __nv_bfloat162 hb = __floats2bfloat162_rn(a, b);
        float ha = __low2float(hb), hbv = __high2float(hb);
        __nv_bfloat162 lb = __floats2bfloat162_rn(a - ha, b - hbv);
        hi[j] = *(uint32_t*)&hb;
        lo[j] = *(uint32_t*)&lb;
    }
    uint4* oh = (uint4*)(g_Bh + (size_t)feat * MTOT + node0 + h * 32);
    uint4* ol = (uint4*)(g_Bl + (size_t)feat * MTOT + node0 + h * 32);
#pragma unroll
    for (int blk = 0; blk < 4; blk++) {
        oh[blk] = make_uint4(hi[4 * blk], hi[4 * blk + 1], hi[4 * blk + 2], hi[4 * blk + 3]);
        ol[blk] = make_uint4(lo[4 * blk], lo[4 * blk + 1], lo[4 * blk + 2], lo[4 * blk + 3]);
    }
}

// ---------------- split-bf16 HMMA GEMM + fused last-CTA fold/stats ----------
#define ROWB 80
#define OPSZ 10240
#define STGSZ 40960
#define SGEMM_SMEM (2 * STGSZ)

__global__ __launch_bounds__(256, 2) void sgemm_mma(const float* __restrict__ L, int xsel) {
    extern __shared__ char smem[];
    const int tid = threadIdx.x;
    const int lane = tid & 31;
    const int w = tid >> 5;
    const int wm = w >> 1;
    const int wn = w & 1;
    const int mtile = blockIdx.x >> 3;
    const int ksl = blockIdx.x & 7;
    const int m0 = mtile * 128;
    const int kc0 = ksl * 1024;

    const uint32_t sb = smem_u32(smem);

    const int a_row = wm * 32 + (lane & 7) + ((lane >> 3) & 1) * 8;
    const uint32_t aOff = (uint32_t)a_row * ROWB + ((lane >> 4) & 1) * 16;
    const int b_row = wn * 64 + (lane & 7) + ((lane >> 4) & 1) * 8;
    const uint32_t bOff = (uint32_t)b_row * ROWB + ((lane >> 3) & 1) * 16;

    const int grow = tid >> 1;
    const int gh = tid & 1;
    const float* Ap = L + (size_t)(m0 + grow) * KDIM + kc0 + gh * 16;
    const __nv_bfloat16* Bhp = g_Bh + (size_t)grow * MTOT + kc0 + gh * 16;
    const __nv_bfloat16* Blp = g_Bl + (size_t)grow * MTOT + kc0 + gh * 16;
    const uint32_t aStOff = (uint32_t)grow * ROWB + gh * 32;

    float acc[2][8][4];
#pragma unroll
    for (int i = 0; i < 2; i++)
#pragma unroll
        for (int j = 0; j < 8; j++)
#pragma unroll
            for (int q = 0; q < 4; q++) acc[i][j][q] = 0.f;

    float4 ar[4];

    cpasync16(sb + 2 * OPSZ + aStOff,      Bhp);
    cpasync16(sb + 2 * OPSZ + aStOff + 16, Bhp + 8);
    cpasync16(sb + 3 * OPSZ + aStOff,      Blp);
    cpasync16(sb + 3 * OPSZ + aStOff + 16, Blp + 8);
    cp_commit();
#pragma unroll
    for (int i = 0; i < 4; i++) ar[i] = *(const float4*)(Ap + 4 * i);
    {
        char* sAh = smem + aStOff;
        char* sAl = smem + OPSZ + aStOff;
#pragma unroll
        for (int i = 0; i < 4; i++) {
            float4 v = ar[i];
            __nv_bfloat162 h01 = __floats2bfloat162_rn(v.x, v.y);
            __nv_bfloat162 h23 = __floats2bfloat162_rn(v.z, v.w);
            __nv_bfloat162 l01 = __floats2bfloat162_rn(v.x - __low2float(h01), v.y - __high2float(h01));
            __nv_bfloat162 l23 = __floats2bfloat162_rn(v.z - __low2float(h23), v.w - __high2float(h23));
            *(uint2*)(sAh + 8 * i) = make_uint2(*(uint32_t*)&h01, *(uint32_t*)&h23);
            *(uint2*)(sAl + 8 * i) = make_uint2(*(uint32_t*)&l01, *(uint32_t*)&l23);
        }
    }

    const int T = 1024 / 32;  // 32

    for (int t = 0; t < T; t++) {
        cp_wait0();
        __syncthreads();
        const int s = t & 1;
        const uint32_t sA = sb + s * STGSZ;
        const uint32_t nsBase = sb + (s ^ 1) * STGSZ;
        const bool more = (t + 1) < T;
        if (more) {
            const int off = (t + 1) * 32;
            cpasync16(nsBase + 2 * OPSZ + aStOff,      Bhp + off);
            cpasync16(nsBase + 2 * OPSZ + aStOff + 16, Bhp + off + 8);
            cpasync16(nsBase + 3 * OPSZ + aStOff,      Blp + off);
            cpasync16(nsBase + 3 * OPSZ + aStOff + 16, Blp + off + 8);
            cp_commit();
#pragma unroll
            for (int i = 0; i < 4; i++) ar[i] = *(const float4*)(Ap + off + 4 * i);
        }

#pragma unroll
        for (int ks = 0; ks < 2; ks++) {
            const uint32_t kb = ks * 32;
            uint32_t Ah[2][4], Al[2][4];
#pragma unroll
            for (int mf = 0; mf < 2; mf++) {
                ldmx4(Ah[mf], sA + aOff + mf * (16 * ROWB) + kb);
                ldmx4(Al[mf], sA + OPSZ + aOff + mf * (16 * ROWB) + kb);
            }
#pragma unroll
            for (int qh = 0; qh < 2; qh++) {
                uint32_t Bh2[2][4], Bl2[2][4];
#pragma unroll
                for (int qq = 0; qq < 2; qq++) {
                    const int q = qh * 2 + qq;
                    ldmx4(Bh2[qq], sA + 2 * OPSZ + bOff + q * (16 * ROWB) + kb);
                    ldmx4(Bl2[qq], sA + 3 * OPSZ + bOff + q * (16 * ROWB) + kb);
                }
#pragma unroll
                for (int mf = 0; mf < 2; mf++)
#pragma unroll
                    for (int qq = 0; qq < 2; qq++)
#pragma unroll
                        for (int j = 0; j < 2; j++) {
                            const int nf = qh * 4 + qq * 2 + j;
                            const int rr = j * 2;
                            mma_bf16(acc[mf][nf], Ah[mf], Bh2[qq][rr], Bh2[qq][rr + 1]);
                            mma_bf16(acc[mf][nf], Ah[mf], Bl2[qq][rr], Bl2[qq][rr + 1]);
                            mma_bf16(acc[mf][nf], Al[mf], Bh2[qq][rr], Bh2[qq][rr + 1]);
                        }
            }
        }

        if (more) {
            char* other = smem + (s ^ 1) * STGSZ;
            char* sAh = other + aStOff;
            char* sAl = other + OPSZ + aStOff;
#pragma unroll
            for (int i = 0; i < 4; i++) {
                float4 v = ar[i];
                __nv_bfloat162 h01 = __floats2bfloat162_rn(v.x, v.y);
                __nv_bfloat162 h23 = __floats2bfloat162_rn(v.z, v.w);
                __nv_bfloat162 l01 = __floats2bfloat162_rn(v.x - __low2float(h01), v.y - __high2float(h01));
                __nv_bfloat162 l23 = __floats2bfloat162_rn(v.z - __low2float(h23), v.w - __high2float(h23));
                *(uint2*)(sAh + 8 * i) = make_uint2(*(uint32_t*)&h01, *(uint32_t*)&h23);
                *(uint2*)(sAl + 8 * i) = make_uint2(*(uint32_t*)&l01, *(uint32_t*)&l23);
            }
        }
    }

    // ---- epilogue: write fp32 partials ----
    float* outb = g_LxP + (size_t)ksl * (MTOT * DIM);
    const int g = lane >> 2, t4 = lane & 3;
#pragma unroll
    for (int mf = 0; mf < 2; mf++) {
        const int row0 = m0 + wm * 32 + mf * 16 + g;
#pragma unroll
        for (int nf = 0; nf < 8; nf++) {
            const int col = wn * 64 + nf * 8 + t4 * 2;
            *(float2*)(outb + (size_t)row0 * DIM + col) =
                make_float2(acc[mf][nf][0], acc[mf][nf][1]);
            *(float2*)(outb + (size_t)(row0 + 8) * DIM + col) =
                make_float2(acc[mf][nf][2], acc[mf][nf][3]);
        }
    }

    // ---- last-CTA-per-tile: fold K-slices + BN column stats ----
    __threadfence();
    __shared__ int isLast;
    if (tid == 0) {
        int old = atomicAdd(&g_tilecnt[mtile], 1);
        isLast = (old == NKSL - 1) ? 1 : 0;
    }
    __syncthreads();
    if (isLast) {
        __threadfence();  // acquire: other CTAs' partials now visible
        const float* __restrict__ X = xsel ? g_bufX2 : g_bufX;
        const int c = tid & 127;
        const int half = tid >> 7;
        float sx = 0.f, sxx = 0.f, sl = 0.f, sll = 0.f;
        for (int r = m0 + half; r < m0 + 128; r += 2) {
            size_t idx = (size_t)r * DIM + c;
            float v = X[idx];
            sx += v; sxx += v * v;
            float s0 = 0.f;
#pragma unroll
            for (int q = 0; q < NKSL; q++) s0 += g_LxP[idx + (size_t)q * MTOT * DIM];
            g_LxP[idx] = s0;
            sl += s0; sll += s0 * s0;
        }
        float* sh = (float*)smem;
        sh[tid] = sx;  __syncthreads();
        if (tid < 128) g_partials[(0 * 128 + c) * NTILE + mtile] = sh[tid] + sh[tid + 128];
        __syncthreads();
        sh[tid] = sxx; __syncthreads();
        if (tid < 128) g_partials[(1 * 128 + c) * NTILE + mtile] = sh[tid] + sh[tid + 128];
        __syncthreads();
        sh[tid] = sl;  __syncthreads();
        if (tid < 128) g_partials[(2 * 128 + c) * NTILE + mtile] = sh[tid] + sh[tid + 128];
        __syncthreads();
        sh[tid] = sll; __syncthreads();
        if (tid < 128) g_partials[(3 * 128 + c) * NTILE + mtile] = sh[tid] + sh[tid + 128];
        __syncthreads();
        if (tid == 0) g_tilecnt[mtile] = 0;   // reset for next replay
    }
}

// ---------------- BN stats pass 2 -------------------------------------------
__global__ __launch_bounds__(256) void stats_final(const float* __restrict__ gamma,
                                                   const float* __restrict__ beta) {
    const int warp = threadIdx.x >> 5;
    const int lane = threadIdx.x & 31;
    const int k = blockIdx.x * 8 + warp;
    const int base = (k < 128) ? 0 : 2;
    const int c = k & 127;
    const float* ps = g_partials + (size_t)(base * 128 + c) * NTILE;
    const float* pq = g_partials + (size_t)((base + 1) * 128 + c) * NTILE;
    float s = 0.f, ss = 0.f;
#pragma unroll
    for (int b = lane; b < NTILE; b += 32) {
        s  += ps[b];
        ss += pq[b];
    }
    s = warp_sum(s);
    ss = warp_sum(ss);
    if (lane == 0) {
        float mean = s / (float)MTOT;
        float var  = ss / (float)MTOT - mean * mean;
        float sc   = rsqrtf(var + EPSV) * gamma[k];
        g_scale[k] = sc;
        g_shift[k] = beta[k] - mean * sc;
    }
}

// ---------------- fold BN into linear weights: bf16 split + beff ------------
__global__ __launch_bounds__(256) void weff_kernel(const float* __restrict__ w,
                                                   const float* __restrict__ b) {
    const int e0 = (blockIdx.x * 256 + threadIdx.x) * 4;
    const int j = e0 >> 8;
    const int k0 = e0 & 255;
    float4 wv = *(const float4*)(w + j * 256 + k0);
    float4 sv = *(const float4*)(g_scale + k0);
    float p0 = wv.x * sv.x, p1 = wv.y * sv.y, p2 = wv.z * sv.z, p3 = wv.w * sv.w;
    __nv_bfloat162 h01 = __floats2bfloat162_rn(p0, p1);
    __nv_bfloat162 h23 = __floats2bfloat162_rn(p2, p3);
    __nv_bfloat162 l01 = __floats2bfloat162_rn(p0 - __low2float(h01), p1 - __high2float(h01));
    __nv_bfloat162 l23 = __floats2bfloat162_rn(p2 - __low2float(h23), p3 - __high2float(h23));
    *(uint2*)(g_wBh + j * 256 + k0) = make_uint2(*(uint32_t*)&h01, *(uint32_t*)&h23);
    *(uint2*)(g_wBl + j * 256 + k0) = make_uint2(*(uint32_t*)&l01, *(uint32_t*)&l23);

    if (blockIdx.x < 16) {
        const int warp = threadIdx.x >> 5;
        const int lane = threadIdx.x & 31;
        const int jo = blockIdx.x * 8 + warp;
        const float4* wj = (const float4*)(w + jo * 256);
        const float4* sh4 = (const float4*)g_shift;
        float s = 0.f;
#pragma unroll
        for (int i = 0; i < 2; i++) {
            float4 a = wj[lane + 32 * i];
            float4 c4 = sh4[lane + 32 * i];
            s += a.x * c4.x + a.y * c4.y + a.z * c4.z + a.w * c4.w;
        }
        s = warp_sum(s);
        if (lane == 0) g_beff[jo] = b[jo] + s;
    }
}

// ---------------- HMMA linear: M=64 tiles, 128 CTAs -------------------------
#define L_AOP 5120
#define L_BBASE (2 * L_AOP)
#define L_STG (2 * L_AOP + 2 * OPSZ)
#define LIN_SMEM (2 * L_STG)

__global__ __launch_bounds__(256, 2) void linear_mma(int xsel,
                                                     const float* __restrict__ resid,
                                                     float* __restrict__ dst, int mode) {
    extern __shared__ char smem[];
    const int tid = threadIdx.x;
    const int lane = tid & 31;
    const int w = tid >> 5;
    const int wm = w >> 1;
    const int wn = w & 1;
    const int m0 = blockIdx.x * 64;

    const uint32_t sb = smem_u32(smem);
    const float* __restrict__ Xs = xsel ? g_bufX2 : g_bufX;

    const int a_row = wm * 16 + (lane & 7) + ((lane >> 3) & 1) * 8;
    const uint32_t aOff = (uint32_t)a_row * ROWB + ((lane >> 4) & 1) * 16;
    const int b_row = wn * 64 + (lane & 7) + ((lane >> 4) & 1) * 8;
    const uint32_t bOff = (uint32_t)b_row * ROWB + ((lane >> 3) & 1) * 16;

    const int garow = tid >> 2;
    const int gseg = tid & 3;
    const uint32_t aStOff = (uint32_t)garow * ROWB + gseg * 16;
    const int gbrow = tid >> 1;
    const int gbh = tid & 1;
    const __nv_bfloat16* Bhp = g_wBh + (size_t)gbrow * FEAT + gbh * 16;
    const __nv_bfloat16* Blp = g_wBl + (size_t)gbrow * FEAT + gbh * 16;
    const uint32_t bStOff = (uint32_t)gbrow * ROWB + gbh * 32;

    float acc[8][4];
#pragma unroll
    for (int j = 0; j < 8; j++)
#pragma unroll
        for (int q = 0; q < 4; q++) acc[j][q] = 0.f;

    float4 ar[2];

    auto aPtr = [&](int t) -> const float* {
        int kk = t * 32 + gseg * 8;
        return (kk < 128) ? (Xs + (size_t)(m0 + garow) * DIM + kk)
                          : (g_LxP + (size_t)(m0 + garow) * DIM + (kk - 128));
    };
    auto convA = [&](char* base, float4* v) {
        char* sAh = base + aStOff;
        char* sAl = base + L_AOP + aStOff;
#pragma unroll
        for (int i = 0; i < 2; i++) {
            float4 x = v[i];
            __nv_bfloat162 h01 = __floats2bfloat162_rn(x.x, x.y);
            __nv_bfloat162 h23 = __floats2bfloat162_rn(x.z, x.w);
            __nv_bfloat162 l01 = __floats2bfloat162_rn(x.x - __low2float(h01), x.y - __high2float(h01));
            __nv_bfloat162 l23 = __floats2bfloat162_rn(x.z - __low2float(h23), x.w - __high2float(h23));
            *(uint2*)(sAh + 8 * i) = make_uint2(*(uint32_t*)&h01, *(uint32_t*)&h23);
            *(uint2*)(sAl + 8 * i) = make_uint2(*(uint32_t*)&l01, *(uint32_t*)&l23);
        }
    };

    cpasync16(sb + L_BBASE + bStOff,              Bhp);
    cpasync16(sb + L_BBASE + bStOff + 16,         Bhp + 8);
    cpasync16(sb + L_BBASE + OPSZ + bStOff,       Blp);
    cpasync16(sb + L_BBASE + OPSZ + bStOff + 16,  Blp + 8);
    cp_commit();
    {
        const float* ap = aPtr(0);
        ar[0] = *(const float4*)ap;
        ar[1] = *(const float4*)(ap + 4);
        convA(smem, ar);
    }

    const int T = FEAT / 32;  // 8

    for (int t = 0; t < T; t++) {
        cp_wait0();
        __syncthreads();
        const int s = t & 1;
        const uint32_t sA = sb + s * L_STG;
        const uint32_t nsBase = sb + (s ^ 1) * L_STG;
        const bool more = (t + 1) < T;
        if (more) {
            const int off = (t + 1) * 32;
            cpasync16(nsBase + L_BBASE + bStOff,              Bhp + off);
            cpasync16(nsBase + L_BBASE + bStOff + 16,         Bhp + off + 8);
            cpasync16(nsBase + L_BBASE + OPSZ + bStOff,       Blp + off);
            cpasync16(nsBase + L_BBASE + OPSZ + bStOff + 16,  Blp + off + 8);
            cp_commit();
            const float* ap = aPtr(t + 1);
            ar[0] = *(const float4*)ap;
            ar[1] = *(const float4*)(ap + 4);
        }

#pragma unroll
        for (int ks = 0; ks < 2; ks++) {
            const uint32_t kb = ks * 32;
            uint32_t Ah[4], Al[4];
            ldmx4(Ah, sA + aOff + kb);
            ldmx4(Al, sA + L_AOP + aOff + kb);
#pragma unroll
            for (int qh = 0; qh < 2; qh++) {
                uint32_t Bh2[2][4], Bl2[2][4];
#pragma unroll
                for (int qq = 0; qq < 2; qq++) {
                    const int q = qh * 2 + qq;
                    ldmx4(Bh2[qq], sA + L_BBASE + bOff + q * (16 * ROWB) + kb);
                    ldmx4(Bl2[qq], sA + L_BBASE + OPSZ + bOff + q * (16 * ROWB) + kb);
                }
#pragma unroll
                for (int qq = 0; qq < 2; qq++)
#pragma unroll
                    for (int j = 0; j < 2; j++) {
                        const int nf = qh * 4 + qq * 2 + j;
                        const int rr = j * 2;
                        mma_bf16(acc[nf], Ah, Bh2[qq][rr], Bh2[qq][rr + 1]);
                        mma_bf16(acc[nf], Ah, Bl2[qq][rr], Bl2[qq][rr + 1]);
                        mma_bf16(acc[nf], Al, Bh2[qq][rr], Bh2[qq][rr + 1]);
                    }
            }
        }

        if (more) {
            convA(smem + (s ^ 1) * L_STG, ar);
        }
    }

    const int g = lane >> 2, t4 = lane & 3;
    const int row0 = m0 + wm * 16 + g;
#pragma unroll
    for (int nf = 0; nf < 8; nf++) {
        const int col = wn * 64 + nf * 8 + t4 * 2;
        float b0 = g_beff[col], b1 = g_beff[col + 1];
        float y0 = acc[nf][0] + b0;
        float y1 = acc[nf][1] + b1;
        float y2 = acc[nf][2] + b0;
        float y3 = acc[nf][3] + b1;
        if (mode == 0) {
            float v0 = eluf(y0), v1 = eluf(y1), v2 = eluf(y2), v3 = eluf(y3);
            *(float2*)(g_bufX2 + (size_t)row0 * DIM + col) = make_float2(v0, v1);
            *(float2*)(g_bufX2 + (size_t)(row0 + 8) * DIM + col) = make_float2(v2, v3);
            __nv_bfloat16 h, l;
            split_bf16(v0, h, l);
            g_Bh[(size_t)col * MTOT + row0] = h;       g_Bl[(size_t)col * MTOT + row0] = l;
            split_bf16(v1, h, l);
            g_Bh[(size_t)(col + 1) * MTOT + row0] = h; g_Bl[(size_t)(col + 1) * MTOT + row0] = l;
            split_bf16(v2, h, l);
            g_Bh[(size_t)col * MTOT + row0 + 8] = h;       g_Bl[(size_t)col * MTOT + row0 + 8] = l;
            split_bf16(v3, h, l);
            g_Bh[(size_t)(col + 1) * MTOT + row0 + 8] = h; g_Bl[(size_t)(col + 1) * MTOT + row0 + 8] = l;
        } else {
            float r0v = resid[(size_t)row0 * DIM + col];
            float r1v = resid[(size_t)row0 * DIM + col + 1];
            float r2v = resid[(size_t)(row0 + 8) * DIM + col];
            float r3v = resid[(size_t)(row0 + 8) * DIM + col + 1];
            *(float2*)(dst + (size_t)row0 * DIM + col) = make_float2(y0 + r0v, y1 + r1v);
            *(float2*)(dst + (size_t)(row0 + 8) * DIM + col) = make_float2(y2 + r2v, y3 + r3v);
        }
    }
}

// ---------------- launch ----------------------------------------------------
extern "C" void kernel_launch(void* const* d_in, const int* in_sizes, int n_in,
                              void* d_out, int out_size) {
    const float* L      = (const float*)d_in[0];
    const float* inputs = (const float*)d_in[2];
    const float* bn0_g  = (const float*)d_in[3];
    const float* bn0_b  = (const float*)d_in[4];
    const float* fc0_w  = (const float*)d_in[5];
    const float* fc0_b  = (const float*)d_in[6];
    const float* bn1_g  = (const float*)d_in[7];
    const float* bn1_b  = (const float*)d_in[8];
    const float* fc1_w  = (const float*)d_in[9];
    const float* fc1_b  = (const float*)d_in[10];
    float* out = (float*)d_out;

    cudaFuncSetAttribute(sgemm_mma, cudaFuncAttributeMaxDynamicSharedMemorySize, SGEMM_SMEM);
    cudaFuncSetAttribute(linear_mma, cudaFuncAttributeMaxDynamicSharedMemorySize, LIN_SMEM);

    // ---- block 0 ----
    pack_kernel<<<128, 256>>>(inputs);
    sgemm_mma<<<512, 256, SGEMM_SMEM>>>(L, 0);   // fold + stats fused into tail
    stats_final<<<32, 256>>>(bn0_g, bn0_b);
    weff_kernel<<<32, 256>>>(fc0_w, fc0_b);
    linear_mma<<<128, 256, LIN_SMEM>>>(0, nullptr, nullptr, 0);  // packs B for block 1

    // ---- block 1 ----
    sgemm_mma<<<512, 256, SGEMM_SMEM>>>(L, 1);
    stats_final<<<32, 256>>>(bn1_g, bn1_b);
    weff_kernel<<<32, 256>>>(fc1_w, fc1_b);
    linear_mma<<<128, 256, LIN_SMEM>>>(1, inputs, out, 1);
}

// round 12
// speedup vs baseline: 1.0734x; 1.0734x over previous
#include <cuda_runtime.h>
#include <cuda_bf16.h>
#include <math.h>
#include <stdint.h>

#define MTOT 8192
#define KDIM 8192
#define DIM 128
#define FEAT 256
#define EPSV 1e-5f
#define STATS_BLOCKS 128
#define NKSL 8

// ---------------- scratch (device globals; no allocs allowed) ----------------
__device__ float g_bufX [MTOT * DIM];
__device__ float g_bufX2[MTOT * DIM];
__device__ float g_LxP [NKSL * MTOT * DIM];  // K-slice partials (slice 0 -> folded sum)
__device__ __nv_bfloat16 g_Bh[DIM * MTOT];   // B^T bf16 hi [feat][node]
__device__ __nv_bfloat16 g_Bl[DIM * MTOT];
__device__ float g_partials[4 * DIM * STATS_BLOCKS];  // [quad][feat][block]
__device__ __nv_bfloat16 g_wBh[DIM * FEAT];  // folded weights bf16 [j][k]
__device__ __nv_bfloat16 g_wBl[DIM * FEAT];
__device__ float g_beff[DIM];

// ---------------- helpers ----------------
__device__ __forceinline__ uint32_t smem_u32(const void* p) {
    uint32_t a;
    asm("{ .reg .u64 t; cvta.to.shared.u64 t, %1; cvt.u32.u64 %0, t; }" : "=r"(a) : "l"(p));
    return a;
}
__device__ __forceinline__ void ldmx4(uint32_t* r, uint32_t addr) {
    asm volatile("ldmatrix.sync.aligned.m8n8.x4.shared.b16 {%0,%1,%2,%3}, [%4];"
                 : "=r"(r[0]), "=r"(r[1]), "=r"(r[2]), "=r"(r[3]) : "r"(addr));
}
__device__ __forceinline__ void mma_bf16(float* d, const uint32_t* a, uint32_t b0, uint32_t b1) {
    asm volatile(
        "mma.sync.aligned.m16n8k16.row.col.f32.bf16.bf16.f32 "
        "{%0,%1,%2,%3}, {%4,%5,%6,%7}, {%8,%9}, {%0,%1,%2,%3};"
        : "+f"(d[0]), "+f"(d[1]), "+f"(d[2]), "+f"(d[3])
        : "r"(a[0]), "r"(a[1]), "r"(a[2]), "r"(a[3]), "r"(b0), "r"(b1));
}
__device__ __forceinline__ void cpasync16(uint32_t dst, const void* src) {
    asm volatile("cp.async.cg.shared.global [%0], [%1], 16;" :: "r"(dst), "l"(src));
}
__device__ __forceinline__ void cp_commit() { asm volatile("cp.async.commit_group;"); }
__device__ __forceinline__ void cp_wait0()  { asm volatile("cp.async.wait_group 0;" ::: "memory"); }

__device__ __forceinline__ float eluf(float v) { return v > 0.f ? v : expm1f(v); }

__device__ __forceinline__ float warp_sum(float v) {
#pragma unroll
    for (int o = 16; o > 0; o >>= 1) v += __shfl_xor_sync(0xFFFFFFFFu, v, o);
    return v;
}
__device__ __forceinline__ void split_bf16(float v, __nv_bfloat16& h, __nv_bfloat16& l) {
    h = __float2bfloat16(v);
    l = __float2bfloat16(v - __bfloat162float(h));
}

// ---------------- pack: inputs -> ELU -> g_bufX + B^T bf16 hi/lo ------------
__global__ __launch_bounds__(256) void pack_kernel(const float* __restrict__ src) {
    __shared__ float tile[128][65];
    const int tid = threadIdx.x;
    const int node0 = blockIdx.x * 64;

    const float4* sv = (const float4*)src + (size_t)node0 * 32;
    float4* xv = (float4*)g_bufX + (size_t)node0 * 32;
#pragma unroll
    for (int i = 0; i < 8; i++) {
        int idx = tid + 256 * i;
        int node = idx >> 5;
        int fq = idx & 31;
        float4 v = sv[idx];
        v.x = eluf(v.x); v.y = eluf(v.y); v.z = eluf(v.z); v.w = eluf(v.w);
        xv[idx] = v;
        tile[fq * 4 + 0][node] = v.x;
        tile[fq * 4 + 1][node] = v.y;
        tile[fq * 4 + 2][node] = v.z;
        tile[fq * 4 + 3][node] = v.w;
    }
    __syncthreads();

    const int feat = tid >> 1;
    const int h = tid & 1;
    const float* r = &tile[feat][h * 32];
    uint32_t hi[16], lo[16];
#pragma unroll
    for (int j = 0; j < 16; j++) {
        float a = r[2 * j], b = r[2 * j + 1];
        __nv_bfloat162 hb = __floats2bfloat162_rn(a, b);
        float ha = __low2float(hb), hbv = __high2float(hb);
        __nv_bfloat162 lb = __floats2bfloat162_rn(a - ha, b - hbv);
        hi[j] = *(uint32_t*)&hb;
        lo[j] = *(uint32_t*)&lb;
    }
    uint4* oh = (uint4*)(g_Bh + (size_t)feat * MTOT + node0 + h * 32);
    uint4* ol = (uint4*)(g_Bl + (size_t)feat * MTOT + node0 + h * 32);
#pragma unroll
    for (int blk = 0; blk < 4; blk++) {
        oh[blk] = make_uint4(hi[4 * blk], hi[4 * blk + 1], hi[4 * blk + 2], hi[4 * blk + 3]);
        ol[blk] = make_uint4(lo[4 * blk], lo[4 * blk + 1], lo[4 * blk + 2], lo[4 * blk + 3]);
    }
}

// ---------------- split-bf16 HMMA GEMM (validated R10 core) -----------------
#define ROWB 80
#define OPSZ 10240
#define STGSZ 40960
#define SGEMM_SMEM (2 * STGSZ)

__global__ __launch_bounds__(256, 2) void sgemm_mma(const float* __restrict__ L) {
    extern __shared__ char smem[];
    const int tid = threadIdx.x;
    const int lane = tid & 31;
    const int w = tid >> 5;
    const int wm = w >> 1;
    const int wn = w & 1;
    const int mtile = blockIdx.x >> 3;
    const int ksl = blockIdx.x & 7;
    const int m0 = mtile * 128;
    const int kc0 = ksl * 1024;

    const uint32_t sb = smem_u32(smem);

    const int a_row = wm * 32 + (lane & 7) + ((lane >> 3) & 1) * 8;
    const uint32_t aOff = (uint32_t)a_row * ROWB + ((lane >> 4) & 1) * 16;
    const int b_row = wn * 64 + (lane & 7) + ((lane >> 4) & 1) * 8;
    const uint32_t bOff = (uint32_t)b_row * ROWB + ((lane >> 3) & 1) * 16;

    const int grow = tid >> 1;
    const int gh = tid & 1;
    const float* Ap = L + (size_t)(m0 + grow) * KDIM + kc0 + gh * 16;
    const __nv_bfloat16* Bhp = g_Bh + (size_t)grow * MTOT + kc0 + gh * 16;
    const __nv_bfloat16* Blp = g_Bl + (size_t)grow * MTOT + kc0 + gh * 16;
    const uint32_t aStOff = (uint32_t)grow * ROWB + gh * 32;

    float acc[2][8][4];
#pragma unroll
    for (int i = 0; i < 2; i++)
#pragma unroll
        for (int j = 0; j < 8; j++)
#pragma unroll
            for (int q = 0; q < 4; q++) acc[i][j][q] = 0.f;

    float4 ar[4];

    cpasync16(sb + 2 * OPSZ + aStOff,      Bhp);
    cpasync16(sb + 2 * OPSZ + aStOff + 16, Bhp + 8);
    cpasync16(sb + 3 * OPSZ + aStOff,      Blp);
    cpasync16(sb + 3 * OPSZ + aStOff + 16, Blp + 8);
    cp_commit();
#pragma unroll
    for (int i = 0; i < 4; i++) ar[i] = *(const float4*)(Ap + 4 * i);
    {
        char* sAh = smem + aStOff;
        char* sAl = smem + OPSZ + aStOff;
#pragma unroll
        for (int i = 0; i < 4; i++) {
            float4 v = ar[i];
            __nv_bfloat162 h01 = __floats2bfloat162_rn(v.x, v.y);
            __nv_bfloat162 h23 = __floats2bfloat162_rn(v.z, v.w);
            __nv_bfloat162 l01 = __floats2bfloat162_rn(v.x - __low2float(h01), v.y - __high2float(h01));
            __nv_bfloat162 l23 = __floats2bfloat162_rn(v.z - __low2float(h23), v.w - __high2float(h23));
            *(uint2*)(sAh + 8 * i) = make_uint2(*(uint32_t*)&h01, *(uint32_t*)&h23);
            *(uint2*)(sAl + 8 * i) = make_uint2(*(uint32_t*)&l01, *(uint32_t*)&l23);
        }
    }

    const int T = 1024 / 32;  // 32

    for (int t = 0; t < T; t++) {
        cp_wait0();
        __syncthreads();
        const int s = t & 1;
        const uint32_t sA = sb + s * STGSZ;
        const uint32_t nsBase = sb + (s ^ 1) * STGSZ;
        const bool more = (t + 1) < T;
        if (more) {
            const int off = (t + 1) * 32;
            cpasync16(nsBase + 2 * OPSZ + aStOff,      Bhp + off);
            cpasync16(nsBase + 2 * OPSZ + aStOff + 16, Bhp + off + 8);
            cpasync16(nsBase + 3 * OPSZ + aStOff,      Blp + off);
            cpasync16(nsBase + 3 * OPSZ + aStOff + 16, Blp + off + 8);
            cp_commit();
#pragma unroll
            for (int i = 0; i < 4; i++) ar[i] = *(const float4*)(Ap + off + 4 * i);
        }

#pragma unroll
        for (int ks = 0; ks < 2; ks++) {
            const uint32_t kb = ks * 32;
            uint32_t Ah[2][4], Al[2][4];
#pragma unroll
            for (int mf = 0; mf < 2; mf++) {
                ldmx4(Ah[mf], sA + aOff + mf * (16 * ROWB) + kb);
                ldmx4(Al[mf], sA + OPSZ + aOff + mf * (16 * ROWB) + kb);
            }
#pragma unroll
            for (int qh = 0; qh < 2; qh++) {
                uint32_t Bh2[2][4], Bl2[2][4];
#pragma unroll
                for (int qq = 0; qq < 2; qq++) {
                    const int q = qh * 2 + qq;
                    ldmx4(Bh2[qq], sA + 2 * OPSZ + bOff + q * (16 * ROWB) + kb);
                    ldmx4(Bl2[qq], sA + 3 * OPSZ + bOff + q * (16 * ROWB) + kb);
                }
#pragma unroll
                for (int mf = 0; mf < 2; mf++)
#pragma unroll
                    for (int qq = 0; qq < 2; qq++)
#pragma unroll
                        for (int j = 0; j < 2; j++) {
                            const int nf = qh * 4 + qq * 2 + j;
                            const int rr = j * 2;
                            mma_bf16(acc[mf][nf], Ah[mf], Bh2[qq][rr], Bh2[qq][rr + 1]);
                            mma_bf16(acc[mf][nf], Ah[mf], Bl2[qq][rr], Bl2[qq][rr + 1]);
                            mma_bf16(acc[mf][nf], Al[mf], Bh2[qq][rr], Bh2[qq][rr + 1]);
                        }
            }
        }

        if (more) {
            char* other = smem + (s ^ 1) * STGSZ;
            char* sAh = other + aStOff;
            char* sAl = other + OPSZ + aStOff;
#pragma unroll
            for (int i = 0; i < 4; i++) {
                float4 v = ar[i];
                __nv_bfloat162 h01 = __floats2bfloat162_rn(v.x, v.y);
                __nv_bfloat162 h23 = __floats2bfloat162_rn(v.z, v.w);
                __nv_bfloat162 l01 = __floats2bfloat162_rn(v.x - __low2float(h01), v.y - __high2float(h01));
                __nv_bfloat162 l23 = __floats2bfloat162_rn(v.z - __low2float(h23), v.w - __high2float(h23));
                *(uint2*)(sAh + 8 * i) = make_uint2(*(uint32_t*)&h01, *(uint32_t*)&h23);
                *(uint2*)(sAl + 8 * i) = make_uint2(*(uint32_t*)&l01, *(uint32_t*)&l23);
            }
        }
    }

    float* outb = g_LxP + (size_t)ksl * (MTOT * DIM);
    const int g = lane >> 2, t4 = lane & 3;
#pragma unroll
    for (int mf = 0; mf < 2; mf++) {
        const int row0 = m0 + wm * 32 + mf * 16 + g;
#pragma unroll
        for (int nf = 0; nf < 8; nf++) {
            const int col = wn * 64 + nf * 8 + t4 * 2;
            *(float2*)(outb + (size_t)row0 * DIM + col) =
                make_float2(acc[mf][nf][0], acc[mf][nf][1]);
            *(float2*)(outb + (size_t)(row0 + 8) * DIM + col) =
                make_float2(acc[mf][nf][2], acc[mf][nf][3]);
        }
    }
}

// ---------------- BN stats pass 1 + K-split fold ----------------------------
__global__ __launch_bounds__(256) void stats_partial(int xsel) {
    const float* __restrict__ X = xsel ? g_bufX2 : g_bufX;
    const int tid = threadIdx.x;
    const int c = tid & 127;
    const int half = tid >> 7;
    const int rpb = MTOT / STATS_BLOCKS;   // 64
    const int r0 = blockIdx.x * rpb;

    float sx = 0.f, sxx = 0.f, sl = 0.f, sll = 0.f;
#pragma unroll 4
    for (int r = r0 + half; r < r0 + rpb; r += 2) {
        float v = X[r * DIM + c];
        sx += v; sxx += v * v;
        size_t idx = (size_t)r * DIM + c;
        float w = 0.f;
#pragma unroll
        for (int q = 0; q < NKSL; q++) w += g_LxP[idx + (size_t)q * MTOT * DIM];
        g_LxP[idx] = w;
        sl += w; sll += w * w;
    }
    __shared__ float sh[256];
    const int b = blockIdx.x;
    sh[tid] = sx;  __syncthreads();
    if (tid < 128) g_partials[(0 * 128 + c) * STATS_BLOCKS + b] = sh[tid] + sh[tid + 128];
    __syncthreads();
    sh[tid] = sxx; __syncthreads();
    if (tid < 128) g_partials[(1 * 128 + c) * STATS_BLOCKS + b] = sh[tid] + sh[tid + 128];
    __syncthreads();
    sh[tid] = sl;  __syncthreads();
    if (tid < 128) g_partials[(2 * 128 + c) * STATS_BLOCKS + b] = sh[tid] + sh[tid + 128];
    __syncthreads();
    sh[tid] = sll; __syncthreads();
    if (tid < 128) g_partials[(3 * 128 + c) * STATS_BLOCKS + b] = sh[tid] + sh[tid + 128];
}

// ---------------- finalize: stats pass 2 + BN-fold weights + beff -----------
// grid 32 x 256. Each block redundantly reduces all 256 features' stats
// (64 float4 loads per thread, L2-resident) into smem scale/shift, then does
// its share of the wT bf16 scatter; blocks 0..15 also compute beff.
__global__ __launch_bounds__(256) void finalize_kernel(const float* __restrict__ gamma,
                                                       const float* __restrict__ beta,
                                                       const float* __restrict__ w,
                                                       const float* __restrict__ b) {
    __shared__ float s_scale[FEAT];
    __shared__ float s_shift[FEAT];
    const int tid = threadIdx.x;

    // phase 1: thread k reduces feature k over STATS_BLOCKS partials
    {
        const int base = (tid < 128) ? 0 : 2;
        const int c = tid & 127;
        const float4* ps = (const float4*)(g_partials + (size_t)(base * 128 + c) * STATS_BLOCKS);
        const float4* pq = (const float4*)(g_partials + (size_t)((base + 1) * 128 + c) * STATS_BLOCKS);
        float s = 0.f, ss = 0.f;
#pragma unroll
        for (int i = 0; i < STATS_BLOCKS / 4; i++) {   // 32
            float4 a = ps[i];
            float4 q = pq[i];
            s  += (a.x + a.y) + (a.z + a.w);
            ss += (q.x + q.y) + (q.z + q.w);
        }
        float mean = s / (float)MTOT;
        float var  = ss / (float)MTOT - mean * mean;
        float sc   = rsqrtf(var + EPSV) * gamma[tid];
        s_scale[tid] = sc;
        s_shift[tid] = beta[tid] - mean * sc;
    }
    __syncthreads();

    // phase 2: wT scatter (this block's 1/32 share of [j][k])
    {
        const int e0 = (blockIdx.x * 256 + tid) * 4;
        const int j = e0 >> 8;
        const int k0 = e0 & 255;
        float4 wv = *(const float4*)(w + j * 256 + k0);
        float p0 = wv.x * s_scale[k0 + 0];
        float p1 = wv.y * s_scale[k0 + 1];
        float p2 = wv.z * s_scale[k0 + 2];
        float p3 = wv.w * s_scale[k0 + 3];
        __nv_bfloat162 h01 = __floats2bfloat162_rn(p0, p1);
        __nv_bfloat162 h23 = __floats2bfloat162_rn(p2, p3);
        __nv_bfloat162 l01 = __floats2bfloat162_rn(p0 - __low2float(h01), p1 - __high2float(h01));
        __nv_bfloat162 l23 = __floats2bfloat162_rn(p2 - __low2float(h23), p3 - __high2float(h23));
        *(uint2*)(g_wBh + j * 256 + k0) = make_uint2(*(uint32_t*)&h01, *(uint32_t*)&h23);
        *(uint2*)(g_wBl + j * 256 + k0) = make_uint2(*(uint32_t*)&l01, *(uint32_t*)&l23);
    }

    // phase 3: beff (blocks 0..15, one warp per output)
    if (blockIdx.x < 16) {
        const int warp = tid >> 5;
        const int lane = tid & 31;
        const int jo = blockIdx.x * 8 + warp;
        const float4* wj = (const float4*)(w + jo * 256);
        const float4* sh4 = (const float4*)s_shift;
        float s = 0.f;
#pragma unroll
        for (int i = 0; i < 2; i++) {
            float4 a = wj[lane + 32 * i];
            float4 c4 = sh4[lane + 32 * i];
            s += a.x * c4.x + a.y * c4.y + a.z * c4.z + a.w * c4.w;
        }
        s = warp_sum(s);
        if (lane == 0) g_beff[jo] = b[jo] + s;
    }
}

// ---------------- HMMA linear: M=64 tiles, 128 CTAs -------------------------
#define L_AOP 5120
#define L_BBASE (2 * L_AOP)
#define L_STG (2 * L_AOP + 2 * OPSZ)
#define LIN_SMEM (2 * L_STG)

__global__ __launch_bounds__(256, 2) void linear_mma(int xsel,
                                                     const float* __restrict__ resid,
                                                     float* __restrict__ dst, int mode) {
    extern __shared__ char smem[];
    const int tid = threadIdx.x;
    const int lane = tid & 31;
    const int w = tid >> 5;
    const int wm = w >> 1;
    const int wn = w & 1;
    const int m0 = blockIdx.x * 64;

    const uint32_t sb = smem_u32(smem);
    const float* __restrict__ Xs = xsel ? g_bufX2 : g_bufX;

    const int a_row = wm * 16 + (lane & 7) + ((lane >> 3) & 1) * 8;
    const uint32_t aOff = (uint32_t)a_row * ROWB + ((lane >> 4) & 1) * 16;
    const int b_row = wn * 64 + (lane & 7) + ((lane >> 4) & 1) * 8;
    const uint32_t bOff = (uint32_t)b_row * ROWB + ((lane >> 3) & 1) * 16;

    const int garow = tid >> 2;
    const int gseg = tid & 3;
    const uint32_t aStOff = (uint32_t)garow * ROWB + gseg * 16;
    const int gbrow = tid >> 1;
    const int gbh = tid & 1;
    const __nv_bfloat16* Bhp = g_wBh + (size_t)gbrow * FEAT + gbh * 16;
    const __nv_bfloat16* Blp = g_wBl + (size_t)gbrow * FEAT + gbh * 16;
    const uint32_t bStOff = (uint32_t)gbrow * ROWB + gbh * 32;

    float acc[8][4];
#pragma unroll
    for (int j = 0; j < 8; j++)
#pragma unroll
        for (int q = 0; q < 4; q++) acc[j][q] = 0.f;

    float4 ar[2];

    auto aPtr = [&](int t) -> const float* {
        int kk = t * 32 + gseg * 8;
        return (kk < 128) ? (Xs + (size_t)(m0 + garow) * DIM + kk)
                          : (g_LxP + (size_t)(m0 + garow) * DIM + (kk - 128));
    };
    auto convA = [&](char* base, float4* v) {
        char* sAh = base + aStOff;
        char* sAl = base + L_AOP + aStOff;
#pragma unroll
        for (int i = 0; i < 2; i++) {
            float4 x = v[i];
            __nv_bfloat162 h01 = __floats2bfloat162_rn(x.x, x.y);
            __nv_bfloat162 h23 = __floats2bfloat162_rn(x.z, x.w);
            __nv_bfloat162 l01 = __floats2bfloat162_rn(x.x - __low2float(h01), x.y - __high2float(h01));
            __nv_bfloat162 l23 = __floats2bfloat162_rn(x.z - __low2float(h23), x.w - __high2float(h23));
            *(uint2*)(sAh + 8 * i) = make_uint2(*(uint32_t*)&h01, *(uint32_t*)&h23);
            *(uint2*)(sAl + 8 * i) = make_uint2(*(uint32_t*)&l01, *(uint32_t*)&l23);
        }
    };

    cpasync16(sb + L_BBASE + bStOff,              Bhp);
    cpasync16(sb + L_BBASE + bStOff + 16,         Bhp + 8);
    cpasync16(sb + L_BBASE + OPSZ + bStOff,       Blp);
    cpasync16(sb + L_BBASE + OPSZ + bStOff + 16,  Blp + 8);
    cp_commit();
    {
        const float* ap = aPtr(0);
        ar[0] = *(const float4*)ap;
        ar[1] = *(const float4*)(ap + 4);
        convA(smem, ar);
    }

    const int T = FEAT / 32;  // 8

    for (int t = 0; t < T; t++) {
        cp_wait0();
        __syncthreads();
        const int s = t & 1;
        const uint32_t sA = sb + s * L_STG;
        const uint32_t nsBase = sb + (s ^ 1) * L_STG;
        const bool more = (t + 1) < T;
        if (more) {
            const int off = (t + 1) * 32;
            cpasync16(nsBase + L_BBASE + bStOff,              Bhp + off);
            cpasync16(nsBase + L_BBASE + bStOff + 16,         Bhp + off + 8);
            cpasync16(nsBase + L_BBASE + OPSZ + bStOff,       Blp + off);
            cpasync16(nsBase + L_BBASE + OPSZ + bStOff + 16,  Blp + off + 8);
            cp_commit();
            const float* ap = aPtr(t + 1);
            ar[0] = *(const float4*)ap;
            ar[1] = *(const float4*)(ap + 4);
        }

#pragma unroll
        for (int ks = 0; ks < 2; ks++) {
            const uint32_t kb = ks * 32;
            uint32_t Ah[4], Al[4];
            ldmx4(Ah, sA + aOff + kb);
            ldmx4(Al, sA + L_AOP + aOff + kb);
#pragma unroll
            for (int qh = 0; qh < 2; qh++) {
                uint32_t Bh2[2][4], Bl2[2][4];
#pragma unroll
                for (int qq = 0; qq < 2; qq++) {
                    const int q = qh * 2 + qq;
                    ldmx4(Bh2[qq], sA + L_BBASE + bOff + q * (16 * ROWB) + kb);
                    ldmx4(Bl2[qq], sA + L_BBASE + OPSZ + bOff + q * (16 * ROWB) + kb);
                }
#pragma unroll
                for (int qq = 0; qq < 2; qq++)
#pragma unroll
                    for (int j = 0; j < 2; j++) {
                        const int nf = qh * 4 + qq * 2 + j;
                        const int rr = j * 2;
                        mma_bf16(acc[nf], Ah, Bh2[qq][rr], Bh2[qq][rr + 1]);
                        mma_bf16(acc[nf], Ah, Bl2[qq][rr], Bl2[qq][rr + 1]);
                        mma_bf16(acc[nf], Al, Bh2[qq][rr], Bh2[qq][rr + 1]);
                    }
            }
        }

        if (more) {
            convA(smem + (s ^ 1) * L_STG, ar);
        }
    }

    const int g = lane >> 2, t4 = lane & 3;
    const int row0 = m0 + wm * 16 + g;
#pragma unroll
    for (int nf = 0; nf < 8; nf++) {
        const int col = wn * 64 + nf * 8 + t4 * 2;
        float b0 = g_beff[col], b1 = g_beff[col + 1];
        float y0 = acc[nf][0] + b0;
        float y1 = acc[nf][1] + b1;
        float y2 = acc[nf][2] + b0;
        float y3 = acc[nf][3] + b1;
        if (mode == 0) {
            float v0 = eluf(y0), v1 = eluf(y1), v2 = eluf(y2), v3 = eluf(y3);
            *(float2*)(g_bufX2 + (size_t)row0 * DIM + col) = make_float2(v0, v1);
            *(float2*)(g_bufX2 + (size_t)(row0 + 8) * DIM + col) = make_float2(v2, v3);
            __nv_bfloat16 h, l;
            split_bf16(v0, h, l);
            g_Bh[(size_t)col * MTOT + row0] = h;       g_Bl[(size_t)col * MTOT + row0] = l;
            split_bf16(v1, h, l);
            g_Bh[(size_t)(col + 1) * MTOT + row0] = h; g_Bl[(size_t)(col + 1) * MTOT + row0] = l;
            split_bf16(v2, h, l);
            g_Bh[(size_t)col * MTOT + row0 + 8] = h;       g_Bl[(size_t)col * MTOT + row0 + 8] = l;
            split_bf16(v3, h, l);
            g_Bh[(size_t)(col + 1) * MTOT + row0 + 8] = h; g_Bl[(size_t)(col + 1) * MTOT + row0 + 8] = l;
        } else {
            float r0v = resid[(size_t)row0 * DIM + col];
            float r1v = resid[(size_t)row0 * DIM + col + 1];
            float r2v = resid[(size_t)(row0 + 8) * DIM + col];
            float r3v = resid[(size_t)(row0 + 8) * DIM + col + 1];
            *(float2*)(dst + (size_t)row0 * DIM + col) = make_float2(y0 + r0v, y1 + r1v);
            *(float2*)(dst + (size_t)(row0 + 8) * DIM + col) = make_float2(y2 + r2v, y3 + r3v);
        }
    }
}

// ---------------- launch ----------------------------------------------------
extern "C" void kernel_launch(void* const* d_in, const int* in_sizes, int n_in,
                              void* d_out, int out_size) {
    const float* L      = (const float*)d_in[0];
    const float* inputs = (const float*)d_in[2];
    const float* bn0_g  = (const float*)d_in[3];
    const float* bn0_b  = (const float*)d_in[4];
    const float* fc0_w  = (const float*)d_in[5];
    const float* fc0_b  = (const float*)d_in[6];
    const float* bn1_g  = (const float*)d_in[7];
    const float* bn1_b  = (const float*)d_in[8];
    const float* fc1_w  = (const float*)d_in[9];
    const float* fc1_b  = (const float*)d_in[10];
    float* out = (float*)d_out;

    cudaFuncSetAttribute(sgemm_mma, cudaFuncAttributeMaxDynamicSharedMemorySize, SGEMM_SMEM);
    cudaFuncSetAttribute(linear_mma, cudaFuncAttributeMaxDynamicSharedMemorySize, LIN_SMEM);

    // ---- block 0 ----
    pack_kernel<<<128, 256>>>(inputs);
    sgemm_mma<<<512, 256, SGEMM_SMEM>>>(L);
    stats_partial<<<STATS_BLOCKS, 256>>>(0);
    finalize_kernel<<<32, 256>>>(bn0_g, bn0_b, fc0_w, fc0_b);
    linear_mma<<<128, 256, LIN_SMEM>>>(0, nullptr, nullptr, 0);  // packs B for block 1

    // ---- block 1 ----
    sgemm_mma<<<512, 256, SGEMM_SMEM>>>(L);
    stats_partial<<<STATS_BLOCKS, 256>>>(1);
    finalize_kernel<<<32, 256>>>(bn1_g, bn1_b, fc1_w, fc1_b);
    linear_mma<<<128, 256, LIN_SMEM>>>(1, inputs, out, 1);
}

// round 13
// speedup vs baseline: 1.1845x; 1.1035x over previous
#include <cuda_runtime.h>
#include <cuda_bf16.h>
#include <math.h>
#include <stdint.h>

#define MTOT 8192
#define KDIM 8192
#define DIM 128
#define FEAT 256
#define EPSV 1e-5f
#define STATS_BLOCKS 512
#define NKSL 8

// ---------------- scratch (device globals; no allocs allowed) ----------------
__device__ float g_bufX [MTOT * DIM];
__device__ float g_bufX2[MTOT * DIM];
__device__ float g_LxP [NKSL * MTOT * DIM];  // K-slice partials (slice 0 -> folded sum)
__device__ __nv_bfloat16 g_Bh[DIM * MTOT];   // B^T bf16 hi [feat][node]
__device__ __nv_bfloat16 g_Bl[DIM * MTOT];
__device__ float g_partials[4 * DIM * STATS_BLOCKS];  // [quad][feat][block]
__device__ float g_scale[FEAT];
__device__ float g_shift[FEAT];
__device__ __nv_bfloat16 g_wBh[DIM * FEAT];  // folded weights bf16 [j][k]
__device__ __nv_bfloat16 g_wBl[DIM * FEAT];
__device__ float g_beff[DIM];

// ---------------- helpers ----------------
__device__ __forceinline__ uint32_t smem_u32(const void* p) {
    uint32_t a;
    asm("{ .reg .u64 t; cvta.to.shared.u64 t, %1; cvt.u32.u64 %0, t; }" : "=r"(a) : "l"(p));
    return a;
}
__device__ __forceinline__ void ldmx4(uint32_t* r, uint32_t addr) {
    asm volatile("ldmatrix.sync.aligned.m8n8.x4.shared.b16 {%0,%1,%2,%3}, [%4];"
                 : "=r"(r[0]), "=r"(r[1]), "=r"(r[2]), "=r"(r[3]) : "r"(addr));
}
__device__ __forceinline__ void mma_bf16(float* d, const uint32_t* a, uint32_t b0, uint32_t b1) {
    asm volatile(
        "mma.sync.aligned.m16n8k16.row.col.f32.bf16.bf16.f32 "
        "{%0,%1,%2,%3}, {%4,%5,%6,%7}, {%8,%9}, {%0,%1,%2,%3};"
        : "+f"(d[0]), "+f"(d[1]), "+f"(d[2]), "+f"(d[3])
        : "r"(a[0]), "r"(a[1]), "r"(a[2]), "r"(a[3]), "r"(b0), "r"(b1));
}
__device__ __forceinline__ void cpasync16(uint32_t dst, const void* src) {
    asm volatile("cp.async.cg.shared.global [%0], [%1], 16;" :: "r"(dst), "l"(src));
}
__device__ __forceinline__ void cp_commit() { asm volatile("cp.async.commit_group;"); }
__device__ __forceinline__ void cp_wait0()  { asm volatile("cp.async.wait_group 0;" ::: "memory"); }

__device__ __forceinline__ float eluf(float v) { return v > 0.f ? v : expm1f(v); }

__device__ __forceinline__ float warp_sum(float v) {
#pragma unroll
    for (int o = 16; o > 0; o >>= 1) v += __shfl_xor_sync(0xFFFFFFFFu, v, o);
    return v;
}
__device__ __forceinline__ void split_bf16(float v, __nv_bfloat16& h, __nv_bfloat16& l) {
    h = __float2bfloat16(v);
    l = __float2bfloat16(v - __bfloat162float(h));
}

// ---------------- pack: inputs -> ELU -> g_bufX + B^T bf16 hi/lo ------------
__global__ __launch_bounds__(256) void pack_kernel(const float* __restrict__ src) {
    __shared__ float tile[128][65];
    const int tid = threadIdx.x;
    const int node0 = blockIdx.x * 64;

    const float4* sv = (const float4*)src + (size_t)node0 * 32;
    float4* xv = (float4*)g_bufX + (size_t)node0 * 32;
#pragma unroll
    for (int i = 0; i < 8; i++) {
        int idx = tid + 256 * i;
        int node = idx >> 5;
        int fq = idx & 31;
        float4 v = sv[idx];
        v.x = eluf(v.x); v.y = eluf(v.y); v.z = eluf(v.z); v.w = eluf(v.w);
        xv[idx] = v;
        tile[fq * 4 + 0][node] = v.x;
        tile[fq * 4 + 1][node] = v.y;
        tile[fq * 4 + 2][node] = v.z;
        tile[fq * 4 + 3][node] = v.w;
    }
    __syncthreads();

    const int feat = tid >> 1;
    const int h = tid & 1;
    const float* r = &tile[feat][h * 32];
    uint32_t hi[16], lo[16];
#pragma unroll
    for (int j = 0; j < 16; j++) {
        float a = r[2 * j], b = r[2 * j + 1];
        __nv_bfloat162 hb = __floats2bfloat162_rn(a, b);
        float ha = __low2float(hb), hbv = __high2float(hb);
        __nv_bfloat162 lb = __floats2bfloat162_rn(a - ha, b - hbv);
        hi[j] = *(uint32_t*)&hb;
        lo[j] = *(uint32_t*)&lb;
    }
    uint4* oh = (uint4*)(g_Bh + (size_t)feat * MTOT + node0 + h * 32);
    uint4* ol = (uint4*)(g_Bl + (size_t)feat * MTOT + node0 + h * 32);
#pragma unroll
    for (int blk = 0; blk < 4; blk++) {
        oh[blk] = make_uint4(hi[4 * blk], hi[4 * blk + 1], hi[4 * blk + 2], hi[4 * blk + 3]);
        ol[blk] = make_uint4(lo[4 * blk], lo[4 * blk + 1], lo[4 * blk + 2], lo[4 * blk + 3]);
    }
}

// ---------------- split-bf16 HMMA GEMM (validated R10 core) -----------------
#define ROWB 80
#define OPSZ 10240
#define STGSZ 40960
#define SGEMM_SMEM (2 * STGSZ)

__global__ __launch_bounds__(256, 2) void sgemm_mma(const float* __restrict__ L) {
    extern __shared__ char smem[];
    const int tid = threadIdx.x;
    const int lane = tid & 31;
    const int w = tid >> 5;
    const int wm = w >> 1;
    const int wn = w & 1;
    const int mtile = blockIdx.x >> 3;
    const int ksl = blockIdx.x & 7;
    const int m0 = mtile * 128;
    const int kc0 = ksl * 1024;

    const uint32_t sb = smem_u32(smem);

    const int a_row = wm * 32 + (lane & 7) + ((lane >> 3) & 1) * 8;
    const uint32_t aOff = (uint32_t)a_row * ROWB + ((lane >> 4) & 1) * 16;
    const int b_row = wn * 64 + (lane & 7) + ((lane >> 4) & 1) * 8;
    const uint32_t bOff = (uint32_t)b_row * ROWB + ((lane >> 3) & 1) * 16;

    const int grow = tid >> 1;
    const int gh = tid & 1;
    const float* Ap = L + (size_t)(m0 + grow) * KDIM + kc0 + gh * 16;
    const __nv_bfloat16* Bhp = g_Bh + (size_t)grow * MTOT + kc0 + gh * 16;
    const __nv_bfloat16* Blp = g_Bl + (size_t)grow * MTOT + kc0 + gh * 16;
    const uint32_t aStOff = (uint32_t)grow * ROWB + gh * 32;

    float acc[2][8][4];
#pragma unroll
    for (int i = 0; i < 2; i++)
#pragma unroll
        for (int j = 0; j < 8; j++)
#pragma unroll
            for (int q = 0; q < 4; q++) acc[i][j][q] = 0.f;

    float4 ar[4];

    cpasync16(sb + 2 * OPSZ + aStOff,      Bhp);
    cpasync16(sb + 2 * OPSZ + aStOff + 16, Bhp + 8);
    cpasync16(sb + 3 * OPSZ + aStOff,      Blp);
    cpasync16(sb + 3 * OPSZ + aStOff + 16, Blp + 8);
    cp_commit();
#pragma unroll
    for (int i = 0; i < 4; i++) ar[i] = *(const float4*)(Ap + 4 * i);
    {
        char* sAh = smem + aStOff;
        char* sAl = smem + OPSZ + aStOff;
#pragma unroll
        for (int i = 0; i < 4; i++) {
            float4 v = ar[i];
            __nv_bfloat162 h01 = __floats2bfloat162_rn(v.x, v.y);
            __nv_bfloat162 h23 = __floats2bfloat162_rn(v.z, v.w);
            __nv_bfloat162 l01 = __floats2bfloat162_rn(v.x - __low2float(h01), v.y - __high2float(h01));
            __nv_bfloat162 l23 = __floats2bfloat162_rn(v.z - __low2float(h23), v.w - __high2float(h23));
            *(uint2*)(sAh + 8 * i) = make_uint2(*(uint32_t*)&h01, *(uint32_t*)&h23);
            *(uint2*)(sAl + 8 * i) = make_uint2(*(uint32_t*)&l01, *(uint32_t*)&l23);
        }
    }

    const int T = 1024 / 32;  // 32

    for (int t = 0; t < T; t++) {
        cp_wait0();
        __syncthreads();
        const int s = t & 1;
        const uint32_t sA = sb + s * STGSZ;
        const uint32_t nsBase = sb + (s ^ 1) * STGSZ;
        const bool more = (t + 1) < T;
        if (more) {
            const int off = (t + 1) * 32;
            cpasync16(nsBase + 2 * OPSZ + aStOff,      Bhp + off);
            cpasync16(nsBase + 2 * OPSZ + aStOff + 16, Bhp + off + 8);
            cpasync16(nsBase + 3 * OPSZ + aStOff,      Blp + off);
            cpasync16(nsBase + 3 * OPSZ + aStOff + 16, Blp + off + 8);
            cp_commit();
#pragma unroll
            for (int i = 0; i < 4; i++) ar[i] = *(const float4*)(Ap + off + 4 * i);
        }

#pragma unroll
        for (int ks = 0; ks < 2; ks++) {
            const uint32_t kb = ks * 32;
            uint32_t Ah[2][4], Al[2][4];
#pragma unroll
            for (int mf = 0; mf < 2; mf++) {
                ldmx4(Ah[mf], sA + aOff + mf * (16 * ROWB) + kb);
                ldmx4(Al[mf], sA + OPSZ + aOff + mf * (16 * ROWB) + kb);
            }
#pragma unroll
            for (int qh = 0; qh < 2; qh++) {
                uint32_t Bh2[2][4], Bl2[2][4];
#pragma unroll
                for (int qq = 0; qq < 2; qq++) {
                    const int q = qh * 2 + qq;
                    ldmx4(Bh2[qq], sA + 2 * OPSZ + bOff + q * (16 * ROWB) + kb);
                    ldmx4(Bl2[qq], sA + 3 * OPSZ + bOff + q * (16 * ROWB) + kb);
                }
#pragma unroll
                for (int mf = 0; mf < 2; mf++)
#pragma unroll
                    for (int qq = 0; qq < 2; qq++)
#pragma unroll
                        for (int j = 0; j < 2; j++) {
                            const int nf = qh * 4 + qq * 2 + j;
                            const int rr = j * 2;
                            mma_bf16(acc[mf][nf], Ah[mf], Bh2[qq][rr], Bh2[qq][rr + 1]);
                            mma_bf16(acc[mf][nf], Ah[mf], Bl2[qq][rr], Bl2[qq][rr + 1]);
                            mma_bf16(acc[mf][nf], Al[mf], Bh2[qq][rr], Bh2[qq][rr + 1]);
                        }
            }
        }

        if (more) {
            char* other = smem + (s ^ 1) * STGSZ;
            char* sAh = other + aStOff;
            char* sAl = other + OPSZ + aStOff;
#pragma unroll
            for (int i = 0; i < 4; i++) {
                float4 v = ar[i];
                __nv_bfloat162 h01 = __floats2bfloat162_rn(v.x, v.y);
                __nv_bfloat162 h23 = __floats2bfloat162_rn(v.z, v.w);
                __nv_bfloat162 l01 = __floats2bfloat162_rn(v.x - __low2float(h01), v.y - __high2float(h01));
                __nv_bfloat162 l23 = __floats2bfloat162_rn(v.z - __low2float(h23), v.w - __high2float(h23));
                *(uint2*)(sAh + 8 * i) = make_uint2(*(uint32_t*)&h01, *(uint32_t*)&h23);
                *(uint2*)(sAl + 8 * i) = make_uint2(*(uint32_t*)&l01, *(uint32_t*)&l23);
            }
        }
    }

    float* outb = g_LxP + (size_t)ksl * (MTOT * DIM);
    const int g = lane >> 2, t4 = lane & 3;
#pragma unroll
    for (int mf = 0; mf < 2; mf++) {
        const int row0 = m0 + wm * 32 + mf * 16 + g;
#pragma unroll
        for (int nf = 0; nf < 8; nf++) {
            const int col = wn * 64 + nf * 8 + t4 * 2;
            *(float2*)(outb + (size_t)row0 * DIM + col) =
                make_float2(acc[mf][nf][0], acc[mf][nf][1]);
            *(float2*)(outb + (size_t)(row0 + 8) * DIM + col) =
                make_float2(acc[mf][nf][2], acc[mf][nf][3]);
        }
    }
}

// ---------------- BN stats pass 1 + K-split fold ----------------------------
__global__ __launch_bounds__(256) void stats_partial(int xsel) {
    const float* __restrict__ X = xsel ? g_bufX2 : g_bufX;
    const int tid = threadIdx.x;
    const int c = tid & 127;
    const int half = tid >> 7;
    const int rpb = MTOT / STATS_BLOCKS;   // 16
    const int r0 = blockIdx.x * rpb;

    float sx = 0.f, sxx = 0.f, sl = 0.f, sll = 0.f;
#pragma unroll 4
    for (int r = r0 + half; r < r0 + rpb; r += 2) {
        float v = X[r * DIM + c];
        sx += v; sxx += v * v;
        size_t idx = (size_t)r * DIM + c;
        float w = 0.f;
#pragma unroll
        for (int q = 0; q < NKSL; q++) w += g_LxP[idx + (size_t)q * MTOT * DIM];
        g_LxP[idx] = w;
        sl += w; sll += w * w;
    }
    __shared__ float sh[256];
    const int b = blockIdx.x;
    sh[tid] = sx;  __syncthreads();
    if (tid < 128) g_partials[(0 * 128 + c) * STATS_BLOCKS + b] = sh[tid] + sh[tid + 128];
    __syncthreads();
    sh[tid] = sxx; __syncthreads();
    if (tid < 128) g_partials[(1 * 128 + c) * STATS_BLOCKS + b] = sh[tid] + sh[tid + 128];
    __syncthreads();
    sh[tid] = sl;  __syncthreads();
    if (tid < 128) g_partials[(2 * 128 + c) * STATS_BLOCKS + b] = sh[tid] + sh[tid + 128];
    __syncthreads();
    sh[tid] = sll; __syncthreads();
    if (tid < 128) g_partials[(3 * 128 + c) * STATS_BLOCKS + b] = sh[tid] + sh[tid + 128];
}

// ---------------- BN stats pass 2: float4 reads -----------------------------
__global__ __launch_bounds__(256) void stats_final(const float* __restrict__ gamma,
                                                   const float* __restrict__ beta) {
    const int warp = threadIdx.x >> 5;
    const int lane = threadIdx.x & 31;
    const int k = blockIdx.x * 8 + warp;
    const int base = (k < 128) ? 0 : 2;
    const int c = k & 127;
    const float4* ps = (const float4*)(g_partials + (size_t)(base * 128 + c) * STATS_BLOCKS);
    const float4* pq = (const float4*)(g_partials + (size_t)((base + 1) * 128 + c) * STATS_BLOCKS);
    float s = 0.f, ss = 0.f;
#pragma unroll
    for (int i = 0; i < STATS_BLOCKS / 128; i++) {   // 4
        float4 a = ps[lane + 32 * i];
        float4 b = pq[lane + 32 * i];
        s  += (a.x + a.y) + (a.z + a.w);
        ss += (b.x + b.y) + (b.z + b.w);
    }
    s = warp_sum(s);
    ss = warp_sum(ss);
    if (lane == 0) {
        float mean = s / (float)MTOT;
        float var  = ss / (float)MTOT - mean * mean;
        float sc   = rsqrtf(var + EPSV) * gamma[k];
        g_scale[k] = sc;
        g_shift[k] = beta[k] - mean * sc;
    }
}

// ---------------- fold BN into linear weights: bf16 split + beff ------------
// grid 64 x 256: 2 elems/thread (wider latency hiding); beff on blocks 0..15.
__global__ __launch_bounds__(256) void weff_kernel(const float* __restrict__ w,
                                                   const float* __restrict__ b) {
    const int e0 = (blockIdx.x * 256 + threadIdx.x) * 2;   // over [j][k] row-major
    const int j = e0 >> 8;
    const int k0 = e0 & 255;
    float2 wv = *(const float2*)(w + j * 256 + k0);
    float2 sv = *(const float2*)(g_scale + k0);
    float p0 = wv.x * sv.x, p1 = wv.y * sv.y;
    __nv_bfloat162 h01 = __floats2bfloat162_rn(p0, p1);
    __nv_bfloat162 l01 = __floats2bfloat162_rn(p0 - __low2float(h01), p1 - __high2float(h01));
    *(uint32_t*)(g_wBh + j * 256 + k0) = *(uint32_t*)&h01;
    *(uint32_t*)(g_wBl + j * 256 + k0) = *(uint32_t*)&l01;

    if (blockIdx.x < 16) {
        const int warp = threadIdx.x >> 5;
        const int lane = threadIdx.x & 31;
        const int jo = blockIdx.x * 8 + warp;
        const float4* wj = (const float4*)(w + jo * 256);
        const float4* sh4 = (const float4*)g_shift;
        float s = 0.f;
#pragma unroll
        for (int i = 0; i < 2; i++) {
            float4 a = wj[lane + 32 * i];
            float4 c4 = sh4[lane + 32 * i];
            s += a.x * c4.x + a.y * c4.y + a.z * c4.z + a.w * c4.w;
        }
        s = warp_sum(s);
        if (lane == 0) g_beff[jo] = b[jo] + s;
    }
}

// ---------------- HMMA linear: M=64 tiles, 128 CTAs -------------------------
#define L_AOP 5120
#define L_BBASE (2 * L_AOP)
#define L_STG (2 * L_AOP + 2 * OPSZ)
#define LIN_SMEM (2 * L_STG)

__global__ __launch_bounds__(256, 2) void linear_mma(int xsel,
                                                     const float* __restrict__ resid,
                                                     float* __restrict__ dst, int mode) {
    extern __shared__ char smem[];
    const int tid = threadIdx.x;
    const int lane = tid & 31;
    const int w = tid >> 5;
    const int wm = w >> 1;
    const int wn = w & 1;
    const int m0 = blockIdx.x * 64;

    const uint32_t sb = smem_u32(smem);
    const float* __restrict__ Xs = xsel ? g_bufX2 : g_bufX;

    const int a_row = wm * 16 + (lane & 7) + ((lane >> 3) & 1) * 8;
    const uint32_t aOff = (uint32_t)a_row * ROWB + ((lane >> 4) & 1) * 16;
    const int b_row = wn * 64 + (lane & 7) + ((lane >> 4) & 1) * 8;
    const uint32_t bOff = (uint32_t)b_row * ROWB + ((lane >> 3) & 1) * 16;

    const int garow = tid >> 2;
    const int gseg = tid & 3;
    const uint32_t aStOff = (uint32_t)garow * ROWB + gseg * 16;
    const int gbrow = tid >> 1;
    const int gbh = tid & 1;
    const __nv_bfloat16* Bhp = g_wBh + (size_t)gbrow * FEAT + gbh * 16;
    const __nv_bfloat16* Blp = g_wBl + (size_t)gbrow * FEAT + gbh * 16;
    const uint32_t bStOff = (uint32_t)gbrow * ROWB + gbh * 32;

    float acc[8][4];
#pragma unroll
    for (int j = 0; j < 8; j++)
#pragma unroll
        for (int q = 0; q < 4; q++) acc[j][q] = 0.f;

    float4 ar[2];

    auto aPtr = [&](int t) -> const float* {
        int kk = t * 32 + gseg * 8;
        return (kk < 128) ? (Xs + (size_t)(m0 + garow) * DIM + kk)
                          : (g_LxP + (size_t)(m0 + garow) * DIM + (kk - 128));
    };
    auto convA = [&](char* base, float4* v) {
        char* sAh = base + aStOff;
        char* sAl = base + L_AOP + aStOff;
#pragma unroll
        for (int i = 0; i < 2; i++) {
            float4 x = v[i];
            __nv_bfloat162 h01 = __floats2bfloat162_rn(x.x, x.y);
            __nv_bfloat162 h23 = __floats2bfloat162_rn(x.z, x.w);
            __nv_bfloat162 l01 = __floats2bfloat162_rn(x.x - __low2float(h01), x.y - __high2float(h01));
            __nv_bfloat162 l23 = __floats2bfloat162_rn(x.z - __low2float(h23), x.w - __high2float(h23));
            *(uint2*)(sAh + 8 * i) = make_uint2(*(uint32_t*)&h01, *(uint32_t*)&h23);
            *(uint2*)(sAl + 8 * i) = make_uint2(*(uint32_t*)&l01, *(uint32_t*)&l23);
        }
    };

    cpasync16(sb + L_BBASE + bStOff,              Bhp);
    cpasync16(sb + L_BBASE + bStOff + 16,         Bhp + 8);
    cpasync16(sb + L_BBASE + OPSZ + bStOff,       Blp);
    cpasync16(sb + L_BBASE + OPSZ + bStOff + 16,  Blp + 8);
    cp_commit();
    {
        const float* ap = aPtr(0);
        ar[0] = *(const float4*)ap;
        ar[1] = *(const float4*)(ap + 4);
        convA(smem, ar);
    }

    const int T = FEAT / 32;  // 8

    for (int t = 0; t < T; t++) {
        cp_wait0();
        __syncthreads();
        const int s = t & 1;
        const uint32_t sA = sb + s * L_STG;
        const uint32_t nsBase = sb + (s ^ 1) * L_STG;
        const bool more = (t + 1) < T;
        if (more) {
            const int off = (t + 1) * 32;
            cpasync16(nsBase + L_BBASE + bStOff,              Bhp + off);
            cpasync16(nsBase + L_BBASE + bStOff + 16,         Bhp + off + 8);
            cpasync16(nsBase + L_BBASE + OPSZ + bStOff,       Blp + off);
            cpasync16(nsBase + L_BBASE + OPSZ + bStOff + 16,  Blp + off + 8);
            cp_commit();
            const float* ap = aPtr(t + 1);
            ar[0] = *(const float4*)ap;
            ar[1] = *(const float4*)(ap + 4);
        }

#pragma unroll
        for (int ks = 0; ks < 2; ks++) {
            const uint32_t kb = ks * 32;
            uint32_t Ah[4], Al[4];
            ldmx4(Ah, sA + aOff + kb);
            ldmx4(Al, sA + L_AOP + aOff + kb);
#pragma unroll
            for (int qh = 0; qh < 2; qh++) {
                uint32_t Bh2[2][4], Bl2[2][4];
#pragma unroll
                for (int qq = 0; qq < 2; qq++) {
                    const int q = qh * 2 + qq;
                    ldmx4(Bh2[qq], sA + L_BBASE + bOff + q * (16 * ROWB) + kb);
                    ldmx4(Bl2[qq], sA + L_BBASE + OPSZ + bOff + q * (16 * ROWB) + kb);
                }
#pragma unroll
                for (int qq = 0; qq < 2; qq++)
#pragma unroll
                    for (int j = 0; j < 2; j++) {
                        const int nf = qh * 4 + qq * 2 + j;
                        const int rr = j * 2;
                        mma_bf16(acc[nf], Ah, Bh2[qq][rr], Bh2[qq][rr + 1]);
                        mma_bf16(acc[nf], Ah, Bl2[qq][rr], Bl2[qq][rr + 1]);
                        mma_bf16(acc[nf], Al, Bh2[qq][rr], Bh2[qq][rr + 1]);
                    }
            }
        }

        if (more) {
            convA(smem + (s ^ 1) * L_STG, ar);
        }
    }

    const int g = lane >> 2, t4 = lane & 3;
    const int row0 = m0 + wm * 16 + g;
#pragma unroll
    for (int nf = 0; nf < 8; nf++) {
        const int col = wn * 64 + nf * 8 + t4 * 2;
        float b0 = g_beff[col], b1 = g_beff[col + 1];
        float y0 = acc[nf][0] + b0;
        float y1 = acc[nf][1] + b1;
        float y2 = acc[nf][2] + b0;
        float y3 = acc[nf][3] + b1;
        if (mode == 0) {
            float v0 = eluf(y0), v1 = eluf(y1), v2 = eluf(y2), v3 = eluf(y3);
            *(float2*)(g_bufX2 + (size_t)row0 * DIM + col) = make_float2(v0, v1);
            *(float2*)(g_bufX2 + (size_t)(row0 + 8) * DIM + col) = make_float2(v2, v3);
            __nv_bfloat16 h, l;
            split_bf16(v0, h, l);
            g_Bh[(size_t)col * MTOT + row0] = h;       g_Bl[(size_t)col * MTOT + row0] = l;
            split_bf16(v1, h, l);
            g_Bh[(size_t)(col + 1) * MTOT + row0] = h; g_Bl[(size_t)(col + 1) * MTOT + row0] = l;
            split_bf16(v2, h, l);
            g_Bh[(size_t)col * MTOT + row0 + 8] = h;       g_Bl[(size_t)col * MTOT + row0 + 8] = l;
            split_bf16(v3, h, l);
            g_Bh[(size_t)(col + 1) * MTOT + row0 + 8] = h; g_Bl[(size_t)(col + 1) * MTOT + row0 + 8] = l;
        } else {
            float r0v = resid[(size_t)row0 * DIM + col];
            float r1v = resid[(size_t)row0 * DIM + col + 1];
            float r2v = resid[(size_t)(row0 + 8) * DIM + col];
            float r3v = resid[(size_t)(row0 + 8) * DIM + col + 1];
            *(float2*)(dst + (size_t)row0 * DIM + col) = make_float2(y0 + r0v, y1 + r1v);
            *(float2*)(dst + (size_t)(row0 + 8) * DIM + col) = make_float2(y2 + r2v, y3 + r3v);
        }
    }
}

// ---------------- launch ----------------------------------------------------
extern "C" void kernel_launch(void* const* d_in, const int* in_sizes, int n_in,
                              void* d_out, int out_size) {
    const float* L      = (const float*)d_in[0];
    const float* inputs = (const float*)d_in[2];
    const float* bn0_g  = (const float*)d_in[3];
    const float* bn0_b  = (const float*)d_in[4];
    const float* fc0_w  = (const float*)d_in[5];
    const float* fc0_b  = (const float*)d_in[6];
    const float* bn1_g  = (const float*)d_in[7];
    const float* bn1_b  = (const float*)d_in[8];
    const float* fc1_w  = (const float*)d_in[9];
    const float* fc1_b  = (const float*)d_in[10];
    float* out = (float*)d_out;

    cudaFuncSetAttribute(sgemm_mma, cudaFuncAttributeMaxDynamicSharedMemorySize, SGEMM_SMEM);
    cudaFuncSetAttribute(linear_mma, cudaFuncAttributeMaxDynamicSharedMemorySize, LIN_SMEM);

    // ---- block 0 ----
    pack_kernel<<<128, 256>>>(inputs);
    sgemm_mma<<<512, 256, SGEMM_SMEM>>>(L);
    stats_partial<<<STATS_BLOCKS, 256>>>(0);
    stats_final<<<32, 256>>>(bn0_g, bn0_b);
    weff_kernel<<<64, 256>>>(fc0_w, fc0_b);
    linear_mma<<<128, 256, LIN_SMEM>>>(0, nullptr, nullptr, 0);  // packs B for block 1

    // ---- block 1 ----
    sgemm_mma<<<512, 256, SGEMM_SMEM>>>(L);
    stats_partial<<<STATS_BLOCKS, 256>>>(1);
    stats_final<<<32, 256>>>(bn1_g, bn1_b);
    weff_kernel<<<64, 256>>>(fc1_w, fc1_b);
    linear_mma<<<128, 256, LIN_SMEM>>>(1, inputs, out, 1);
}

// round 14
// speedup vs baseline: 1.2089x; 1.0206x over previous
#include <cuda_runtime.h>
#include <cuda_bf16.h>
#include <math.h>
#include <stdint.h>

#define MTOT 8192
#define KDIM 8192
#define DIM 128
#define FEAT 256
#define EPSV 1e-5f
#define STATS_BLOCKS 512
#define NKSL 8

// ---------------- scratch (device globals; no allocs allowed) ----------------
__device__ float g_bufX [MTOT * DIM];
__device__ float g_bufX2[MTOT * DIM];
__device__ float g_LxP [NKSL * MTOT * DIM];  // K-slice partials (slice 0 -> folded sum)
__device__ __nv_bfloat16 g_Bh[DIM * MTOT];   // B^T bf16 hi [feat][node]
__device__ __nv_bfloat16 g_Bl[DIM * MTOT];
__device__ float g_partials[4 * DIM * STATS_BLOCKS];  // [quad][feat][block]
__device__ float g_scale[FEAT];
__device__ float g_shift[FEAT];
__device__ __nv_bfloat16 g_wBh[DIM * FEAT];  // folded weights bf16 [j][k]
__device__ __nv_bfloat16 g_wBl[DIM * FEAT];
__device__ float g_beff[DIM];

// ---------------- helpers ----------------
__device__ __forceinline__ void pdl_wait() {
    asm volatile("griddepcontrol.wait;" ::: "memory");
}
__device__ __forceinline__ uint32_t smem_u32(const void* p) {
    uint32_t a;
    asm("{ .reg .u64 t; cvta.to.shared.u64 t, %1; cvt.u32.u64 %0, t; }" : "=r"(a) : "l"(p));
    return a;
}
__device__ __forceinline__ void ldmx4(uint32_t* r, uint32_t addr) {
    asm volatile("ldmatrix.sync.aligned.m8n8.x4.shared.b16 {%0,%1,%2,%3}, [%4];"
                 : "=r"(r[0]), "=r"(r[1]), "=r"(r[2]), "=r"(r[3]) : "r"(addr));
}
__device__ __forceinline__ void mma_bf16(float* d, const uint32_t* a, uint32_t b0, uint32_t b1) {
    asm volatile(
        "mma.sync.aligned.m16n8k16.row.col.f32.bf16.bf16.f32 "
        "{%0,%1,%2,%3}, {%4,%5,%6,%7}, {%8,%9}, {%0,%1,%2,%3};"
        : "+f"(d[0]), "+f"(d[1]), "+f"(d[2]), "+f"(d[3])
        : "r"(a[0]), "r"(a[1]), "r"(a[2]), "r"(a[3]), "r"(b0), "r"(b1));
}
__device__ __forceinline__ void cpasync16(uint32_t dst, const void* src) {
    asm volatile("cp.async.cg.shared.global [%0], [%1], 16;" :: "r"(dst), "l"(src));
}
__device__ __forceinline__ void cp_commit() { asm volatile("cp.async.commit_group;"); }
__device__ __forceinline__ void cp_wait0()  { asm volatile("cp.async.wait_group 0;" ::: "memory"); }

__device__ __forceinline__ float eluf(float v) { return v > 0.f ? v : expm1f(v); }

__device__ __forceinline__ float warp_sum(float v) {
#pragma unroll
    for (int o = 16; o > 0; o >>= 1) v += __shfl_xor_sync(0xFFFFFFFFu, v, o);
    return v;
}
__device__ __forceinline__ void split_bf16(float v, __nv_bfloat16& h, __nv_bfloat16& l) {
    h = __float2bfloat16(v);
    l = __float2bfloat16(v - __bfloat162float(h));
}

// ---------------- pack: inputs -> ELU -> g_bufX + B^T bf16 hi/lo ------------
__global__ __launch_bounds__(256) void pack_kernel(const float* __restrict__ src) {
    pdl_wait();
    __shared__ float tile[128][65];
    const int tid = threadIdx.x;
    const int node0 = blockIdx.x * 64;

    const float4* sv = (const float4*)src + (size_t)node0 * 32;
    float4* xv = (float4*)g_bufX + (size_t)node0 * 32;
#pragma unroll
    for (int i = 0; i < 8; i++) {
        int idx = tid + 256 * i;
        int node = idx >> 5;
        int fq = idx & 31;
        float4 v = sv[idx];
        v.x = eluf(v.x); v.y = eluf(v.y); v.z = eluf(v.z); v.w = eluf(v.w);
        xv[idx] = v;
        tile[fq * 4 + 0][node] = v.x;
        tile[fq * 4 + 1][node] = v.y;
        tile[fq * 4 + 2][node] = v.z;
        tile[fq * 4 + 3][node] = v.w;
    }
    __syncthreads();

    const int feat = tid >> 1;
    const int h = tid & 1;
    const float* r = &tile[feat][h * 32];
    uint32_t hi[16], lo[16];
#pragma unroll
    for (int j = 0; j < 16; j++) {
        float a = r[2 * j], b = r[2 * j + 1];
        __nv_bfloat162 hb = __floats2bfloat162_rn(a, b);
        float ha = __low2float(hb), hbv = __high2float(hb);
        __nv_bfloat162 lb = __floats2bfloat162_rn(a - ha, b - hbv);
        hi[j] = *(uint32_t*)&hb;
        lo[j] = *(uint32_t*)&lb;
    }
    uint4* oh = (uint4*)(g_Bh + (size_t)feat * MTOT + node0 + h * 32);
    uint4* ol = (uint4*)(g_Bl + (size_t)feat * MTOT + node0 + h * 32);
#pragma unroll
    for (int blk = 0; blk < 4; blk++) {
        oh[blk] = make_uint4(hi[4 * blk], hi[4 * blk + 1], hi[4 * blk + 2], hi[4 * blk + 3]);
        ol[blk] = make_uint4(lo[4 * blk], lo[4 * blk + 1], lo[4 * blk + 2], lo[4 * blk + 3]);
    }
}

// ---------------- split-bf16 HMMA GEMM (validated core) ---------------------
#define ROWB 80
#define OPSZ 10240
#define STGSZ 40960
#define SGEMM_SMEM (2 * STGSZ)

__global__ __launch_bounds__(256, 2) void sgemm_mma(const float* __restrict__ L) {
    pdl_wait();
    extern __shared__ char smem[];
    const int tid = threadIdx.x;
    const int lane = tid & 31;
    const int w = tid >> 5;
    const int wm = w >> 1;
    const int wn = w & 1;
    const int mtile = blockIdx.x >> 3;
    const int ksl = blockIdx.x & 7;
    const int m0 = mtile * 128;
    const int kc0 = ksl * 1024;

    const uint32_t sb = smem_u32(smem);

    const int a_row = wm * 32 + (lane & 7) + ((lane >> 3) & 1) * 8;
    const uint32_t aOff = (uint32_t)a_row * ROWB + ((lane >> 4) & 1) * 16;
    const int b_row = wn * 64 + (lane & 7) + ((lane >> 4) & 1) * 8;
    const uint32_t bOff = (uint32_t)b_row * ROWB + ((lane >> 3) & 1) * 16;

    const int grow = tid >> 1;
    const int gh = tid & 1;
    const float* Ap = L + (size_t)(m0 + grow) * KDIM + kc0 + gh * 16;
    const __nv_bfloat16* Bhp = g_Bh + (size_t)grow * MTOT + kc0 + gh * 16;
    const __nv_bfloat16* Blp = g_Bl + (size_t)grow * MTOT + kc0 + gh * 16;
    const uint32_t aStOff = (uint32_t)grow * ROWB + gh * 32;

    float acc[2][8][4];
#pragma unroll
    for (int i = 0; i < 2; i++)
#pragma unroll
        for (int j = 0; j < 8; j++)
#pragma unroll
            for (int q = 0; q < 4; q++) acc[i][j][q] = 0.f;

    float4 ar[4];

    cpasync16(sb + 2 * OPSZ + aStOff,      Bhp);
    cpasync16(sb + 2 * OPSZ + aStOff + 16, Bhp + 8);
    cpasync16(sb + 3 * OPSZ + aStOff,      Blp);
    cpasync16(sb + 3 * OPSZ + aStOff + 16, Blp + 8);
    cp_commit();
#pragma unroll
    for (int i = 0; i < 4; i++) ar[i] = *(const float4*)(Ap + 4 * i);
    {
        char* sAh = smem + aStOff;
        char* sAl = smem + OPSZ + aStOff;
#pragma unroll
        for (int i = 0; i < 4; i++) {
            float4 v = ar[i];
            __nv_bfloat162 h01 = __floats2bfloat162_rn(v.x, v.y);
            __nv_bfloat162 h23 = __floats2bfloat162_rn(v.z, v.w);
            __nv_bfloat162 l01 = __floats2bfloat162_rn(v.x - __low2float(h01), v.y - __high2float(h01));
            __nv_bfloat162 l23 = __floats2bfloat162_rn(v.z - __low2float(h23), v.w - __high2float(h23));
            *(uint2*)(sAh + 8 * i) = make_uint2(*(uint32_t*)&h01, *(uint32_t*)&h23);
            *(uint2*)(sAl + 8 * i) = make_uint2(*(uint32_t*)&l01, *(uint32_t*)&l23);
        }
    }

    const int T = 1024 / 32;  // 32

    for (int t = 0; t < T; t++) {
        cp_wait0();
        __syncthreads();
        const int s = t & 1;
        const uint32_t sA = sb + s * STGSZ;
        const uint32_t nsBase = sb + (s ^ 1) * STGSZ;
        const bool more = (t + 1) < T;
        if (more) {
            const int off = (t + 1) * 32;
            cpasync16(nsBase + 2 * OPSZ + aStOff,      Bhp + off);
            cpasync16(nsBase + 2 * OPSZ + aStOff + 16, Bhp + off + 8);
            cpasync16(nsBase + 3 * OPSZ + aStOff,      Blp + off);
            cpasync16(nsBase + 3 * OPSZ + aStOff + 16, Blp + off + 8);
            cp_commit();
#pragma unroll
            for (int i = 0; i < 4; i++) ar[i] = *(const float4*)(Ap + off + 4 * i);
        }

#pragma unroll
        for (int ks = 0; ks < 2; ks++) {
            const uint32_t kb = ks * 32;
            uint32_t Ah[2][4], Al[2][4];
#pragma unroll
            for (int mf = 0; mf < 2; mf++) {
                ldmx4(Ah[mf], sA + aOff + mf * (16 * ROWB) + kb);
                ldmx4(Al[mf], sA + OPSZ + aOff + mf * (16 * ROWB) + kb);
            }
#pragma unroll
            for (int qh = 0; qh < 2; qh++) {
                uint32_t Bh2[2][4], Bl2[2][4];
#pragma unroll
                for (int qq = 0; qq < 2; qq++) {
                    const int q = qh * 2 + qq;
                    ldmx4(Bh2[qq], sA + 2 * OPSZ + bOff + q * (16 * ROWB) + kb);
                    ldmx4(Bl2[qq], sA + 3 * OPSZ + bOff + q * (16 * ROWB) + kb);
                }
#pragma unroll
                for (int mf = 0; mf < 2; mf++)
#pragma unroll
                    for (int qq = 0; qq < 2; qq++)
#pragma unroll
                        for (int j = 0; j < 2; j++) {
                            const int nf = qh * 4 + qq * 2 + j;
                            const int rr = j * 2;
                            mma_bf16(acc[mf][nf], Ah[mf], Bh2[qq][rr], Bh2[qq][rr + 1]);
                            mma_bf16(acc[mf][nf], Ah[mf], Bl2[qq][rr], Bl2[qq][rr + 1]);
                            mma_bf16(acc[mf][nf], Al[mf], Bh2[qq][rr], Bh2[qq][rr + 1]);
                        }
            }
        }

        if (more) {
            char* other = smem + (s ^ 1) * STGSZ;
            char* sAh = other + aStOff;
            char* sAl = other + OPSZ + aStOff;
#pragma unroll
            for (int i = 0; i < 4; i++) {
                float4 v = ar[i];
                __nv_bfloat162 h01 = __floats2bfloat162_rn(v.x, v.y);
                __nv_bfloat162 h23 = __floats2bfloat162_rn(v.z, v.w);
                __nv_bfloat162 l01 = __floats2bfloat162_rn(v.x - __low2float(h01), v.y - __high2float(h01));
                __nv_bfloat162 l23 = __floats2bfloat162_rn(v.z - __low2float(h23), v.w - __high2float(h23));
                *(uint2*)(sAh + 8 * i) = make_uint2(*(uint32_t*)&h01, *(uint32_t*)&h23);
                *(uint2*)(sAl + 8 * i) = make_uint2(*(uint32_t*)&l01, *(uint32_t*)&l23);
            }
        }
    }

    float* outb = g_LxP + (size_t)ksl * (MTOT * DIM);
    const int g = lane >> 2, t4 = lane & 3;
#pragma unroll
    for (int mf = 0; mf < 2; mf++) {
        const int row0 = m0 + wm * 32 + mf * 16 + g;
#pragma unroll
        for (int nf = 0; nf < 8; nf++) {
            const int col = wn * 64 + nf * 8 + t4 * 2;
            *(float2*)(outb + (size_t)row0 * DIM + col) =
                make_float2(acc[mf][nf][0], acc[mf][nf][1]);
            *(float2*)(outb + (size_t)(row0 + 8) * DIM + col) =
                make_float2(acc[mf][nf][2], acc[mf][nf][3]);
        }
    }
}

// ---------------- BN stats pass 1 + K-split fold ----------------------------
__global__ __launch_bounds__(256) void stats_partial(int xsel) {
    pdl_wait();
    const float* __restrict__ X = xsel ? g_bufX2 : g_bufX;
    const int tid = threadIdx.x;
    const int c = tid & 127;
    const int half = tid >> 7;
    const int rpb = MTOT / STATS_BLOCKS;   // 16
    const int r0 = blockIdx.x * rpb;

    float sx = 0.f, sxx = 0.f, sl = 0.f, sll = 0.f;
#pragma unroll 4
    for (int r = r0 + half; r < r0 + rpb; r += 2) {
        float v = X[r * DIM + c];
        sx += v; sxx += v * v;
        size_t idx = (size_t)r * DIM + c;
        float w = 0.f;
#pragma unroll
        for (int q = 0; q < NKSL; q++) w += g_LxP[idx + (size_t)q * MTOT * DIM];
        g_LxP[idx] = w;
        sl += w; sll += w * w;
    }
    __shared__ float sh[256];
    const int b = blockIdx.x;
    sh[tid] = sx;  __syncthreads();
    if (tid < 128) g_partials[(0 * 128 + c) * STATS_BLOCKS + b] = sh[tid] + sh[tid + 128];
    __syncthreads();
    sh[tid] = sxx; __syncthreads();
    if (tid < 128) g_partials[(1 * 128 + c) * STATS_BLOCKS + b] = sh[tid] + sh[tid + 128];
    __syncthreads();
    sh[tid] = sl;  __syncthreads();
    if (tid < 128) g_partials[(2 * 128 + c) * STATS_BLOCKS + b] = sh[tid] + sh[tid + 128];
    __syncthreads();
    sh[tid] = sll; __syncthreads();
    if (tid < 128) g_partials[(3 * 128 + c) * STATS_BLOCKS + b] = sh[tid] + sh[tid + 128];
}

// ---------------- BN stats pass 2: float4 reads -----------------------------
__global__ __launch_bounds__(256) void stats_final(const float* __restrict__ gamma,
                                                   const float* __restrict__ beta) {
    pdl_wait();
    const int warp = threadIdx.x >> 5;
    const int lane = threadIdx.x & 31;
    const int k = blockIdx.x * 8 + warp;
    const int base = (k < 128) ? 0 : 2;
    const int c = k & 127;
    const float4* ps = (const float4*)(g_partials + (size_t)(base * 128 + c) * STATS_BLOCKS);
    const float4* pq = (const float4*)(g_partials + (size_t)((base + 1) * 128 + c) * STATS_BLOCKS);
    float s = 0.f, ss = 0.f;
#pragma unroll
    for (int i = 0; i < STATS_BLOCKS / 128; i++) {   // 4
        float4 a = ps[lane + 32 * i];
        float4 b = pq[lane + 32 * i];
        s  += (a.x + a.y) + (a.z + a.w);
        ss += (b.x + b.y) + (b.z + b.w);
    }
    s = warp_sum(s);
    ss = warp_sum(ss);
    if (lane == 0) {
        float mean = s / (float)MTOT;
        float var  = ss / (float)MTOT - mean * mean;
        float sc   = rsqrtf(var + EPSV) * gamma[k];
        g_scale[k] = sc;
        g_shift[k] = beta[k] - mean * sc;
    }
}

// ---------------- fold BN into linear weights: bf16 split + beff ------------
__global__ __launch_bounds__(256) void weff_kernel(const float* __restrict__ w,
                                                   const float* __restrict__ b) {
    pdl_wait();
    const int e0 = (blockIdx.x * 256 + threadIdx.x) * 2;   // over [j][k] row-major
    const int j = e0 >> 8;
    const int k0 = e0 & 255;
    float2 wv = *(const float2*)(w + j * 256 + k0);
    float2 sv = *(const float2*)(g_scale + k0);
    float p0 = wv.x * sv.x, p1 = wv.y * sv.y;
    __nv_bfloat162 h01 = __floats2bfloat162_rn(p0, p1);
    __nv_bfloat162 l01 = __floats2bfloat162_rn(p0 - __low2float(h01), p1 - __high2float(h01));
    *(uint32_t*)(g_wBh + j * 256 + k0) = *(uint32_t*)&h01;
    *(uint32_t*)(g_wBl + j * 256 + k0) = *(uint32_t*)&l01;

    if (blockIdx.x < 16) {
        const int warp = threadIdx.x >> 5;
        const int lane = threadIdx.x & 31;
        const int jo = blockIdx.x * 8 + warp;
        const float4* wj = (const float4*)(w + jo * 256);
        const float4* sh4 = (const float4*)g_shift;
        float s = 0.f;
#pragma unroll
        for (int i = 0; i < 2; i++) {
            float4 a = wj[lane + 32 * i];
            float4 c4 = sh4[lane + 32 * i];
            s += a.x * c4.x + a.y * c4.y + a.z * c4.z + a.w * c4.w;
        }
        s = warp_sum(s);
        if (lane == 0) g_beff[jo] = b[jo] + s;
    }
}

// ---------------- HMMA linear: M=64 tiles, 128 CTAs -------------------------
#define L_AOP 5120
#define L_BBASE (2 * L_AOP)
#define L_STG (2 * L_AOP + 2 * OPSZ)
#define LIN_SMEM (2 * L_STG)

__global__ __launch_bounds__(256, 2) void linear_mma(int xsel,
                                                     const float* __restrict__ resid,
                                                     float* __restrict__ dst, int mode) {
    pdl_wait();
    extern __shared__ char smem[];
    const int tid = threadIdx.x;
    const int lane = tid & 31;
    const int w = tid >> 5;
    const int wm = w >> 1;
    const int wn = w & 1;
    const int m0 = blockIdx.x * 64;

    const uint32_t sb = smem_u32(smem);
    const float* __restrict__ Xs = xsel ? g_bufX2 : g_bufX;

    const int a_row = wm * 16 + (lane & 7) + ((lane >> 3) & 1) * 8;
    const uint32_t aOff = (uint32_t)a_row * ROWB + ((lane >> 4) & 1) * 16;
    const int b_row = wn * 64 + (lane & 7) + ((lane >> 4) & 1) * 8;
    const uint32_t bOff = (uint32_t)b_row * ROWB + ((lane >> 3) & 1) * 16;

    const int garow = tid >> 2;
    const int gseg = tid & 3;
    const uint32_t aStOff = (uint32_t)garow * ROWB + gseg * 16;
    const int gbrow = tid >> 1;
    const int gbh = tid & 1;
    const __nv_bfloat16* Bhp = g_wBh + (size_t)gbrow * FEAT + gbh * 16;
    const __nv_bfloat16* Blp = g_wBl + (size_t)gbrow * FEAT + gbh * 16;
    const uint32_t bStOff = (uint32_t)gbrow * ROWB + gbh * 32;

    float acc[8][4];
#pragma unroll
    for (int j = 0; j < 8; j++)
#pragma unroll
        for (int q = 0; q < 4; q++) acc[j][q] = 0.f;

    float4 ar[2];

    auto aPtr = [&](int t) -> const float* {
        int kk = t * 32 + gseg * 8;
        return (kk < 128) ? (Xs + (size_t)(m0 + garow) * DIM + kk)
                          : (g_LxP + (size_t)(m0 + garow) * DIM + (kk - 128));
    };
    auto convA = [&](char* base, float4* v) {
        char* sAh = base + aStOff;
        char* sAl = base + L_AOP + aStOff;
#pragma unroll
        for (int i = 0; i < 2; i++) {
            float4 x = v[i];
            __nv_bfloat162 h01 = __floats2bfloat162_rn(x.x, x.y);
            __nv_bfloat162 h23 = __floats2bfloat162_rn(x.z, x.w);
            __nv_bfloat162 l01 = __floats2bfloat162_rn(x.x - __low2float(h01), x.y - __high2float(h01));
            __nv_bfloat162 l23 = __floats2bfloat162_rn(x.z - __low2float(h23), x.w - __high2float(h23));
            *(uint2*)(sAh + 8 * i) = make_uint2(*(uint32_t*)&h01, *(uint32_t*)&h23);
            *(uint2*)(sAl + 8 * i) = make_uint2(*(uint32_t*)&l01, *(uint32_t*)&l23);
        }
    };

    cpasync16(sb + L_BBASE + bStOff,              Bhp);
    cpasync16(sb + L_BBASE + bStOff + 16,         Bhp + 8);
    cpasync16(sb + L_BBASE + OPSZ + bStOff,       Blp);
    cpasync16(sb + L_BBASE + OPSZ + bStOff + 16,  Blp + 8);
    cp_commit();
    {
        const float* ap = aPtr(0);
        ar[0] = *(const float4*)ap;
        ar[1] = *(const float4*)(ap + 4);
        convA(smem, ar);
    }

    const int T = FEAT / 32;  // 8

    for (int t = 0; t < T; t++) {
        cp_wait0();
        __syncthreads();
        const int s = t & 1;
        const uint32_t sA = sb + s * L_STG;
        const uint32_t nsBase = sb + (s ^ 1) * L_STG;
        const bool more = (t + 1) < T;
        if (more) {
            const int off = (t + 1) * 32;
            cpasync16(nsBase + L_BBASE + bStOff,              Bhp + off);
            cpasync16(nsBase + L_BBASE + bStOff + 16,         Bhp + off + 8);
            cpasync16(nsBase + L_BBASE + OPSZ + bStOff,       Blp + off);
            cpasync16(nsBase + L_BBASE + OPSZ + bStOff + 16,  Blp + off + 8);
            cp_commit();
            const float* ap = aPtr(t + 1);
            ar[0] = *(const float4*)ap;
            ar[1] = *(const float4*)(ap + 4);
        }

#pragma unroll
        for (int ks = 0; ks < 2; ks++) {
            const uint32_t kb = ks * 32;
            uint32_t Ah[4], Al[4];
            ldmx4(Ah, sA + aOff + kb);
            ldmx4(Al, sA + L_AOP + aOff + kb);
#pragma unroll
            for (int qh = 0; qh < 2; qh++) {
                uint32_t Bh2[2][4], Bl2[2][4];
#pragma unroll
                for (int qq = 0; qq < 2; qq++) {
                    const int q = qh * 2 + qq;
                    ldmx4(Bh2[qq], sA + L_BBASE + bOff + q * (16 * ROWB) + kb);
                    ldmx4(Bl2[qq], sA + L_BBASE + OPSZ + bOff + q * (16 * ROWB) + kb);
                }
#pragma unroll
                for (int qq = 0; qq < 2; qq++)
#pragma unroll
                    for (int j = 0; j < 2; j++) {
                        const int nf = qh * 4 + qq * 2 + j;
                        const int rr = j * 2;
                        mma_bf16(acc[nf], Ah, Bh2[qq][rr], Bh2[qq][rr + 1]);
                        mma_bf16(acc[nf], Ah, Bl2[qq][rr], Bl2[qq][rr + 1]);
                        mma_bf16(acc[nf], Al, Bh2[qq][rr], Bh2[qq][rr + 1]);
                    }
            }
        }

        if (more) {
            convA(smem + (s ^ 1) * L_STG, ar);
        }
    }

    const int g = lane >> 2, t4 = lane & 3;
    const int row0 = m0 + wm * 16 + g;
#pragma unroll
    for (int nf = 0; nf < 8; nf++) {
        const int col = wn * 64 + nf * 8 + t4 * 2;
        float b0 = g_beff[col], b1 = g_beff[col + 1];
        float y0 = acc[nf][0] + b0;
        float y1 = acc[nf][1] + b1;
        float y2 = acc[nf][2] + b0;
        float y3 = acc[nf][3] + b1;
        if (mode == 0) {
            float v0 = eluf(y0), v1 = eluf(y1), v2 = eluf(y2), v3 = eluf(y3);
            *(float2*)(g_bufX2 + (size_t)row0 * DIM + col) = make_float2(v0, v1);
            *(float2*)(g_bufX2 + (size_t)(row0 + 8) * DIM + col) = make_float2(v2, v3);
            __nv_bfloat16 h, l;
            split_bf16(v0, h, l);
            g_Bh[(size_t)col * MTOT + row0] = h;       g_Bl[(size_t)col * MTOT + row0] = l;
            split_bf16(v1, h, l);
            g_Bh[(size_t)(col + 1) * MTOT + row0] = h; g_Bl[(size_t)(col + 1) * MTOT + row0] = l;
            split_bf16(v2, h, l);
            g_Bh[(size_t)col * MTOT + row0 + 8] = h;       g_Bl[(size_t)col * MTOT + row0 + 8] = l;
            split_bf16(v3, h, l);
            g_Bh[(size_t)(col + 1) * MTOT + row0 + 8] = h; g_Bl[(size_t)(col + 1) * MTOT + row0 + 8] = l;
        } else {
            float r0v = resid[(size_t)row0 * DIM + col];
            float r1v = resid[(size_t)row0 * DIM + col + 1];
            float r2v = resid[(size_t)(row0 + 8) * DIM + col];
            float r3v = resid[(size_t)(row0 + 8) * DIM + col + 1];
            *(float2*)(dst + (size_t)row0 * DIM + col) = make_float2(y0 + r0v, y1 + r1v);
            *(float2*)(dst + (size_t)(row0 + 8) * DIM + col) = make_float2(y2 + r2v, y3 + r3v);
        }
    }
}

// ---------------- launch (all kernels with PDL attribute) --------------------
extern "C" void kernel_launch(void* const* d_in, const int* in_sizes, int n_in,
                              void* d_out, int out_size) {
    const float* L      = (const float*)d_in[0];
    const float* inputs = (const float*)d_in[2];
    const float* bn0_g  = (const float*)d_in[3];
    const float* bn0_b  = (const float*)d_in[4];
    const float* fc0_w  = (const float*)d_in[5];
    const float* fc0_b  = (const float*)d_in[6];
    const float* bn1_g  = (const float*)d_in[7];
    const float* bn1_b  = (const float*)d_in[8];
    const float* fc1_w  = (const float*)d_in[9];
    const float* fc1_b  = (const float*)d_in[10];
    float* out = (float*)d_out;

    cudaFuncSetAttribute(sgemm_mma, cudaFuncAttributeMaxDynamicSharedMemorySize, SGEMM_SMEM);
    cudaFuncSetAttribute(linear_mma, cudaFuncAttributeMaxDynamicSharedMemorySize, LIN_SMEM);

    cudaLaunchAttribute attr;
    attr.id = cudaLaunchAttributeProgrammaticStreamSerialization;
    attr.val.programmaticStreamSerializationAllowed = 1;

    cudaLaunchConfig_t cfg = {};
    cfg.blockDim = dim3(256, 1, 1);
    cfg.stream = 0;
    cfg.attrs = &attr;
    cfg.numAttrs = 1;

    auto go = [&](const void* fn, int grid, size_t smem, void** args) {
        cfg.gridDim = dim3(grid, 1, 1);
        cfg.dynamicSmemBytes = smem;
        cudaLaunchKernelExC(&cfg, fn, args);
    };

    int i0 = 0, i1 = 1;
    const float* nullres = nullptr;
    float* nulldst = nullptr;

    // ---- block 0 ----
    { void* a[] = {(void*)&inputs};
      go((const void*)pack_kernel, 128, 0, a); }
    { void* a[] = {(void*)&L};
      go((const void*)sgemm_mma, 512, SGEMM_SMEM, a); }
    { void* a[] = {&i0};
      go((const void*)stats_partial, STATS_BLOCKS, 0, a); }
    { void* a[] = {(void*)&bn0_g, (void*)&bn0_b};
      go((const void*)stats_final, 32, 0, a); }
    { void* a[] = {(void*)&fc0_w, (void*)&fc0_b};
      go((const void*)weff_kernel, 64, 0, a); }
    { void* a[] = {&i0, (void*)&nullres, (void*)&nulldst, &i0};
      go((const void*)linear_mma, 128, LIN_SMEM, a); }

    // ---- block 1 ----
    { void* a[] = {(void*)&L};
      go((const void*)sgemm_mma, 512, SGEMM_SMEM, a); }
    { void* a[] = {&i1};
      go((const void*)stats_partial, STATS_BLOCKS, 0, a); }
    { void* a[] = {(void*)&bn1_g, (void*)&bn1_b};
      go((const void*)stats_final, 32, 0, a); }
    { void* a[] = {(void*)&fc1_w, (void*)&fc1_b};
      go((const void*)weff_kernel, 64, 0, a); }
    { void* a[] = {&i1, (void*)&inputs, (void*)&out, &i1};
      go((const void*)linear_mma, 128, LIN_SMEM, a); }
}

// round 15
// speedup vs baseline: 1.2172x; 1.0069x over previous
#include <cuda_runtime.h>
#include <cuda_bf16.h>
#include <math.h>
#include <stdint.h>

#define MTOT 8192
#define KDIM 8192
#define DIM 128
#define FEAT 256
#define EPSV 1e-5f
#define STATS_BLOCKS 512
#define NKSL 8

// ---------------- scratch (device globals; no allocs allowed) ----------------
__device__ float g_bufX [MTOT * DIM];
__device__ float g_bufX2[MTOT * DIM];
__device__ float g_LxP [NKSL * MTOT * DIM];  // K-slice partials (slice 0 -> folded sum)
__device__ __nv_bfloat16 g_Bh[DIM * MTOT];   // B^T bf16 hi [feat][node]
__device__ __nv_bfloat16 g_Bl[DIM * MTOT];
__device__ float g_partials[4 * DIM * STATS_BLOCKS];  // [quad][feat][block]
__device__ float g_scale[FEAT];
__device__ float g_shift[FEAT];
__device__ __nv_bfloat16 g_wBh[DIM * FEAT];  // folded weights bf16 [j][k]
__device__ __nv_bfloat16 g_wBl[DIM * FEAT];
__device__ float g_beff[DIM];

// ---------------- helpers ----------------
__device__ __forceinline__ void pdl_wait() {
    asm volatile("griddepcontrol.wait;" ::: "memory");
}
__device__ __forceinline__ uint32_t smem_u32(const void* p) {
    uint32_t a;
    asm("{ .reg .u64 t; cvta.to.shared.u64 t, %1; cvt.u32.u64 %0, t; }" : "=r"(a) : "l"(p));
    return a;
}
__device__ __forceinline__ void ldmx4(uint32_t* r, uint32_t addr) {
    asm volatile("ldmatrix.sync.aligned.m8n8.x4.shared.b16 {%0,%1,%2,%3}, [%4];"
                 : "=r"(r[0]), "=r"(r[1]), "=r"(r[2]), "=r"(r[3]) : "r"(addr));
}
__device__ __forceinline__ void mma_bf16(float* d, const uint32_t* a, uint32_t b0, uint32_t b1) {
    asm volatile(
        "mma.sync.aligned.m16n8k16.row.col.f32.bf16.bf16.f32 "
        "{%0,%1,%2,%3}, {%4,%5,%6,%7}, {%8,%9}, {%0,%1,%2,%3};"
        : "+f"(d[0]), "+f"(d[1]), "+f"(d[2]), "+f"(d[3])
        : "r"(a[0]), "r"(a[1]), "r"(a[2]), "r"(a[3]), "r"(b0), "r"(b1));
}
__device__ __forceinline__ void cpasync16(uint32_t dst, const void* src) {
    asm volatile("cp.async.cg.shared.global [%0], [%1], 16;" :: "r"(dst), "l"(src));
}
__device__ __forceinline__ void cp_commit() { asm volatile("cp.async.commit_group;"); }
__device__ __forceinline__ void cp_wait0()  { asm volatile("cp.async.wait_group 0;" ::: "memory"); }

__device__ __forceinline__ float eluf(float v) { return v > 0.f ? v : expm1f(v); }

__device__ __forceinline__ float warp_sum(float v) {
#pragma unroll
    for (int o = 16; o > 0; o >>= 1) v += __shfl_xor_sync(0xFFFFFFFFu, v, o);
    return v;
}
__device__ __forceinline__ void split_bf16(float v, __nv_bfloat16& h, __nv_bfloat16& l) {
    h = __float2bfloat16(v);
    l = __float2bfloat16(v - __bfloat162float(h));
}
__device__ __forceinline__ float4 f4add(float4 a, float4 b) {
    return make_float4(a.x + b.x, a.y + b.y, a.z + b.z, a.w + b.w);
}
__device__ __forceinline__ float4 f4fma(float4 a, float4 b, float4 c) {
    return make_float4(fmaf(a.x, b.x, c.x), fmaf(a.y, b.y, c.y),
                       fmaf(a.z, b.z, c.z), fmaf(a.w, b.w, c.w));
}

// ---------------- pack: inputs -> ELU -> g_bufX + B^T bf16 hi/lo ------------
__global__ __launch_bounds__(256) void pack_kernel(const float* __restrict__ src) {
    pdl_wait();
    __shared__ float tile[128][65];
    const int tid = threadIdx.x;
    const int node0 = blockIdx.x * 64;

    const float4* sv = (const float4*)src + (size_t)node0 * 32;
    float4* xv = (float4*)g_bufX + (size_t)node0 * 32;
#pragma unroll
    for (int i = 0; i < 8; i++) {
        int idx = tid + 256 * i;
        int node = idx >> 5;
        int fq = idx & 31;
        float4 v = sv[idx];
        v.x = eluf(v.x); v.y = eluf(v.y); v.z = eluf(v.z); v.w = eluf(v.w);
        xv[idx] = v;
        tile[fq * 4 + 0][node] = v.x;
        tile[fq * 4 + 1][node] = v.y;
        tile[fq * 4 + 2][node] = v.z;
        tile[fq * 4 + 3][node] = v.w;
    }
    __syncthreads();

    const int feat = tid >> 1;
    const int h = tid & 1;
    const float* r = &tile[feat][h * 32];
    uint32_t hi[16], lo[16];
#pragma unroll
    for (int j = 0; j < 16; j++) {
        float a = r[2 * j], b = r[2 * j + 1];
        __nv_bfloat162 hb = __floats2bfloat162_rn(a, b);
        float ha = __low2float(hb), hbv = __high2float(hb);
        __nv_bfloat162 lb = __floats2bfloat162_rn(a - ha, b - hbv);
        hi[j] = *(uint32_t*)&hb;
        lo[j] = *(uint32_t*)&lb;
    }
    uint4* oh = (uint4*)(g_Bh + (size_t)feat * MTOT + node0 + h * 32);
    uint4* ol = (uint4*)(g_Bl + (size_t)feat * MTOT + node0 + h * 32);
#pragma unroll
    for (int blk = 0; blk < 4; blk++) {
        oh[blk] = make_uint4(hi[4 * blk], hi[4 * blk + 1], hi[4 * blk + 2], hi[4 * blk + 3]);
        ol[blk] = make_uint4(lo[4 * blk], lo[4 * blk + 1], lo[4 * blk + 2], lo[4 * blk + 3]);
    }
}

// ---------------- split-bf16 HMMA GEMM (validated core) ---------------------
#define ROWB 80
#define OPSZ 10240
#define STGSZ 40960
#define SGEMM_SMEM (2 * STGSZ)

__global__ __launch_bounds__(256, 2) void sgemm_mma(const float* __restrict__ L) {
    pdl_wait();
    extern __shared__ char smem[];
    const int tid = threadIdx.x;
    const int lane = tid & 31;
    const int w = tid >> 5;
    const int wm = w >> 1;
    const int wn = w & 1;
    const int mtile = blockIdx.x >> 3;
    const int ksl = blockIdx.x & 7;
    const int m0 = mtile * 128;
    const int kc0 = ksl * 1024;

    const uint32_t sb = smem_u32(smem);

    const int a_row = wm * 32 + (lane & 7) + ((lane >> 3) & 1) * 8;
    const uint32_t aOff = (uint32_t)a_row * ROWB + ((lane >> 4) & 1) * 16;
    const int b_row = wn * 64 + (lane & 7) + ((lane >> 4) & 1) * 8;
    const uint32_t bOff = (uint32_t)b_row * ROWB + ((lane >> 3) & 1) * 16;

    const int grow = tid >> 1;
    const int gh = tid & 1;
    const float* Ap = L + (size_t)(m0 + grow) * KDIM + kc0 + gh * 16;
    const __nv_bfloat16* Bhp = g_Bh + (size_t)grow * MTOT + kc0 + gh * 16;
    const __nv_bfloat16* Blp = g_Bl + (size_t)grow * MTOT + kc0 + gh * 16;
    const uint32_t aStOff = (uint32_t)grow * ROWB + gh * 32;

    float acc[2][8][4];
#pragma unroll
    for (int i = 0; i < 2; i++)
#pragma unroll
        for (int j = 0; j < 8; j++)
#pragma unroll
            for (int q = 0; q < 4; q++) acc[i][j][q] = 0.f;

    float4 ar[4];

    cpasync16(sb + 2 * OPSZ + aStOff,      Bhp);
    cpasync16(sb + 2 * OPSZ + aStOff + 16, Bhp + 8);
    cpasync16(sb + 3 * OPSZ + aStOff,      Blp);
    cpasync16(sb + 3 * OPSZ + aStOff + 16, Blp + 8);
    cp_commit();
#pragma unroll
    for (int i = 0; i < 4; i++) ar[i] = *(const float4*)(Ap + 4 * i);
    {
        char* sAh = smem + aStOff;
        char* sAl = smem + OPSZ + aStOff;
#pragma unroll
        for (int i = 0; i < 4; i++) {
            float4 v = ar[i];
            __nv_bfloat162 h01 = __floats2bfloat162_rn(v.x, v.y);
            __nv_bfloat162 h23 = __floats2bfloat162_rn(v.z, v.w);
            __nv_bfloat162 l01 = __floats2bfloat162_rn(v.x - __low2float(h01), v.y - __high2float(h01));
            __nv_bfloat162 l23 = __floats2bfloat162_rn(v.z - __low2float(h23), v.w - __high2float(h23));
            *(uint2*)(sAh + 8 * i) = make_uint2(*(uint32_t*)&h01, *(uint32_t*)&h23);
            *(uint2*)(sAl + 8 * i) = make_uint2(*(uint32_t*)&l01, *(uint32_t*)&l23);
        }
    }

    const int T = 1024 / 32;  // 32

    for (int t = 0; t < T; t++) {
        cp_wait0();
        __syncthreads();
        const int s = t & 1;
        const uint32_t sA = sb + s * STGSZ;
        const uint32_t nsBase = sb + (s ^ 1) * STGSZ;
        const bool more = (t + 1) < T;
        if (more) {
            const int off = (t + 1) * 32;
            cpasync16(nsBase + 2 * OPSZ + aStOff,      Bhp + off);
            cpasync16(nsBase + 2 * OPSZ + aStOff + 16, Bhp + off + 8);
            cpasync16(nsBase + 3 * OPSZ + aStOff,      Blp + off);
            cpasync16(nsBase + 3 * OPSZ + aStOff + 16, Blp + off + 8);
            cp_commit();
#pragma unroll
            for (int i = 0; i < 4; i++) ar[i] = *(const float4*)(Ap + off + 4 * i);
        }

#pragma unroll
        for (int ks = 0; ks < 2; ks++) {
            const uint32_t kb = ks * 32;
            uint32_t Ah[2][4], Al[2][4];
#pragma unroll
            for (int mf = 0; mf < 2; mf++) {
                ldmx4(Ah[mf], sA + aOff + mf * (16 * ROWB) + kb);
                ldmx4(Al[mf], sA + OPSZ + aOff + mf * (16 * ROWB) + kb);
            }
#pragma unroll
            for (int qh = 0; qh < 2; qh++) {
                uint32_t Bh2[2][4], Bl2[2][4];
#pragma unroll
                for (int qq = 0; qq < 2; qq++) {
                    const int q = qh * 2 + qq;
                    ldmx4(Bh2[qq], sA + 2 * OPSZ + bOff + q * (16 * ROWB) + kb);
                    ldmx4(Bl2[qq], sA + 3 * OPSZ + bOff + q * (16 * ROWB) + kb);
                }
#pragma unroll
                for (int mf = 0; mf < 2; mf++)
#pragma unroll
                    for (int qq = 0; qq < 2; qq++)
#pragma unroll
                        for (int j = 0; j < 2; j++) {
                            const int nf = qh * 4 + qq * 2 + j;
                            const int rr = j * 2;
                            mma_bf16(acc[mf][nf], Ah[mf], Bh2[qq][rr], Bh2[qq][rr + 1]);
                            mma_bf16(acc[mf][nf], Ah[mf], Bl2[qq][rr], Bl2[qq][rr + 1]);
                            mma_bf16(acc[mf][nf], Al[mf], Bh2[qq][rr], Bh2[qq][rr + 1]);
                        }
            }
        }

        if (more) {
            char* other = smem + (s ^ 1) * STGSZ;
            char* sAh = other + aStOff;
            char* sAl = other + OPSZ + aStOff;
#pragma unroll
            for (int i = 0; i < 4; i++) {
                float4 v = ar[i];
                __nv_bfloat162 h01 = __floats2bfloat162_rn(v.x, v.y);
                __nv_bfloat162 h23 = __floats2bfloat162_rn(v.z, v.w);
                __nv_bfloat162 l01 = __floats2bfloat162_rn(v.x - __low2float(h01), v.y - __high2float(h01));
                __nv_bfloat162 l23 = __floats2bfloat162_rn(v.z - __low2float(h23), v.w - __high2float(h23));
                *(uint2*)(sAh + 8 * i) = make_uint2(*(uint32_t*)&h01, *(uint32_t*)&h23);
                *(uint2*)(sAl + 8 * i) = make_uint2(*(uint32_t*)&l01, *(uint32_t*)&l23);
            }
        }
    }

    float* outb = g_LxP + (size_t)ksl * (MTOT * DIM);
    const int g = lane >> 2, t4 = lane & 3;
#pragma unroll
    for (int mf = 0; mf < 2; mf++) {
        const int row0 = m0 + wm * 32 + mf * 16 + g;
#pragma unroll
        for (int nf = 0; nf < 8; nf++) {
            const int col = wn * 64 + nf * 8 + t4 * 2;
            *(float2*)(outb + (size_t)row0 * DIM + col) =
                make_float2(acc[mf][nf][0], acc[mf][nf][1]);
            *(float2*)(outb + (size_t)(row0 + 8) * DIM + col) =
                make_float2(acc[mf][nf][2], acc[mf][nf][3]);
        }
    }
}

// ---------------- BN stats pass 1 + K-split fold (float4, wide MLP) ---------
// thread = 4 columns x 1/8 of the block's rows; 18 float4 LDGs per thread.
__global__ __launch_bounds__(256) void stats_partial(int xsel) {
    pdl_wait();
    const float* __restrict__ X = xsel ? g_bufX2 : g_bufX;
    const int tid = threadIdx.x;
    const int cg = (tid & 31) * 4;         // column base 0..124
    const int rq = tid >> 5;               // 0..7 row quad
    const int rpb = MTOT / STATS_BLOCKS;   // 16
    const int r0 = blockIdx.x * rpb;

    float4 sx  = make_float4(0.f, 0.f, 0.f, 0.f);
    float4 sxx = make_float4(0.f, 0.f, 0.f, 0.f);
    float4 sl  = make_float4(0.f, 0.f, 0.f, 0.f);
    float4 sll = make_float4(0.f, 0.f, 0.f, 0.f);

#pragma unroll
    for (int it = 0; it < 2; it++) {       // rows r0+rq, r0+rq+8
        const int r = r0 + rq + it * 8;
        const size_t idx = (size_t)r * DIM + cg;
        float4 v = *(const float4*)(X + idx);
        sx = f4add(sx, v);
        sxx = f4fma(v, v, sxx);
        float4 wv = *(const float4*)(g_LxP + idx);
#pragma unroll
        for (int q = 1; q < NKSL; q++)
            wv = f4add(wv, *(const float4*)(g_LxP + idx + (size_t)q * MTOT * DIM));
        *(float4*)(g_LxP + idx) = wv;      // fold into slice 0
        sl = f4add(sl, wv);
        sll = f4fma(wv, wv, sll);
    }

    __shared__ float4 shv[256];
    const int b = blockIdx.x;
    float4 acc4;
#define STATS_REDUCE(VAL, QUAD)                                               \
    shv[tid] = VAL; __syncthreads();                                          \
    if (tid < 32) {                                                           \
        acc4 = shv[tid];                                                      \
        _Pragma("unroll")                                                     \
        for (int rr = 1; rr < 8; rr++) acc4 = f4add(acc4, shv[tid + 32 * rr]); \
        const int c0 = tid * 4;                                               \
        g_partials[((QUAD) * 128 + c0 + 0) * STATS_BLOCKS + b] = acc4.x;      \
        g_partials[((QUAD) * 128 + c0 + 1) * STATS_BLOCKS + b] = acc4.y;      \
        g_partials[((QUAD) * 128 + c0 + 2) * STATS_BLOCKS + b] = acc4.z;      \
        g_partials[((QUAD) * 128 + c0 + 3) * STATS_BLOCKS + b] = acc4.w;      \
    }                                                                         \
    __syncthreads();

    STATS_REDUCE(sx, 0)
    STATS_REDUCE(sxx, 1)
    STATS_REDUCE(sl, 2)
    STATS_REDUCE(sll, 3)
#undef STATS_REDUCE
}

// ---------------- BN stats pass 2: float4 reads -----------------------------
__global__ __launch_bounds__(256) void stats_final(const float* __restrict__ gamma,
                                                   const float* __restrict__ beta) {
    pdl_wait();
    const int warp = threadIdx.x >> 5;
    const int lane = threadIdx.x & 31;
    const int k = blockIdx.x * 8 + warp;
    const int base = (k < 128) ? 0 : 2;
    const int c = k & 127;
    const float4* ps = (const float4*)(g_partials + (size_t)(base * 128 + c) * STATS_BLOCKS);
    const float4* pq = (const float4*)(g_partials + (size_t)((base + 1) * 128 + c) * STATS_BLOCKS);
    float s = 0.f, ss = 0.f;
#pragma unroll
    for (int i = 0; i < STATS_BLOCKS / 128; i++) {   // 4
        float4 a = ps[lane + 32 * i];
        float4 b = pq[lane + 32 * i];
        s  += (a.x + a.y) + (a.z + a.w);
        ss += (b.x + b.y) + (b.z + b.w);
    }
    s = warp_sum(s);
    ss = warp_sum(ss);
    if (lane == 0) {
        float mean = s / (float)MTOT;
        float var  = ss / (float)MTOT - mean * mean;
        float sc   = rsqrtf(var + EPSV) * gamma[k];
        g_scale[k] = sc;
        g_shift[k] = beta[k] - mean * sc;
    }
}

// ---------------- fold BN into linear weights: bf16 split + beff ------------
__global__ __launch_bounds__(256) void weff_kernel(const float* __restrict__ w,
                                                   const float* __restrict__ b) {
    pdl_wait();
    const int e0 = (blockIdx.x * 256 + threadIdx.x) * 2;   // over [j][k] row-major
    const int j = e0 >> 8;
    const int k0 = e0 & 255;
    float2 wv = *(const float2*)(w + j * 256 + k0);
    float2 sv = *(const float2*)(g_scale + k0);
    float p0 = wv.x * sv.x, p1 = wv.y * sv.y;
    __nv_bfloat162 h01 = __floats2bfloat162_rn(p0, p1);
    __nv_bfloat162 l01 = __floats2bfloat162_rn(p0 - __low2float(h01), p1 - __high2float(h01));
    *(uint32_t*)(g_wBh + j * 256 + k0) = *(uint32_t*)&h01;
    *(uint32_t*)(g_wBl + j * 256 + k0) = *(uint32_t*)&l01;

    if (blockIdx.x < 16) {
        const int warp = threadIdx.x >> 5;
        const int lane = threadIdx.x & 31;
        const int jo = blockIdx.x * 8 + warp;
        const float4* wj = (const float4*)(w + jo * 256);
        const float4* sh4 = (const float4*)g_shift;
        float s = 0.f;
#pragma unroll
        for (int i = 0; i < 2; i++) {
            float4 a = wj[lane + 32 * i];
            float4 c4 = sh4[lane + 32 * i];
            s += a.x * c4.x + a.y * c4.y + a.z * c4.z + a.w * c4.w;
        }
        s = warp_sum(s);
        if (lane == 0) g_beff[jo] = b[jo] + s;
    }
}

// ---------------- HMMA linear: M=64 tiles, 128 CTAs -------------------------
#define L_AOP 5120
#define L_BBASE (2 * L_AOP)
#define L_STG (2 * L_AOP + 2 * OPSZ)
#define LIN_SMEM (2 * L_STG)

__global__ __launch_bounds__(256, 2) void linear_mma(int xsel,
                                                     const float* __restrict__ resid,
                                                     float* __restrict__ dst, int mode) {
    pdl_wait();
    extern __shared__ char smem[];
    const int tid = threadIdx.x;
    const int lane = tid & 31;
    const int w = tid >> 5;
    const int wm = w >> 1;
    const int wn = w & 1;
    const int m0 = blockIdx.x * 64;

    const uint32_t sb = smem_u32(smem);
    const float* __restrict__ Xs = xsel ? g_bufX2 : g_bufX;

    const int a_row = wm * 16 + (lane & 7) + ((lane >> 3) & 1) * 8;
    const uint32_t aOff = (uint32_t)a_row * ROWB + ((lane >> 4) & 1) * 16;
    const int b_row = wn * 64 + (lane & 7) + ((lane >> 4) & 1) * 8;
    const uint32_t bOff = (uint32_t)b_row * ROWB + ((lane >> 3) & 1) * 16;

    const int garow = tid >> 2;
    const int gseg = tid & 3;
    const uint32_t aStOff = (uint32_t)garow * ROWB + gseg * 16;
    const int gbrow = tid >> 1;
    const int gbh = tid & 1;
    const __nv_bfloat16* Bhp = g_wBh + (size_t)gbrow * FEAT + gbh * 16;
    const __nv_bfloat16* Blp = g_wBl + (size_t)gbrow * FEAT + gbh * 16;
    const uint32_t bStOff = (uint32_t)gbrow * ROWB + gbh * 32;

    float acc[8][4];
#pragma unroll
    for (int j = 0; j < 8; j++)
#pragma unroll
        for (int q = 0; q < 4; q++) acc[j][q] = 0.f;

    float4 ar[2];

    auto aPtr = [&](int t) -> const float* {
        int kk = t * 32 + gseg * 8;
        return (kk < 128) ? (Xs + (size_t)(m0 + garow) * DIM + kk)
                          : (g_LxP + (size_t)(m0 + garow) * DIM + (kk - 128));
    };
    auto convA = [&](char* base, float4* v) {
        char* sAh = base + aStOff;
        char* sAl = base + L_AOP + aStOff;
#pragma unroll
        for (int i = 0; i < 2; i++) {
            float4 x = v[i];
            __nv_bfloat162 h01 = __floats2bfloat162_rn(x.x, x.y);
            __nv_bfloat162 h23 = __floats2bfloat162_rn(x.z, x.w);
            __nv_bfloat162 l01 = __floats2bfloat162_rn(x.x - __low2float(h01), x.y - __high2float(h01));
            __nv_bfloat162 l23 = __floats2bfloat162_rn(x.z - __low2float(h23), x.w - __high2float(h23));
            *(uint2*)(sAh + 8 * i) = make_uint2(*(uint32_t*)&h01, *(uint32_t*)&h23);
            *(uint2*)(sAl + 8 * i) = make_uint2(*(uint32_t*)&l01, *(uint32_t*)&l23);
        }
    };

    cpasync16(sb + L_BBASE + bStOff,              Bhp);
    cpasync16(sb + L_BBASE + bStOff + 16,         Bhp + 8);
    cpasync16(sb + L_BBASE + OPSZ + bStOff,       Blp);
    cpasync16(sb + L_BBASE + OPSZ + bStOff + 16,  Blp + 8);
    cp_commit();
    {
        const float* ap = aPtr(0);
        ar[0] = *(const float4*)ap;
        ar[1] = *(const float4*)(ap + 4);
        convA(smem, ar);
    }

    const int T = FEAT / 32;  // 8

    for (int t = 0; t < T; t++) {
        cp_wait0();
        __syncthreads();
        const int s = t & 1;
        const uint32_t sA = sb + s * L_STG;
        const uint32_t nsBase = sb + (s ^ 1) * L_STG;
        const bool more = (t + 1) < T;
        if (more) {
            const int off = (t + 1) * 32;
            cpasync16(nsBase + L_BBASE + bStOff,              Bhp + off);
            cpasync16(nsBase + L_BBASE + bStOff + 16,         Bhp + off + 8);
            cpasync16(nsBase + L_BBASE + OPSZ + bStOff,       Blp + off);
            cpasync16(nsBase + L_BBASE + OPSZ + bStOff + 16,  Blp + off + 8);
            cp_commit();
            const float* ap = aPtr(t + 1);
            ar[0] = *(const float4*)ap;
            ar[1] = *(const float4*)(ap + 4);
        }

#pragma unroll
        for (int ks = 0; ks < 2; ks++) {
            const uint32_t kb = ks * 32;
            uint32_t Ah[4], Al[4];
            ldmx4(Ah, sA + aOff + kb);
            ldmx4(Al, sA + L_AOP + aOff + kb);
#pragma unroll
            for (int qh = 0; qh < 2; qh++) {
                uint32_t Bh2[2][4], Bl2[2][4];
#pragma unroll
                for (int qq = 0; qq < 2; qq++) {
                    const int q = qh * 2 + qq;
                    ldmx4(Bh2[qq], sA + L_BBASE + bOff + q * (16 * ROWB) + kb);
                    ldmx4(Bl2[qq], sA + L_BBASE + OPSZ + bOff + q * (16 * ROWB) + kb);
                }
#pragma unroll
                for (int qq = 0; qq < 2; qq++)
#pragma unroll
                    for (int j = 0; j < 2; j++) {
                        const int nf = qh * 4 + qq * 2 + j;
                        const int rr = j * 2;
                        mma_bf16(acc[nf], Ah, Bh2[qq][rr], Bh2[qq][rr + 1]);
                        mma_bf16(acc[nf], Ah, Bl2[qq][rr], Bl2[qq][rr + 1]);
                        mma_bf16(acc[nf], Al, Bh2[qq][rr], Bh2[qq][rr + 1]);
                    }
            }
        }

        if (more) {
            convA(smem + (s ^ 1) * L_STG, ar);
        }
    }

    const int g = lane >> 2, t4 = lane & 3;
    const int row0 = m0 + wm * 16 + g;
#pragma unroll
    for (int nf = 0; nf < 8; nf++) {
        const int col = wn * 64 + nf * 8 + t4 * 2;
        float b0 = g_beff[col], b1 = g_beff[col + 1];
        float y0 = acc[nf][0] + b0;
        float y1 = acc[nf][1] + b1;
        float y2 = acc[nf][2] + b0;
        float y3 = acc[nf][3] + b1;
        if (mode == 0) {
            float v0 = eluf(y0), v1 = eluf(y1), v2 = eluf(y2), v3 = eluf(y3);
            *(float2*)(g_bufX2 + (size_t)row0 * DIM + col) = make_float2(v0, v1);
            *(float2*)(g_bufX2 + (size_t)(row0 + 8) * DIM + col) = make_float2(v2, v3);
            __nv_bfloat16 h, l;
            split_bf16(v0, h, l);
            g_Bh[(size_t)col * MTOT + row0] = h;       g_Bl[(size_t)col * MTOT + row0] = l;
            split_bf16(v1, h, l);
            g_Bh[(size_t)(col + 1) * MTOT + row0] = h; g_Bl[(size_t)(col + 1) * MTOT + row0] = l;
            split_bf16(v2, h, l);
            g_Bh[(size_t)col * MTOT + row0 + 8] = h;       g_Bl[(size_t)col * MTOT + row0 + 8] = l;
            split_bf16(v3, h, l);
            g_Bh[(size_t)(col + 1) * MTOT + row0 + 8] = h; g_Bl[(size_t)(col + 1) * MTOT + row0 + 8] = l;
        } else {
            float r0v = resid[(size_t)row0 * DIM + col];
            float r1v = resid[(size_t)row0 * DIM + col + 1];
            float r2v = resid[(size_t)(row0 + 8) * DIM + col];
            float r3v = resid[(size_t)(row0 + 8) * DIM + col + 1];
            *(float2*)(dst + (size_t)row0 * DIM + col) = make_float2(y0 + r0v, y1 + r1v);
            *(float2*)(dst + (size_t)(row0 + 8) * DIM + col) = make_float2(y2 + r2v, y3 + r3v);
        }
    }
}

// ---------------- launch (all kernels with PDL attribute) --------------------
extern "C" void kernel_launch(void* const* d_in, const int* in_sizes, int n_in,
                              void* d_out, int out_size) {
    const float* L      = (const float*)d_in[0];
    const float* inputs = (const float*)d_in[2];
    const float* bn0_g  = (const float*)d_in[3];
    const float* bn0_b  = (const float*)d_in[4];
    const float* fc0_w  = (const float*)d_in[5];
    const float* fc0_b  = (const float*)d_in[6];
    const float* bn1_g  = (const float*)d_in[7];
    const float* bn1_b  = (const float*)d_in[8];
    const float* fc1_w  = (const float*)d_in[9];
    const float* fc1_b  = (const float*)d_in[10];
    float* out = (float*)d_out;

    cudaFuncSetAttribute(sgemm_mma, cudaFuncAttributeMaxDynamicSharedMemorySize, SGEMM_SMEM);
    cudaFuncSetAttribute(linear_mma, cudaFuncAttributeMaxDynamicSharedMemorySize, LIN_SMEM);

    cudaLaunchAttribute attr;
    attr.id = cudaLaunchAttributeProgrammaticStreamSerialization;
    attr.val.programmaticStreamSerializationAllowed = 1;

    cudaLaunchConfig_t cfg = {};
    cfg.blockDim = dim3(256, 1, 1);
    cfg.stream = 0;
    cfg.attrs = &attr;
    cfg.numAttrs = 1;

    auto go = [&](const void* fn, int grid, size_t smem, void** args) {
        cfg.gridDim = dim3(grid, 1, 1);
        cfg.dynamicSmemBytes = smem;
        cudaLaunchKernelExC(&cfg, fn, args);
    };

    int i0 = 0, i1 = 1;
    const float* nullres = nullptr;
    float* nulldst = nullptr;

    // ---- block 0 ----
    { void* a[] = {(void*)&inputs};
      go((const void*)pack_kernel, 128, 0, a); }
    { void* a[] = {(void*)&L};
      go((const void*)sgemm_mma, 512, SGEMM_SMEM, a); }
    { void* a[] = {&i0};
      go((const void*)stats_partial, STATS_BLOCKS, 0, a); }
    { void* a[] = {(void*)&bn0_g, (void*)&bn0_b};
      go((const void*)stats_final, 32, 0, a); }
    { void* a[] = {(void*)&fc0_w, (void*)&fc0_b};
      go((const void*)weff_kernel, 64, 0, a); }
    { void* a[] = {&i0, (void*)&nullres, (void*)&nulldst, &i0};
      go((const void*)linear_mma, 128, LIN_SMEM, a); }

    // ---- block 1 ----
    { void* a[] = {(void*)&L};
      go((const void*)sgemm_mma, 512, SGEMM_SMEM, a); }
    { void* a[] = {&i1};
      go((const void*)stats_partial, STATS_BLOCKS, 0, a); }
    { void* a[] = {(void*)&bn1_g, (void*)&bn1_b};
      go((const void*)stats_final, 32, 0, a); }
    { void* a[] = {(void*)&fc1_w, (void*)&fc1_b};
      go((const void*)weff_kernel, 64, 0, a); }
    { void* a[] = {&i1, (void*)&inputs, (void*)&out, &i1};
      go((const void*)linear_mma, 128, LIN_SMEM, a); }
}

// round 16
// speedup vs baseline: 1.3368x; 1.0982x over previous
#include <cuda_runtime.h>
#include <cuda_bf16.h>
#include <math.h>
#include <stdint.h>

#define MTOT 8192
#define KDIM 8192
#define DIM 128
#define FEAT 256
#define EPSV 1e-5f
#define STATS_BLOCKS 512
#define NSLOT 6
#define NCTA 296          // 148 SMs x occupancy 2: one exact wave
#define NCHUNK 16384      // 64 mtiles x 256 BK-chunks

// ---------------- scratch (device globals; no allocs allowed) ----------------
__device__ float g_bufX [MTOT * DIM];
__device__ float g_bufX2[MTOT * DIM];
__device__ float g_LxP [NSLOT * MTOT * DIM]; // per-(mtile,slot) partials; slot0 -> folded sum
__device__ __nv_bfloat16 g_Bh[DIM * MTOT];   // B^T bf16 hi [feat][node]
__device__ __nv_bfloat16 g_Bl[DIM * MTOT];
__device__ float g_partials[4 * DIM * STATS_BLOCKS];  // [quad][feat][block]
__device__ float g_scale[FEAT];
__device__ float g_shift[FEAT];
__device__ __nv_bfloat16 g_wBh[DIM * FEAT];  // folded weights bf16 [j][k]
__device__ __nv_bfloat16 g_wBl[DIM * FEAT];
__device__ float g_beff[DIM];

// ---------------- helpers ----------------
__device__ __forceinline__ void pdl_wait() {
    asm volatile("griddepcontrol.wait;" ::: "memory");
}
__device__ __forceinline__ uint32_t smem_u32(const void* p) {
    uint32_t a;
    asm("{ .reg .u64 t; cvta.to.shared.u64 t, %1; cvt.u32.u64 %0, t; }" : "=r"(a) : "l"(p));
    return a;
}
__device__ __forceinline__ void ldmx4(uint32_t* r, uint32_t addr) {
    asm volatile("ldmatrix.sync.aligned.m8n8.x4.shared.b16 {%0,%1,%2,%3}, [%4];"
                 : "=r"(r[0]), "=r"(r[1]), "=r"(r[2]), "=r"(r[3]) : "r"(addr));
}
__device__ __forceinline__ void mma_bf16(float* d, const uint32_t* a, uint32_t b0, uint32_t b1) {
    asm volatile(
        "mma.sync.aligned.m16n8k16.row.col.f32.bf16.bf16.f32 "
        "{%0,%1,%2,%3}, {%4,%5,%6,%7}, {%8,%9}, {%0,%1,%2,%3};"
        : "+f"(d[0]), "+f"(d[1]), "+f"(d[2]), "+f"(d[3])
        : "r"(a[0]), "r"(a[1]), "r"(a[2]), "r"(a[3]), "r"(b0), "r"(b1));
}
__device__ __forceinline__ void cpasync16(uint32_t dst, const void* src) {
    asm volatile("cp.async.cg.shared.global [%0], [%1], 16;" :: "r"(dst), "l"(src));
}
__device__ __forceinline__ void cp_commit() { asm volatile("cp.async.commit_group;"); }
__device__ __forceinline__ void cp_wait0()  { asm volatile("cp.async.wait_group 0;" ::: "memory"); }

__device__ __forceinline__ float eluf(float v) { return v > 0.f ? v : expm1f(v); }

__device__ __forceinline__ float warp_sum(float v) {
#pragma unroll
    for (int o = 16; o > 0; o >>= 1) v += __shfl_xor_sync(0xFFFFFFFFu, v, o);
    return v;
}
__device__ __forceinline__ void split_bf16(float v, __nv_bfloat16& h, __nv_bfloat16& l) {
    h = __float2bfloat16(v);
    l = __float2bfloat16(v - __bfloat162float(h));
}
__device__ __forceinline__ float4 f4add(float4 a, float4 b) {
    return make_float4(a.x + b.x, a.y + b.y, a.z + b.z, a.w + b.w);
}
__device__ __forceinline__ float4 f4fma(float4 a, float4 b, float4 c) {
    return make_float4(fmaf(a.x, b.x, c.x), fmaf(a.y, b.y, c.y),
                       fmaf(a.z, b.z, c.z), fmaf(a.w, b.w, c.w));
}

// chunk-schedule arithmetic: CTA c covers chunks [start(c), start(c)+cnt(c))
// start(c) = 55c + min(c,104); cnt(c) = 55 + (c<104). 104*56 = 5824.
__device__ __forceinline__ int cta_of_chunk(int g) {
    return (g < 5824) ? (g / 56) : (104 + (g - 5824) / 55);
}

// ---------------- pack: inputs -> ELU -> g_bufX + B^T bf16 hi/lo ------------
__global__ __launch_bounds__(256) void pack_kernel(const float* __restrict__ src) {
    pdl_wait();
    __shared__ float tile[128][65];
    const int tid = threadIdx.x;
    const int node0 = blockIdx.x * 64;

    const float4* sv = (const float4*)src + (size_t)node0 * 32;
    float4* xv = (float4*)g_bufX + (size_t)node0 * 32;
#pragma unroll
    for (int i = 0; i < 8; i++) {
        int idx = tid + 256 * i;
        int node = idx >> 5;
        int fq = idx & 31;
        float4 v = sv[idx];
        v.x = eluf(v.x); v.y = eluf(v.y); v.z = eluf(v.z); v.w = eluf(v.w);
        xv[idx] = v;
        tile[fq * 4 + 0][node] = v.x;
        tile[fq * 4 + 1][node] = v.y;
        tile[fq * 4 + 2][node] = v.z;
        tile[fq * 4 + 3][node] = v.w;
    }
    __syncthreads();

    const int feat = tid >> 1;
    const int h = tid & 1;
    const float* r = &tile[feat][h * 32];
    uint32_t hi[16], lo[16];
#pragma unroll
    for (int j = 0; j < 16; j++) {
        float a = r[2 * j], b = r[2 * j + 1];
        __nv_bfloat162 hb = __floats2bfloat162_rn(a, b);
        float ha = __low2float(hb), hbv = __high2float(hb);
        __nv_bfloat162 lb = __floats2bfloat162_rn(a - ha, b - hbv);
        hi[j] = *(uint32_t*)&hb;
        lo[j] = *(uint32_t*)&lb;
    }
    uint4* oh = (uint4*)(g_Bh + (size_t)feat * MTOT + node0 + h * 32);
    uint4* ol = (uint4*)(g_Bl + (size_t)feat * MTOT + node0 + h * 32);
#pragma unroll
    for (int blk = 0; blk < 4; blk++) {
        oh[blk] = make_uint4(hi[4 * blk], hi[4 * blk + 1], hi[4 * blk + 2], hi[4 * blk + 3]);
        ol[blk] = make_uint4(lo[4 * blk], lo[4 * blk + 1], lo[4 * blk + 2], lo[4 * blk + 3]);
    }
}

// ---------------- split-bf16 HMMA GEMM, balanced 296-CTA chunk schedule -----
#define ROWB 80
#define OPSZ 10240
#define STGSZ 40960
#define SGEMM_SMEM (2 * STGSZ)

__global__ __launch_bounds__(256, 2) void sgemm_mma(const float* __restrict__ L) {
    pdl_wait();
    extern __shared__ char smem[];
    const int tid = threadIdx.x;
    const int lane = tid & 31;
    const int w = tid >> 5;
    const int wm = w >> 1;
    const int wn = w & 1;
    const int c = blockIdx.x;                       // 0..295

    const int gs = 55 * c + (c < 104 ? c : 104);
    const int ge = gs + 55 + (c < 104 ? 1 : 0);

    const uint32_t sb = smem_u32(smem);

    const int a_row = wm * 32 + (lane & 7) + ((lane >> 3) & 1) * 8;
    const uint32_t aOff = (uint32_t)a_row * ROWB + ((lane >> 4) & 1) * 16;
    const int b_row = wn * 64 + (lane & 7) + ((lane >> 4) & 1) * 8;
    const uint32_t bOff = (uint32_t)b_row * ROWB + ((lane >> 3) & 1) * 16;

    const int grow = tid >> 1;
    const int gh = tid & 1;
    const uint32_t aStOff = (uint32_t)grow * ROWB + gh * 32;
    const int g4 = lane >> 2, t4 = lane & 3;

    int g = gs;
    while (g < ge) {
        const int m = g >> 8;                       // mtile
        const int gend = (ge < ((m + 1) << 8)) ? ge : ((m + 1) << 8);
        const int T = gend - g;                     // 1..56 BK-chunks this run
        const int m0 = m * 128;
        const int kc0 = (g & 255) * 32;
        const int slot = c - cta_of_chunk(m << 8);  // 0..5

        const float* Ap = L + (size_t)(m0 + grow) * KDIM + kc0 + gh * 16;
        const __nv_bfloat16* Bhp = g_Bh + (size_t)grow * MTOT + kc0 + gh * 16;
        const __nv_bfloat16* Blp = g_Bl + (size_t)grow * MTOT + kc0 + gh * 16;

        float acc[2][8][4];
#pragma unroll
        for (int i = 0; i < 2; i++)
#pragma unroll
            for (int j = 0; j < 8; j++)
#pragma unroll
                for (int q = 0; q < 4; q++) acc[i][j][q] = 0.f;

        float4 ar[4];

        // prologue: tile 0 of this run into stage 0
        __syncthreads();   // protect stage reuse across runs
        cpasync16(sb + 2 * OPSZ + aStOff,      Bhp);
        cpasync16(sb + 2 * OPSZ + aStOff + 16, Bhp + 8);
        cpasync16(sb + 3 * OPSZ + aStOff,      Blp);
        cpasync16(sb + 3 * OPSZ + aStOff + 16, Blp + 8);
        cp_commit();
#pragma unroll
        for (int i = 0; i < 4; i++) ar[i] = *(const float4*)(Ap + 4 * i);
        {
            char* sAh = smem + aStOff;
            char* sAl = smem + OPSZ + aStOff;
#pragma unroll
            for (int i = 0; i < 4; i++) {
                float4 v = ar[i];
                __nv_bfloat162 h01 = __floats2bfloat162_rn(v.x, v.y);
                __nv_bfloat162 h23 = __floats2bfloat162_rn(v.z, v.w);
                __nv_bfloat162 l01 = __floats2bfloat162_rn(v.x - __low2float(h01), v.y - __high2float(h01));
                __nv_bfloat162 l23 = __floats2bfloat162_rn(v.z - __low2float(h23), v.w - __high2float(h23));
                *(uint2*)(sAh + 8 * i) = make_uint2(*(uint32_t*)&h01, *(uint32_t*)&h23);
                *(uint2*)(sAl + 8 * i) = make_uint2(*(uint32_t*)&l01, *(uint32_t*)&l23);
            }
        }

        for (int t = 0; t < T; t++) {
            cp_wait0();
            __syncthreads();
            const int s = t & 1;
            const uint32_t sA = sb + s * STGSZ;
            const uint32_t nsBase = sb + (s ^ 1) * STGSZ;
            const bool more = (t + 1) < T;
            if (more) {
                const int off = (t + 1) * 32;
                cpasync16(nsBase + 2 * OPSZ + aStOff,      Bhp + off);
                cpasync16(nsBase + 2 * OPSZ + aStOff + 16, Bhp + off + 8);
                cpasync16(nsBase + 3 * OPSZ + aStOff,      Blp + off);
                cpasync16(nsBase + 3 * OPSZ + aStOff + 16, Blp + off + 8);
                cp_commit();
#pragma unroll
                for (int i = 0; i < 4; i++) ar[i] = *(const float4*)(Ap + off + 4 * i);
            }

#pragma unroll
            for (int ks = 0; ks < 2; ks++) {
                const uint32_t kb = ks * 32;
                uint32_t Ah[2][4], Al[2][4];
#pragma unroll
                for (int mf = 0; mf < 2; mf++) {
                    ldmx4(Ah[mf], sA + aOff + mf * (16 * ROWB) + kb);
                    ldmx4(Al[mf], sA + OPSZ + aOff + mf * (16 * ROWB) + kb);
                }
#pragma unroll
                for (int qh = 0; qh < 2; qh++) {
                    uint32_t Bh2[2][4], Bl2[2][4];
#pragma unroll
                    for (int qq = 0; qq < 2; qq++) {
                        const int q = qh * 2 + qq;
                        ldmx4(Bh2[qq], sA + 2 * OPSZ + bOff + q * (16 * ROWB) + kb);
                        ldmx4(Bl2[qq], sA + 3 * OPSZ + bOff + q * (16 * ROWB) + kb);
                    }
#pragma unroll
                    for (int mf = 0; mf < 2; mf++)
#pragma unroll
                        for (int qq = 0; qq < 2; qq++)
#pragma unroll
                            for (int j = 0; j < 2; j++) {
                                const int nf = qh * 4 + qq * 2 + j;
                                const int rr = j * 2;
                                mma_bf16(acc[mf][nf], Ah[mf], Bh2[qq][rr], Bh2[qq][rr + 1]);
                                mma_bf16(acc[mf][nf], Ah[mf], Bl2[qq][rr], Bl2[qq][rr + 1]);
                                mma_bf16(acc[mf][nf], Al[mf], Bh2[qq][rr], Bh2[qq][rr + 1]);
                            }
                }
            }

            if (more) {
                char* other = smem + (s ^ 1) * STGSZ;
                char* sAh = other + aStOff;
                char* sAl = other + OPSZ + aStOff;
#pragma unroll
                for (int i = 0; i < 4; i++) {
                    float4 v = ar[i];
                    __nv_bfloat162 h01 = __floats2bfloat162_rn(v.x, v.y);
                    __nv_bfloat162 h23 = __floats2bfloat162_rn(v.z, v.w);
                    __nv_bfloat162 l01 = __floats2bfloat162_rn(v.x - __low2float(h01), v.y - __high2float(h01));
                    __nv_bfloat162 l23 = __floats2bfloat162_rn(v.z - __low2float(h23), v.w - __high2float(h23));
                    *(uint2*)(sAh + 8 * i) = make_uint2(*(uint32_t*)&h01, *(uint32_t*)&h23);
                    *(uint2*)(sAl + 8 * i) = make_uint2(*(uint32_t*)&l01, *(uint32_t*)&l23);
                }
            }
        }

        // epilogue: flush this run's partial to (slot, mtile)
        float* outb = g_LxP + (size_t)slot * (MTOT * DIM);
#pragma unroll
        for (int mf = 0; mf < 2; mf++) {
            const int row0 = m0 + wm * 32 + mf * 16 + g4;
#pragma unroll
            for (int nf = 0; nf < 8; nf++) {
                const int col = wn * 64 + nf * 8 + t4 * 2;
                *(float2*)(outb + (size_t)row0 * DIM + col) =
                    make_float2(acc[mf][nf][0], acc[mf][nf][1]);
                *(float2*)(outb + (size_t)(row0 + 8) * DIM + col) =
                    make_float2(acc[mf][nf][2], acc[mf][nf][3]);
            }
        }

        g = gend;
    }
}

// ---------------- BN stats pass 1 + slot fold (float4, wide MLP) ------------
__global__ __launch_bounds__(256) void stats_partial(int xsel) {
    pdl_wait();
    const float* __restrict__ X = xsel ? g_bufX2 : g_bufX;
    const int tid = threadIdx.x;
    const int cg = (tid & 31) * 4;
    const int rq = tid >> 5;
    const int rpb = MTOT / STATS_BLOCKS;   // 16
    const int r0 = blockIdx.x * rpb;

    float4 sx  = make_float4(0.f, 0.f, 0.f, 0.f);
    float4 sxx = make_float4(0.f, 0.f, 0.f, 0.f);
    float4 sl  = make_float4(0.f, 0.f, 0.f, 0.f);
    float4 sll = make_float4(0.f, 0.f, 0.f, 0.f);

#pragma unroll
    for (int it = 0; it < 2; it++) {
        const int r = r0 + rq + it * 8;
        const size_t idx = (size_t)r * DIM + cg;
        float4 v = *(const float4*)(X + idx);
        sx = f4add(sx, v);
        sxx = f4fma(v, v, sxx);
        float4 wv = *(const float4*)(g_LxP + idx);
#pragma unroll
        for (int q = 1; q < NSLOT; q++)
            wv = f4add(wv, *(const float4*)(g_LxP + idx + (size_t)q * MTOT * DIM));
        *(float4*)(g_LxP + idx) = wv;      // fold into slot 0
        sl = f4add(sl, wv);
        sll = f4fma(wv, wv, sll);
    }

    __shared__ float4 shv[256];
    const int b = blockIdx.x;
    float4 acc4;
#define STATS_REDUCE(VAL, QUAD)                                               \
    shv[tid] = VAL; __syncthreads();                                          \
    if (tid < 32) {                                                           \
        acc4 = shv[tid];                                                      \
        _Pragma("unroll")                                                     \
        for (int rr = 1; rr < 8; rr++) acc4 = f4add(acc4, shv[tid + 32 * rr]); \
        const int c0 = tid * 4;                                               \
        g_partials[((QUAD) * 128 + c0 + 0) * STATS_BLOCKS + b] = acc4.x;      \
        g_partials[((QUAD) * 128 + c0 + 1) * STATS_BLOCKS + b] = acc4.y;      \
        g_partials[((QUAD) * 128 + c0 + 2) * STATS_BLOCKS + b] = acc4.z;      \
        g_partials[((QUAD) * 128 + c0 + 3) * STATS_BLOCKS + b] = acc4.w;      \
    }                                                                         \
    __syncthreads();

    STATS_REDUCE(sx, 0)
    STATS_REDUCE(sxx, 1)
    STATS_REDUCE(sl, 2)
    STATS_REDUCE(sll, 3)
#undef STATS_REDUCE
}

// ---------------- BN stats pass 2: float4 reads -----------------------------
__global__ __launch_bounds__(256) void stats_final(const float* __restrict__ gamma,
                                                   const float* __restrict__ beta) {
    pdl_wait();
    const int warp = threadIdx.x >> 5;
    const int lane = threadIdx.x & 31;
    const int k = blockIdx.x * 8 + warp;
    const int base = (k < 128) ? 0 : 2;
    const int c = k & 127;
    const float4* ps = (const float4*)(g_partials + (size_t)(base * 128 + c) * STATS_BLOCKS);
    const float4* pq = (const float4*)(g_partials + (size_t)((base + 1) * 128 + c) * STATS_BLOCKS);
    float s = 0.f, ss = 0.f;
#pragma unroll
    for (int i = 0; i < STATS_BLOCKS / 128; i++) {
        float4 a = ps[lane + 32 * i];
        float4 b = pq[lane + 32 * i];
        s  += (a.x + a.y) + (a.z + a.w);
        ss += (b.x + b.y) + (b.z + b.w);
    }
    s = warp_sum(s);
    ss = warp_sum(ss);
    if (lane == 0) {
        float mean = s / (float)MTOT;
        float var  = ss / (float)MTOT - mean * mean;
        float sc   = rsqrtf(var + EPSV) * gamma[k];
        g_scale[k] = sc;
        g_shift[k] = beta[k] - mean * sc;
    }
}

// ---------------- fold BN into linear weights: bf16 split + beff ------------
__global__ __launch_bounds__(256) void weff_kernel(const float* __restrict__ w,
                                                   const float* __restrict__ b) {
    pdl_wait();
    const int e0 = (blockIdx.x * 256 + threadIdx.x) * 2;
    const int j = e0 >> 8;
    const int k0 = e0 & 255;
    float2 wv = *(const float2*)(w + j * 256 + k0);
    float2 sv = *(const float2*)(g_scale + k0);
    float p0 = wv.x * sv.x, p1 = wv.y * sv.y;
    __nv_bfloat162 h01 = __floats2bfloat162_rn(p0, p1);
    __nv_bfloat162 l01 = __floats2bfloat162_rn(p0 - __low2float(h01), p1 - __high2float(h01));
    *(uint32_t*)(g_wBh + j * 256 + k0) = *(uint32_t*)&h01;
    *(uint32_t*)(g_wBl + j * 256 + k0) = *(uint32_t*)&l01;

    if (blockIdx.x < 16) {
        const int warp = threadIdx.x >> 5;
        const int lane = threadIdx.x & 31;
        const int jo = blockIdx.x * 8 + warp;
        const float4* wj = (const float4*)(w + jo * 256);
        const float4* sh4 = (const float4*)g_shift;
        float s = 0.f;
#pragma unroll
        for (int i = 0; i < 2; i++) {
            float4 a = wj[lane + 32 * i];
            float4 c4 = sh4[lane + 32 * i];
            s += a.x * c4.x + a.y * c4.y + a.z * c4.z + a.w * c4.w;
        }
        s = warp_sum(s);
        if (lane == 0) g_beff[jo] = b[jo] + s;
    }
}

// ---------------- HMMA linear: M=64 tiles, 128 CTAs -------------------------
#define L_AOP 5120
#define L_BBASE (2 * L_AOP)
#define L_STG (2 * L_AOP + 2 * OPSZ)
#define LIN_SMEM (2 * L_STG)

__global__ __launch_bounds__(256, 2) void linear_mma(int xsel,
                                                     const float* __restrict__ resid,
                                                     float* __restrict__ dst, int mode) {
    pdl_wait();
    extern __shared__ char smem[];
    const int tid = threadIdx.x;
    const int lane = tid & 31;
    const int w = tid >> 5;
    const int wm = w >> 1;
    const int wn = w & 1;
    const int m0 = blockIdx.x * 64;

    const uint32_t sb = smem_u32(smem);
    const float* __restrict__ Xs = xsel ? g_bufX2 : g_bufX;

    const int a_row = wm * 16 + (lane & 7) + ((lane >> 3) & 1) * 8;
    const uint32_t aOff = (uint32_t)a_row * ROWB + ((lane >> 4) & 1) * 16;
    const int b_row = wn * 64 + (lane & 7) + ((lane >> 4) & 1) * 8;
    const uint32_t bOff = (uint32_t)b_row * ROWB + ((lane >> 3) & 1) * 16;

    const int garow = tid >> 2;
    const int gseg = tid & 3;
    const uint32_t aStOff = (uint32_t)garow * ROWB + gseg * 16;
    const int gbrow = tid >> 1;
    const int gbh = tid & 1;
    const __nv_bfloat16* Bhp = g_wBh + (size_t)gbrow * FEAT + gbh * 16;
    const __nv_bfloat16* Blp = g_wBl + (size_t)gbrow * FEAT + gbh * 16;
    const uint32_t bStOff = (uint32_t)gbrow * ROWB + gbh * 32;

    float acc[8][4];
#pragma unroll
    for (int j = 0; j < 8; j++)
#pragma unroll
        for (int q = 0; q < 4; q++) acc[j][q] = 0.f;

    float4 ar[2];

    auto aPtr = [&](int t) -> const float* {
        int kk = t * 32 + gseg * 8;
        return (kk < 128) ? (Xs + (size_t)(m0 + garow) * DIM + kk)
                          : (g_LxP + (size_t)(m0 + garow) * DIM + (kk - 128));
    };
    auto convA = [&](char* base, float4* v) {
        char* sAh = base + aStOff;
        char* sAl = base + L_AOP + aStOff;
#pragma unroll
        for (int i = 0; i < 2; i++) {
            float4 x = v[i];
            __nv_bfloat162 h01 = __floats2bfloat162_rn(x.x, x.y);
            __nv_bfloat162 h23 = __floats2bfloat162_rn(x.z, x.w);
            __nv_bfloat162 l01 = __floats2bfloat162_rn(x.x - __low2float(h01), x.y - __high2float(h01));
            __nv_bfloat162 l23 = __floats2bfloat162_rn(x.z - __low2float(h23), x.w - __high2float(h23));
            *(uint2*)(sAh + 8 * i) = make_uint2(*(uint32_t*)&h01, *(uint32_t*)&h23);
            *(uint2*)(sAl + 8 * i) = make_uint2(*(uint32_t*)&l01, *(uint32_t*)&l23);
        }
    };

    cpasync16(sb + L_BBASE + bStOff,              Bhp);
    cpasync16(sb + L_BBASE + bStOff + 16,         Bhp + 8);
    cpasync16(sb + L_BBASE + OPSZ + bStOff,       Blp);
    cpasync16(sb + L_BBASE + OPSZ + bStOff + 16,  Blp + 8);
    cp_commit();
    {
        const float* ap = aPtr(0);
        ar[0] = *(const float4*)ap;
        ar[1] = *(const float4*)(ap + 4);
        convA(smem, ar);
    }

    const int T = FEAT / 32;  // 8

    for (int t = 0; t < T; t++) {
        cp_wait0();
        __syncthreads();
        const int s = t & 1;
        const uint32_t sA = sb + s * L_STG;
        const uint32_t nsBase = sb + (s ^ 1) * L_STG;
        const bool more = (t + 1) < T;
        if (more) {
            const int off = (t + 1) * 32;
            cpasync16(nsBase + L_BBASE + bStOff,              Bhp + off);
            cpasync16(nsBase + L_BBASE + bStOff + 16,         Bhp + off + 8);
            cpasync16(nsBase + L_BBASE + OPSZ + bStOff,       Blp + off);
            cpasync16(nsBase + L_BBASE + OPSZ + bStOff + 16,  Blp + off + 8);
            cp_commit();
            const float* ap = aPtr(t + 1);
            ar[0] = *(const float4*)ap;
            ar[1] = *(const float4*)(ap + 4);
        }

#pragma unroll
        for (int ks = 0; ks < 2; ks++) {
            const uint32_t kb = ks * 32;
            uint32_t Ah[4], Al[4];
            ldmx4(Ah, sA + aOff + kb);
            ldmx4(Al, sA + L_AOP + aOff + kb);
#pragma unroll
            for (int qh = 0; qh < 2; qh++) {
                uint32_t Bh2[2][4], Bl2[2][4];
#pragma unroll
                for (int qq = 0; qq < 2; qq++) {
                    const int q = qh * 2 + qq;
                    ldmx4(Bh2[qq], sA + L_BBASE + bOff + q * (16 * ROWB) + kb);
                    ldmx4(Bl2[qq], sA + L_BBASE + OPSZ + bOff + q * (16 * ROWB) + kb);
                }
#pragma unroll
                for (int qq = 0; qq < 2; qq++)
#pragma unroll
                    for (int j = 0; j < 2; j++) {
                        const int nf = qh * 4 + qq * 2 + j;
                        const int rr = j * 2;
                        mma_bf16(acc[nf], Ah, Bh2[qq][rr], Bh2[qq][rr + 1]);
                        mma_bf16(acc[nf], Ah, Bl2[qq][rr], Bl2[qq][rr + 1]);
                        mma_bf16(acc[nf], Al, Bh2[qq][rr], Bh2[qq][rr + 1]);
                    }
            }
        }

        if (more) {
            convA(smem + (s ^ 1) * L_STG, ar);
        }
    }

    const int g = lane >> 2, t4 = lane & 3;
    const int row0 = m0 + wm * 16 + g;
#pragma unroll
    for (int nf = 0; nf < 8; nf++) {
        const int col = wn * 64 + nf * 8 + t4 * 2;
        float b0 = g_beff[col], b1 = g_beff[col + 1];
        float y0 = acc[nf][0] + b0;
        float y1 = acc[nf][1] + b1;
        float y2 = acc[nf][2] + b0;
        float y3 = acc[nf][3] + b1;
        if (mode == 0) {
            float v0 = eluf(y0), v1 = eluf(y1), v2 = eluf(y2), v3 = eluf(y3);
            *(float2*)(g_bufX2 + (size_t)row0 * DIM + col) = make_float2(v0, v1);
            *(float2*)(g_bufX2 + (size_t)(row0 + 8) * DIM + col) = make_float2(v2, v3);
            __nv_bfloat16 h, l;
            split_bf16(v0, h, l);
            g_Bh[(size_t)col * MTOT + row0] = h;       g_Bl[(size_t)col * MTOT + row0] = l;
            split_bf16(v1, h, l);
            g_Bh[(size_t)(col + 1) * MTOT + row0] = h; g_Bl[(size_t)(col + 1) * MTOT + row0] = l;
            split_bf16(v2, h, l);
            g_Bh[(size_t)col * MTOT + row0 + 8] = h;       g_Bl[(size_t)col * MTOT + row0 + 8] = l;
            split_bf16(v3, h, l);
            g_Bh[(size_t)(col + 1) * MTOT + row0 + 8] = h; g_Bl[(size_t)(col + 1) * MTOT + row0 + 8] = l;
        } else {
            float r0v = resid[(size_t)row0 * DIM + col];
            float r1v = resid[(size_t)row0 * DIM + col + 1];
            float r2v = resid[(size_t)(row0 + 8) * DIM + col];
            float r3v = resid[(size_t)(row0 + 8) * DIM + col + 1];
            *(float2*)(dst + (size_t)row0 * DIM + col) = make_float2(y0 + r0v, y1 + r1v);
            *(float2*)(dst + (size_t)(row0 + 8) * DIM + col) = make_float2(y2 + r2v, y3 + r3v);
        }
    }
}

// ---------------- launch (all kernels with PDL attribute) --------------------
extern "C" void kernel_launch(void* const* d_in, const int* in_sizes, int n_in,
                              void* d_out, int out_size) {
    const float* L      = (const float*)d_in[0];
    const float* inputs = (const float*)d_in[2];
    const float* bn0_g  = (const float*)d_in[3];
    const float* bn0_b  = (const float*)d_in[4];
    const float* fc0_w  = (const float*)d_in[5];
    const float* fc0_b  = (const float*)d_in[6];
    const float* bn1_g  = (const float*)d_in[7];
    const float* bn1_b  = (const float*)d_in[8];
    const float* fc1_w  = (const float*)d_in[9];
    const float* fc1_b  = (const float*)d_in[10];
    float* out = (float*)d_out;

    cudaFuncSetAttribute(sgemm_mma, cudaFuncAttributeMaxDynamicSharedMemorySize, SGEMM_SMEM);
    cudaFuncSetAttribute(linear_mma, cudaFuncAttributeMaxDynamicSharedMemorySize, LIN_SMEM);

    cudaLaunchAttribute attr;
    attr.id = cudaLaunchAttributeProgrammaticStreamSerialization;
    attr.val.programmaticStreamSerializationAllowed = 1;

    cudaLaunchConfig_t cfg = {};
    cfg.blockDim = dim3(256, 1, 1);
    cfg.stream = 0;
    cfg.attrs = &attr;
    cfg.numAttrs = 1;

    auto go = [&](const void* fn, int grid, size_t smem, void** args) {
        cfg.gridDim = dim3(grid, 1, 1);
        cfg.dynamicSmemBytes = smem;
        cudaLaunchKernelExC(&cfg, fn, args);
    };

    int i0 = 0, i1 = 1;
    const float* nullres = nullptr;
    float* nulldst = nullptr;

    // ---- block 0 ----
    { void* a[] = {(void*)&inputs};
      go((const void*)pack_kernel, 128, 0, a); }
    { void* a[] = {(void*)&L};
      go((const void*)sgemm_mma, NCTA, SGEMM_SMEM, a); }
    { void* a[] = {&i0};
      go((const void*)stats_partial, STATS_BLOCKS, 0, a); }
    { void* a[] = {(void*)&bn0_g, (void*)&bn0_b};
      go((const void*)stats_final, 32, 0, a); }
    { void* a[] = {(void*)&fc0_w, (void*)&fc0_b};
      go((const void*)weff_kernel, 64, 0, a); }
    { void* a[] = {&i0, (void*)&nullres, (void*)&nulldst, &i0};
      go((const void*)linear_mma, 128, LIN_SMEM, a); }

    // ---- block 1 ----
    { void* a[] = {(void*)&L};
      go((const void*)sgemm_mma, NCTA, SGEMM_SMEM, a); }
    { void* a[] = {&i1};
      go((const void*)stats_partial, STATS_BLOCKS, 0, a); }
    { void* a[] = {(void*)&bn1_g, (void*)&bn1_b};
      go((const void*)stats_final, 32, 0, a); }
    { void* a[] = {(void*)&fc1_w, (void*)&fc1_b};
      go((const void*)weff_kernel, 64, 0, a); }
    { void* a[] = {&i1, (void*)&inputs, (void*)&out, &i1};
      go((const void*)linear_mma, 128, LIN_SMEM, a); }
}

// round 17
// speedup vs baseline: 1.3471x; 1.0078x over previous
#include <cuda_runtime.h>
#include <cuda_bf16.h>
#include <math.h>
#include <stdint.h>

#define MTOT 8192
#define KDIM 8192
#define DIM 128
#define FEAT 256
#define EPSV 1e-5f
#define STATS_BLOCKS 512
#define NSLOT 6
#define NCTA 296          // 148 SMs x occupancy 2: one exact wave

// ---------------- scratch (device globals; no allocs allowed) ----------------
__device__ float g_bufX [MTOT * DIM];
__device__ float g_bufX2[MTOT * DIM];
__device__ float g_LxP [NSLOT * MTOT * DIM]; // per-(mtile,slot) partials; slot0 -> folded sum
__device__ __nv_bfloat16 g_Bh[DIM * MTOT];   // B^T bf16 hi [feat][node]
__device__ __nv_bfloat16 g_Bl[DIM * MTOT];
__device__ float g_partials[4 * DIM * STATS_BLOCKS];  // [quad][feat][block]
__device__ float g_scale[FEAT];
__device__ float g_shift[FEAT];
__device__ __nv_bfloat16 g_wBh[DIM * FEAT];  // folded weights bf16 [j][k]
__device__ __nv_bfloat16 g_wBl[DIM * FEAT];
__device__ float g_beff[DIM];

// ---------------- helpers ----------------
__device__ __forceinline__ void pdl_wait() {
    asm volatile("griddepcontrol.wait;" ::: "memory");
}
__device__ __forceinline__ uint32_t smem_u32(const void* p) {
    uint32_t a;
    asm("{ .reg .u64 t; cvta.to.shared.u64 t, %1; cvt.u32.u64 %0, t; }" : "=r"(a) : "l"(p));
    return a;
}
__device__ __forceinline__ void ldmx4(uint32_t* r, uint32_t addr) {
    asm volatile("ldmatrix.sync.aligned.m8n8.x4.shared.b16 {%0,%1,%2,%3}, [%4];"
                 : "=r"(r[0]), "=r"(r[1]), "=r"(r[2]), "=r"(r[3]) : "r"(addr));
}
__device__ __forceinline__ void mma_bf16(float* d, const uint32_t* a, uint32_t b0, uint32_t b1) {
    asm volatile(
        "mma.sync.aligned.m16n8k16.row.col.f32.bf16.bf16.f32 "
        "{%0,%1,%2,%3}, {%4,%5,%6,%7}, {%8,%9}, {%0,%1,%2,%3};"
        : "+f"(d[0]), "+f"(d[1]), "+f"(d[2]), "+f"(d[3])
        : "r"(a[0]), "r"(a[1]), "r"(a[2]), "r"(a[3]), "r"(b0), "r"(b1));
}
__device__ __forceinline__ void cpasync16(uint32_t dst, const void* src) {
    asm volatile("cp.async.cg.shared.global [%0], [%1], 16;" :: "r"(dst), "l"(src));
}
__device__ __forceinline__ void cp_commit() { asm volatile("cp.async.commit_group;"); }
__device__ __forceinline__ void cp_wait0()  { asm volatile("cp.async.wait_group 0;" ::: "memory"); }

__device__ __forceinline__ float eluf(float v) { return v > 0.f ? v : expm1f(v); }

__device__ __forceinline__ float warp_sum(float v) {
#pragma unroll
    for (int o = 16; o > 0; o >>= 1) v += __shfl_xor_sync(0xFFFFFFFFu, v, o);
    return v;
}
__device__ __forceinline__ void split_bf16(float v, __nv_bfloat16& h, __nv_bfloat16& l) {
    h = __float2bfloat16(v);
    l = __float2bfloat16(v - __bfloat162float(h));
}
__device__ __forceinline__ float4 f4add(float4 a, float4 b) {
    return make_float4(a.x + b.x, a.y + b.y, a.z + b.z, a.w + b.w);
}
__device__ __forceinline__ float4 f4fma(float4 a, float4 b, float4 c) {
    return make_float4(fmaf(a.x, b.x, c.x), fmaf(a.y, b.y, c.y),
                       fmaf(a.z, b.z, c.z), fmaf(a.w, b.w, c.w));
}

// chunk-schedule arithmetic: CTA c covers chunks [start(c), start(c)+cnt(c))
__device__ __forceinline__ int cta_of_chunk(int g) {
    return (g < 5824) ? (g / 56) : (104 + (g - 5824) / 55);
}

// ---------------- pack: inputs -> ELU -> g_bufX + B^T bf16 hi/lo ------------
__global__ __launch_bounds__(256) void pack_kernel(const float* __restrict__ src) {
    pdl_wait();
    __shared__ float tile[128][65];
    const int tid = threadIdx.x;
    const int node0 = blockIdx.x * 64;

    const float4* sv = (const float4*)src + (size_t)node0 * 32;
    float4* xv = (float4*)g_bufX + (size_t)node0 * 32;
#pragma unroll
    for (int i = 0; i < 8; i++) {
        int idx = tid + 256 * i;
        int node = idx >> 5;
        int fq = idx & 31;
        float4 v = sv[idx];
        v.x = eluf(v.x); v.y = eluf(v.y); v.z = eluf(v.z); v.w = eluf(v.w);
        xv[idx] = v;
        tile[fq * 4 + 0][node] = v.x;
        tile[fq * 4 + 1][node] = v.y;
        tile[fq * 4 + 2][node] = v.z;
        tile[fq * 4 + 3][node] = v.w;
    }
    __syncthreads();

    const int feat = tid >> 1;
    const int h = tid & 1;
    const float* r = &tile[feat][h * 32];
    uint32_t hi[16], lo[16];
#pragma unroll
    for (int j = 0; j < 16; j++) {
        float a = r[2 * j], b = r[2 * j + 1];
        __nv_bfloat162 hb = __floats2bfloat162_rn(a, b);
        float ha = __low2float(hb), hbv = __high2float(hb);
        __nv_bfloat162 lb = __floats2bfloat162_rn(a - ha, b - hbv);
        hi[j] = *(uint32_t*)&hb;
        lo[j] = *(uint32_t*)&lb;
    }
    uint4* oh = (uint4*)(g_Bh + (size_t)feat * MTOT + node0 + h * 32);
    uint4* ol = (uint4*)(g_Bl + (size_t)feat * MTOT + node0 + h * 32);
#pragma unroll
    for (int blk = 0; blk < 4; blk++) {
        oh[blk] = make_uint4(hi[4 * blk], hi[4 * blk + 1], hi[4 * blk + 2], hi[4 * blk + 3]);
        ol[blk] = make_uint4(lo[4 * blk], lo[4 * blk + 1], lo[4 * blk + 2], lo[4 * blk + 3]);
    }
}

// ---------------- split-bf16 HMMA GEMM, balanced 296-CTA chunk schedule -----
// pdl_wait deferred: A tile-0 (reads L, a harness input) prefetched pre-wait.
#define ROWB 80
#define OPSZ 10240
#define STGSZ 40960
#define SGEMM_SMEM (2 * STGSZ)

__global__ __launch_bounds__(256, 2) void sgemm_mma(const float* __restrict__ L) {
    extern __shared__ char smem[];
    const int tid = threadIdx.x;
    const int lane = tid & 31;
    const int w = tid >> 5;
    const int wm = w >> 1;
    const int wn = w & 1;
    const int c = blockIdx.x;                       // 0..295

    const int gs = 55 * c + (c < 104 ? c : 104);
    const int ge = gs + 55 + (c < 104 ? 1 : 0);

    const uint32_t sb = smem_u32(smem);

    const int a_row = wm * 32 + (lane & 7) + ((lane >> 3) & 1) * 8;
    const uint32_t aOff = (uint32_t)a_row * ROWB + ((lane >> 4) & 1) * 16;
    const int b_row = wn * 64 + (lane & 7) + ((lane >> 4) & 1) * 8;
    const uint32_t bOff = (uint32_t)b_row * ROWB + ((lane >> 3) & 1) * 16;

    const int grow = tid >> 1;
    const int gh = tid & 1;
    const uint32_t aStOff = (uint32_t)grow * ROWB + gh * 32;
    const int g4 = lane >> 2, t4 = lane & 3;

    bool first = true;
    int g = gs;
    while (g < ge) {
        const int m = g >> 8;                       // mtile
        const int gend = (ge < ((m + 1) << 8)) ? ge : ((m + 1) << 8);
        const int T = gend - g;                     // 1..56 BK-chunks this run
        const int m0 = m * 128;
        const int kc0 = (g & 255) * 32;
        const int slot = c - cta_of_chunk(m << 8);  // 0..5

        const float* Ap = L + (size_t)(m0 + grow) * KDIM + kc0 + gh * 16;
        const __nv_bfloat16* Bhp = g_Bh + (size_t)grow * MTOT + kc0 + gh * 16;
        const __nv_bfloat16* Blp = g_Bl + (size_t)grow * MTOT + kc0 + gh * 16;

        float acc[2][8][4];
#pragma unroll
        for (int i = 0; i < 2; i++)
#pragma unroll
            for (int j = 0; j < 8; j++)
#pragma unroll
                for (int q = 0; q < 4; q++) acc[i][j][q] = 0.f;

        float4 ar[4];

        // A tile-0 prefetch (registers only; L is independent of upstream)
#pragma unroll
        for (int i = 0; i < 4; i++) ar[i] = *(const float4*)(Ap + 4 * i);

        if (first) { pdl_wait(); first = false; }

        __syncthreads();   // protect stage reuse across runs
        cpasync16(sb + 2 * OPSZ + aStOff,      Bhp);
        cpasync16(sb + 2 * OPSZ + aStOff + 16, Bhp + 8);
        cpasync16(sb + 3 * OPSZ + aStOff,      Blp);
        cpasync16(sb + 3 * OPSZ + aStOff + 16, Blp + 8);
        cp_commit();
        {
            char* sAh = smem + aStOff;
            char* sAl = smem + OPSZ + aStOff;
#pragma unroll
            for (int i = 0; i < 4; i++) {
                float4 v = ar[i];
                __nv_bfloat162 h01 = __floats2bfloat162_rn(v.x, v.y);
                __nv_bfloat162 h23 = __floats2bfloat162_rn(v.z, v.w);
                __nv_bfloat162 l01 = __floats2bfloat162_rn(v.x - __low2float(h01), v.y - __high2float(h01));
                __nv_bfloat162 l23 = __floats2bfloat162_rn(v.z - __low2float(h23), v.w - __high2float(h23));
                *(uint2*)(sAh + 8 * i) = make_uint2(*(uint32_t*)&h01, *(uint32_t*)&h23);
                *(uint2*)(sAl + 8 * i) = make_uint2(*(uint32_t*)&l01, *(uint32_t*)&l23);
            }
        }

        for (int t = 0; t < T; t++) {
            cp_wait0();
            __syncthreads();
            const int s = t & 1;
            const uint32_t sA = sb + s * STGSZ;
            const uint32_t nsBase = sb + (s ^ 1) * STGSZ;
            const bool more = (t + 1) < T;
            if (more) {
                const int off = (t + 1) * 32;
                cpasync16(nsBase + 2 * OPSZ + aStOff,      Bhp + off);
                cpasync16(nsBase + 2 * OPSZ + aStOff + 16, Bhp + off + 8);
                cpasync16(nsBase + 3 * OPSZ + aStOff,      Blp + off);
                cpasync16(nsBase + 3 * OPSZ + aStOff + 16, Blp + off + 8);
                cp_commit();
#pragma unroll
                for (int i = 0; i < 4; i++) ar[i] = *(const float4*)(Ap + off + 4 * i);
            }

#pragma unroll
            for (int ks = 0; ks < 2; ks++) {
                const uint32_t kb = ks * 32;
                uint32_t Ah[2][4], Al[2][4];
#pragma unroll
                for (int mf = 0; mf < 2; mf++) {
                    ldmx4(Ah[mf], sA + aOff + mf * (16 * ROWB) + kb);
                    ldmx4(Al[mf], sA + OPSZ + aOff + mf * (16 * ROWB) + kb);
                }
#pragma unroll
                for (int qh = 0; qh < 2; qh++) {
                    uint32_t Bh2[2][4], Bl2[2][4];
#pragma unroll
                    for (int qq = 0; qq < 2; qq++) {
                        const int q = qh * 2 + qq;
                        ldmx4(Bh2[qq], sA + 2 * OPSZ + bOff + q * (16 * ROWB) + kb);
                        ldmx4(Bl2[qq], sA + 3 * OPSZ + bOff + q * (16 * ROWB) + kb);
                    }
#pragma unroll
                    for (int mf = 0; mf < 2; mf++)
#pragma unroll
                        for (int qq = 0; qq < 2; qq++)
#pragma unroll
                            for (int j = 0; j < 2; j++) {
                                const int nf = qh * 4 + qq * 2 + j;
                                const int rr = j * 2;
                                mma_bf16(acc[mf][nf], Ah[mf], Bh2[qq][rr], Bh2[qq][rr + 1]);
                                mma_bf16(acc[mf][nf], Ah[mf], Bl2[qq][rr], Bl2[qq][rr + 1]);
                                mma_bf16(acc[mf][nf], Al[mf], Bh2[qq][rr], Bh2[qq][rr + 1]);
                            }
                }
            }

            if (more) {
                char* other = smem + (s ^ 1) * STGSZ;
                char* sAh = other + aStOff;
                char* sAl = other + OPSZ + aStOff;
#pragma unroll
                for (int i = 0; i < 4; i++) {
                    float4 v = ar[i];
                    __nv_bfloat162 h01 = __floats2bfloat162_rn(v.x, v.y);
                    __nv_bfloat162 h23 = __floats2bfloat162_rn(v.z, v.w);
                    __nv_bfloat162 l01 = __floats2bfloat162_rn(v.x - __low2float(h01), v.y - __high2float(h01));
                    __nv_bfloat162 l23 = __floats2bfloat162_rn(v.z - __low2float(h23), v.w - __high2float(h23));
                    *(uint2*)(sAh + 8 * i) = make_uint2(*(uint32_t*)&h01, *(uint32_t*)&h23);
                    *(uint2*)(sAl + 8 * i) = make_uint2(*(uint32_t*)&l01, *(uint32_t*)&l23);
                }
            }
        }

        // epilogue: flush this run's partial to (slot, mtile)
        float* outb = g_LxP + (size_t)slot * (MTOT * DIM);
#pragma unroll
        for (int mf = 0; mf < 2; mf++) {
            const int row0 = m0 + wm * 32 + mf * 16 + g4;
#pragma unroll
            for (int nf = 0; nf < 8; nf++) {
                const int col = wn * 64 + nf * 8 + t4 * 2;
                *(float2*)(outb + (size_t)row0 * DIM + col) =
                    make_float2(acc[mf][nf][0], acc[mf][nf][1]);
                *(float2*)(outb + (size_t)(row0 + 8) * DIM + col) =
                    make_float2(acc[mf][nf][2], acc[mf][nf][3]);
            }
        }

        g = gend;
    }
}

// ---------------- BN stats pass 1 + slot fold (float4, wide MLP) ------------
// X rows (>=2 kernels upstream) prefetched pre-wait.
__global__ __launch_bounds__(256) void stats_partial(int xsel) {
    const float* __restrict__ X = xsel ? g_bufX2 : g_bufX;
    const int tid = threadIdx.x;
    const int cg = (tid & 31) * 4;
    const int rq = tid >> 5;
    const int rpb = MTOT / STATS_BLOCKS;   // 16
    const int r0 = blockIdx.x * rpb;

    const size_t idx0 = (size_t)(r0 + rq) * DIM + cg;
    const size_t idx1 = (size_t)(r0 + rq + 8) * DIM + cg;
    float4 xv0 = *(const float4*)(X + idx0);   // pre-wait prefetch
    float4 xv1 = *(const float4*)(X + idx1);

    pdl_wait();

    float4 sx  = f4add(xv0, xv1);
    float4 sxx = f4fma(xv0, xv0, make_float4(0.f, 0.f, 0.f, 0.f));
    sxx = f4fma(xv1, xv1, sxx);
    float4 sl  = make_float4(0.f, 0.f, 0.f, 0.f);
    float4 sll = make_float4(0.f, 0.f, 0.f, 0.f);

    const size_t idxs[2] = {idx0, idx1};
#pragma unroll
    for (int it = 0; it < 2; it++) {
        const size_t idx = idxs[it];
        float4 wv = *(const float4*)(g_LxP + idx);
#pragma unroll
        for (int q = 1; q < NSLOT; q++)
            wv = f4add(wv, *(const float4*)(g_LxP + idx + (size_t)q * MTOT * DIM));
        *(float4*)(g_LxP + idx) = wv;      // fold into slot 0
        sl = f4add(sl, wv);
        sll = f4fma(wv, wv, sll);
    }

    __shared__ float4 shv[256];
    const int b = blockIdx.x;
    float4 acc4;
#define STATS_REDUCE(VAL, QUAD)                                               \
    shv[tid] = VAL; __syncthreads();                                          \
    if (tid < 32) {                                                           \
        acc4 = shv[tid];                                                      \
        _Pragma("unroll")                                                     \
        for (int rr = 1; rr < 8; rr++) acc4 = f4add(acc4, shv[tid + 32 * rr]); \
        const int c0 = tid * 4;                                               \
        g_partials[((QUAD) * 128 + c0 + 0) * STATS_BLOCKS + b] = acc4.x;      \
        g_partials[((QUAD) * 128 + c0 + 1) * STATS_BLOCKS + b] = acc4.y;      \
        g_partials[((QUAD) * 128 + c0 + 2) * STATS_BLOCKS + b] = acc4.z;      \
        g_partials[((QUAD) * 128 + c0 + 3) * STATS_BLOCKS + b] = acc4.w;      \
    }                                                                         \
    __syncthreads();

    STATS_REDUCE(sx, 0)
    STATS_REDUCE(sxx, 1)
    STATS_REDUCE(sl, 2)
    STATS_REDUCE(sll, 3)
#undef STATS_REDUCE
}

// ---------------- BN stats pass 2: float4 reads -----------------------------
__global__ __launch_bounds__(256) void stats_final(const float* __restrict__ gamma,
                                                   const float* __restrict__ beta) {
    pdl_wait();
    const int warp = threadIdx.x >> 5;
    const int lane = threadIdx.x & 31;
    const int k = blockIdx.x * 8 + warp;
    const int base = (k < 128) ? 0 : 2;
    const int c = k & 127;
    const float4* ps = (const float4*)(g_partials + (size_t)(base * 128 + c) * STATS_BLOCKS);
    const float4* pq = (const float4*)(g_partials + (size_t)((base + 1) * 128 + c) * STATS_BLOCKS);
    float s = 0.f, ss = 0.f;
#pragma unroll
    for (int i = 0; i < STATS_BLOCKS / 128; i++) {
        float4 a = ps[lane + 32 * i];
        float4 b = pq[lane + 32 * i];
        s  += (a.x + a.y) + (a.z + a.w);
        ss += (b.x + b.y) + (b.z + b.w);
    }
    s = warp_sum(s);
    ss = warp_sum(ss);
    if (lane == 0) {
        float mean = s / (float)MTOT;
        float var  = ss / (float)MTOT - mean * mean;
        float sc   = rsqrtf(var + EPSV) * gamma[k];
        g_scale[k] = sc;
        g_shift[k] = beta[k] - mean * sc;
    }
}

// ---------------- fold BN into linear weights: bf16 split + beff ------------
// w (harness input) prefetched pre-wait.
__global__ __launch_bounds__(256) void weff_kernel(const float* __restrict__ w,
                                                   const float* __restrict__ b) {
    const int e0 = (blockIdx.x * 256 + threadIdx.x) * 2;
    const int j = e0 >> 8;
    const int k0 = e0 & 255;
    float2 wv = *(const float2*)(w + j * 256 + k0);   // pre-wait prefetch
    pdl_wait();
    float2 sv = *(const float2*)(g_scale + k0);
    float p0 = wv.x * sv.x, p1 = wv.y * sv.y;
    __nv_bfloat162 h01 = __floats2bfloat162_rn(p0, p1);
    __nv_bfloat162 l01 = __floats2bfloat162_rn(p0 - __low2float(h01), p1 - __high2float(h01));
    *(uint32_t*)(g_wBh + j * 256 + k0) = *(uint32_t*)&h01;
    *(uint32_t*)(g_wBl + j * 256 + k0) = *(uint32_t*)&l01;

    if (blockIdx.x < 16) {
        const int warp = threadIdx.x >> 5;
        const int lane = threadIdx.x & 31;
        const int jo = blockIdx.x * 8 + warp;
        const float4* wj = (const float4*)(w + jo * 256);
        const float4* sh4 = (const float4*)g_shift;
        float s = 0.f;
#pragma unroll
        for (int i = 0; i < 2; i++) {
            float4 a = wj[lane + 32 * i];
            float4 c4 = sh4[lane + 32 * i];
            s += a.x * c4.x + a.y * c4.y + a.z * c4.z + a.w * c4.w;
        }
        s = warp_sum(s);
        if (lane == 0) g_beff[jo] = b[jo] + s;
    }
}

// ---------------- HMMA linear: M=64 tiles, 128 CTAs -------------------------
// A tile-0 (sources >=2 kernels upstream) prefetched pre-wait.
#define L_AOP 5120
#define L_BBASE (2 * L_AOP)
#define L_STG (2 * L_AOP + 2 * OPSZ)
#define LIN_SMEM (2 * L_STG)

__global__ __launch_bounds__(256, 2) void linear_mma(int xsel,
                                                     const float* __restrict__ resid,
                                                     float* __restrict__ dst, int mode) {
    extern __shared__ char smem[];
    const int tid = threadIdx.x;
    const int lane = tid & 31;
    const int w = tid >> 5;
    const int wm = w >> 1;
    const int wn = w & 1;
    const int m0 = blockIdx.x * 64;

    const uint32_t sb = smem_u32(smem);
    const float* __restrict__ Xs = xsel ? g_bufX2 : g_bufX;

    const int a_row = wm * 16 + (lane & 7) + ((lane >> 3) & 1) * 8;
    const uint32_t aOff = (uint32_t)a_row * ROWB + ((lane >> 4) & 1) * 16;
    const int b_row = wn * 64 + (lane & 7) + ((lane >> 4) & 1) * 8;
    const uint32_t bOff = (uint32_t)b_row * ROWB + ((lane >> 3) & 1) * 16;

    const int garow = tid >> 2;
    const int gseg = tid & 3;
    const uint32_t aStOff = (uint32_t)garow * ROWB + gseg * 16;
    const int gbrow = tid >> 1;
    const int gbh = tid & 1;
    const __nv_bfloat16* Bhp = g_wBh + (size_t)gbrow * FEAT + gbh * 16;
    const __nv_bfloat16* Blp = g_wBl + (size_t)gbrow * FEAT + gbh * 16;
    const uint32_t bStOff = (uint32_t)gbrow * ROWB + gbh * 32;

    float acc[8][4];
#pragma unroll
    for (int j = 0; j < 8; j++)
#pragma unroll
        for (int q = 0; q < 4; q++) acc[j][q] = 0.f;

    float4 ar[2];

    auto aPtr = [&](int t) -> const float* {
        int kk = t * 32 + gseg * 8;
        return (kk < 128) ? (Xs + (size_t)(m0 + garow) * DIM + kk)
                          : (g_LxP + (size_t)(m0 + garow) * DIM + (kk - 128));
    };
    auto convA = [&](char* base, float4* v) {
        char* sAh = base + aStOff;
        char* sAl = base + L_AOP + aStOff;
#pragma unroll
        for (int i = 0; i < 2; i++) {
            float4 x = v[i];
            __nv_bfloat162 h01 = __floats2bfloat162_rn(x.x, x.y);
            __nv_bfloat162 h23 = __floats2bfloat162_rn(x.z, x.w);
            __nv_bfloat162 l01 = __floats2bfloat162_rn(x.x - __low2float(h01), x.y - __high2float(h01));
            __nv_bfloat162 l23 = __floats2bfloat162_rn(x.z - __low2float(h23), x.w - __high2float(h23));
            *(uint2*)(sAh + 8 * i) = make_uint2(*(uint32_t*)&h01, *(uint32_t*)&h23);
            *(uint2*)(sAl + 8 * i) = make_uint2(*(uint32_t*)&l01, *(uint32_t*)&l23);
        }
    };

    // A tile-0 prefetch (Xs / g_LxP are >=2 kernels upstream: complete)
    {
        const float* ap = aPtr(0);
        ar[0] = *(const float4*)ap;
        ar[1] = *(const float4*)(ap + 4);
    }
    pdl_wait();

    cpasync16(sb + L_BBASE + bStOff,              Bhp);
    cpasync16(sb + L_BBASE + bStOff + 16,         Bhp + 8);
    cpasync16(sb + L_BBASE + OPSZ + bStOff,       Blp);
    cpasync16(sb + L_BBASE + OPSZ + bStOff + 16,  Blp + 8);
    cp_commit();
    convA(smem, ar);

    const int T = FEAT / 32;  // 8

    for (int t = 0; t < T; t++) {
        cp_wait0();
        __syncthreads();
        const int s = t & 1;
        const uint32_t sA = sb + s * L_STG;
        const uint32_t nsBase = sb + (s ^ 1) * L_STG;
        const bool more = (t + 1) < T;
        if (more) {
            const int off = (t + 1) * 32;
            cpasync16(nsBase + L_BBASE + bStOff,              Bhp + off);
            cpasync16(nsBase + L_BBASE + bStOff + 16,         Bhp + off + 8);
            cpasync16(nsBase + L_BBASE + OPSZ + bStOff,       Blp + off);
            cpasync16(nsBase + L_BBASE + OPSZ + bStOff + 16,  Blp + off + 8);
            cp_commit();
            const float* ap = aPtr(t + 1);
            ar[0] = *(const float4*)ap;
            ar[1] = *(const float4*)(ap + 4);
        }

#pragma unroll
        for (int ks = 0; ks < 2; ks++) {
            const uint32_t kb = ks * 32;
            uint32_t Ah[4], Al[4];
            ldmx4(Ah, sA + aOff + kb);
            ldmx4(Al, sA + L_AOP + aOff + kb);
#pragma unroll
            for (int qh = 0; qh < 2; qh++) {
                uint32_t Bh2[2][4], Bl2[2][4];
#pragma unroll
                for (int qq = 0; qq < 2; qq++) {
                    const int q = qh * 2 + qq;
                    ldmx4(Bh2[qq], sA + L_BBASE + bOff + q * (16 * ROWB) + kb);
                    ldmx4(Bl2[qq], sA + L_BBASE + OPSZ + bOff + q * (16 * ROWB) + kb);
                }
#pragma unroll
                for (int qq = 0; qq < 2; qq++)
#pragma unroll
                    for (int j = 0; j < 2; j++) {
                        const int nf = qh * 4 + qq * 2 + j;
                        const int rr = j * 2;
                        mma_bf16(acc[nf], Ah, Bh2[qq][rr], Bh2[qq][rr + 1]);
                        mma_bf16(acc[nf], Ah, Bl2[qq][rr], Bl2[qq][rr + 1]);
                        mma_bf16(acc[nf], Al, Bh2[qq][rr], Bh2[qq][rr + 1]);
                    }
            }
        }

        if (more) {
            convA(smem + (s ^ 1) * L_STG, ar);
        }
    }

    const int g = lane >> 2, t4 = lane & 3;
    const int row0 = m0 + wm * 16 + g;
#pragma unroll
    for (int nf = 0; nf < 8; nf++) {
        const int col = wn * 64 + nf * 8 + t4 * 2;
        float b0 = g_beff[col], b1 = g_beff[col + 1];
        float y0 = acc[nf][0] + b0;
        float y1 = acc[nf][1] + b1;
        float y2 = acc[nf][2] + b0;
        float y3 = acc[nf][3] + b1;
        if (mode == 0) {
            float v0 = eluf(y0), v1 = eluf(y1), v2 = eluf(y2), v3 = eluf(y3);
            *(float2*)(g_bufX2 + (size_t)row0 * DIM + col) = make_float2(v0, v1);
            *(float2*)(g_bufX2 + (size_t)(row0 + 8) * DIM + col) = make_float2(v2, v3);
            __nv_bfloat16 h, l;
            split_bf16(v0, h, l);
            g_Bh[(size_t)col * MTOT + row0] = h;       g_Bl[(size_t)col * MTOT + row0] = l;
            split_bf16(v1, h, l);
            g_Bh[(size_t)(col + 1) * MTOT + row0] = h; g_Bl[(size_t)(col + 1) * MTOT + row0] = l;
            split_bf16(v2, h, l);
            g_Bh[(size_t)col * MTOT + row0 + 8] = h;       g_Bl[(size_t)col * MTOT + row0 + 8] = l;
            split_bf16(v3, h, l);
            g_Bh[(size_t)(col + 1) * MTOT + row0 + 8] = h; g_Bl[(size_t)(col + 1) * MTOT + row0 + 8] = l;
        } else {
            float r0v = resid[(size_t)row0 * DIM + col];
            float r1v = resid[(size_t)row0 * DIM + col + 1];
            float r2v = resid[(size_t)(row0 + 8) * DIM + col];
            float r3v = resid[(size_t)(row0 + 8) * DIM + col + 1];
            *(float2*)(dst + (size_t)row0 * DIM + col) = make_float2(y0 + r0v, y1 + r1v);
            *(float2*)(dst + (size_t)(row0 + 8) * DIM + col) = make_float2(y2 + r2v, y3 + r3v);
        }
    }
}

// ---------------- launch (all kernels with PDL attribute) --------------------
extern "C" void kernel_launch(void* const* d_in, const int* in_sizes, int n_in,
                              void* d_out, int out_size) {
    const float* L      = (const float*)d_in[0];
    const float* inputs = (const float*)d_in[2];
    const float* bn0_g  = (const float*)d_in[3];
    const float* bn0_b  = (const float*)d_in[4];
    const float* fc0_w  = (const float*)d_in[5];
    const float* fc0_b  = (const float*)d_in[6];
    const float* bn1_g  = (const float*)d_in[7];
    const float* bn1_b  = (const float*)d_in[8];
    const float* fc1_w  = (const float*)d_in[9];
    const float* fc1_b  = (const float*)d_in[10];
    float* out = (float*)d_out;

    cudaFuncSetAttribute(sgemm_mma, cudaFuncAttributeMaxDynamicSharedMemorySize, SGEMM_SMEM);
    cudaFuncSetAttribute(linear_mma, cudaFuncAttributeMaxDynamicSharedMemorySize, LIN_SMEM);

    cudaLaunchAttribute attr;
    attr.id = cudaLaunchAttributeProgrammaticStreamSerialization;
    attr.val.programmaticStreamSerializationAllowed = 1;

    cudaLaunchConfig_t cfg = {};
    cfg.blockDim = dim3(256, 1, 1);
    cfg.stream = 0;
    cfg.attrs = &attr;
    cfg.numAttrs = 1;

    auto go = [&](const void* fn, int grid, size_t smem, void** args) {
        cfg.gridDim = dim3(grid, 1, 1);
        cfg.dynamicSmemBytes = smem;
        cudaLaunchKernelExC(&cfg, fn, args);
    };

    int i0 = 0, i1 = 1;
    const float* nullres = nullptr;
    float* nulldst = nullptr;

    // ---- block 0 ----
    { void* a[] = {(void*)&inputs};
      go((const void*)pack_kernel, 128, 0, a); }
    { void* a[] = {(void*)&L};
      go((const void*)sgemm_mma, NCTA, SGEMM_SMEM, a); }
    { void* a[] = {&i0};
      go((const void*)stats_partial, STATS_BLOCKS, 0, a); }
    { void* a[] = {(void*)&bn0_g, (void*)&bn0_b};
      go((const void*)stats_final, 32, 0, a); }
    { void* a[] = {(void*)&fc0_w, (void*)&fc0_b};
      go((const void*)weff_kernel, 64, 0, a); }
    { void* a[] = {&i0, (void*)&nullres, (void*)&nulldst, &i0};
      go((const void*)linear_mma, 128, LIN_SMEM, a); }

    // ---- block 1 ----
    { void* a[] = {(void*)&L};
      go((const void*)sgemm_mma, NCTA, SGEMM_SMEM, a); }
    { void* a[] = {&i1};
      go((const void*)stats_partial, STATS_BLOCKS, 0, a); }
    { void* a[] = {(void*)&bn1_g, (void*)&bn1_b};
      go((const void*)stats_final, 32, 0, a); }
    { void* a[] = {(void*)&fc1_w, (void*)&fc1_b};
      go((const void*)weff_kernel, 64, 0, a); }
    { void* a[] = {&i1, (void*)&inputs, (void*)&out, &i1};
      go((const void*)linear_mma, 128, LIN_SMEM, a); }
}